// round 1
// baseline (speedup 1.0000x reference)
#include <cuda_runtime.h>
#include <math.h>

#define H   768
#define FFD 3072
#define BB  4
#define SS  1024
#define NHH 12
#define HDD 64
#define NTOK (BB*SS)   // 4096
#define NLAYER 6

// ---------------- device scratch (no allocations allowed) ----------------
__device__ float g_x   [NTOK*H];       // layer input / output
__device__ float g_q   [NTOK*H];
__device__ float g_k   [NTOK*H];
__device__ float g_v   [NTOK*H];
__device__ float g_ctx [NTOK*H];
__device__ float g_t   [NTOK*H];       // pre-LN buffer
__device__ float g_attn[NTOK*H];       // post-LN1
__device__ float g_ffh [NTOK*FFD];     // post-GELU
__device__ float g_sc  [BB*NHH*SS*SS]; // attention scores / probs (201 MB)

// ---------------- epilogue modes ----------------
#define EPI_NONE      0   // C = acc
#define EPI_BIAS      1   // C = acc + bias[n]
#define EPI_GELU      2   // C = gelu(acc + bias[n])
#define EPI_BIASRES   3   // C = acc + bias[n] + res[m,n]
#define EPI_MASKSCALE 4   // C = acc*scale + mask[b, n]

// ---------------------------------------------------------------------------
// Tiled SGEMM: C[M,N] = A[M,K] * B[K,N]  (or A * B^T when TRANSB, B is [N,K])
// 64x64 tile, BK=16, 256 threads, 4x4 microtile per thread.
// Batched over blockIdx.z with (per-batch, per-head) stride pairs so the same
// kernel serves plain GEMMs, head-sliced Q*K^T and P*V.
// All M,N divisible by 64 and K divisible by 16 in this problem -> no guards.
// ---------------------------------------------------------------------------
template<bool TRANSB, int EPI>
__global__ void __launch_bounds__(256)
gemm64(const float* __restrict__ A, const float* __restrict__ Bm,
       const float* __restrict__ bias, const float* __restrict__ res,
       float* __restrict__ C,
       int K, int lda, int ldb, int ldc,
       long sAb, long sAh, long sBb, long sBh, long sCb, long sCh,
       float scale)
{
    const int z  = blockIdx.z;
    const int bb = z / NHH;
    const int hh = z % NHH;
    A  += bb * sAb + hh * sAh;
    Bm += bb * sBb + hh * sBh;
    C  += bb * sCb + hh * sCh;

    const int row0 = blockIdx.y * 64;
    const int col0 = blockIdx.x * 64;
    const int tid  = threadIdx.x;
    const int tx   = tid & 15;   // 0..15 -> 4 output cols each
    const int ty   = tid >> 4;   // 0..15 -> 4 output rows each

    __shared__ float As[16][68];   // padded: avoids 16-way STS conflicts
    __shared__ float Bs[16][68];

    float acc[4][4] = {};

    for (int k0 = 0; k0 < K; k0 += 16) {
        // A tile: 64 rows x 16 k  -> As[k][m]
        #pragma unroll
        for (int i = 0; i < 4; i++) {
            int idx = tid + i * 256;
            int r = idx >> 4, c = idx & 15;
            As[c][r] = A[(long)(row0 + r) * lda + (k0 + c)];
        }
        if (!TRANSB) {
            // B tile: 16 k x 64 cols -> Bs[k][n]
            #pragma unroll
            for (int i = 0; i < 4; i++) {
                int idx = tid + i * 256;
                int r = idx >> 6, c = idx & 63;
                Bs[r][c] = Bm[(long)(k0 + r) * ldb + (col0 + c)];
            }
        } else {
            // B is [N,K]: tile 64 n x 16 k -> Bs[k][n]
            #pragma unroll
            for (int i = 0; i < 4; i++) {
                int idx = tid + i * 256;
                int r = idx >> 4, c = idx & 15;
                Bs[c][r] = Bm[(long)(col0 + r) * ldb + (k0 + c)];
            }
        }
        __syncthreads();

        #pragma unroll
        for (int kk = 0; kk < 16; kk++) {
            float a[4], b[4];
            #pragma unroll
            for (int j = 0; j < 4; j++) a[j] = As[kk][ty * 4 + j];
            #pragma unroll
            for (int j = 0; j < 4; j++) b[j] = Bs[kk][tx * 4 + j];
            #pragma unroll
            for (int i = 0; i < 4; i++)
                #pragma unroll
                for (int j = 0; j < 4; j++)
                    acc[i][j] = fmaf(a[i], b[j], acc[i][j]);
        }
        __syncthreads();
    }

    #pragma unroll
    for (int i = 0; i < 4; i++) {
        const int r = row0 + ty * 4 + i;
        #pragma unroll
        for (int j = 0; j < 4; j++) {
            const int c = col0 + tx * 4 + j;
            float v = acc[i][j];
            if (EPI == EPI_MASKSCALE) {
                v = v * scale + res[(long)bb * SS + c];   // res = additive mask [B,S]
            } else if (EPI != EPI_NONE) {
                v += bias[c];
                if (EPI == EPI_GELU) {
                    v = 0.5f * v * (1.0f + erff(v * 0.70710678118654752440f));
                } else if (EPI == EPI_BIASRES) {
                    v += res[(long)r * ldc + c];
                }
            }
            C[(long)r * ldc + c] = v;
        }
    }
}

// ---------------------------------------------------------------------------
// Row softmax over scores: one block per row of length S=1024.
// ---------------------------------------------------------------------------
__global__ void __launch_bounds__(256) softmax_rows(float* __restrict__ sc)
{
    float* p = sc + (long)blockIdx.x * SS;
    const int tid = threadIdx.x;
    __shared__ float red[256];

    float v[4];
    float m = -1e30f;
    #pragma unroll
    for (int i = 0; i < 4; i++) { v[i] = p[tid + i * 256]; m = fmaxf(m, v[i]); }

    red[tid] = m; __syncthreads();
    #pragma unroll
    for (int off = 128; off > 0; off >>= 1) {
        if (tid < off) red[tid] = fmaxf(red[tid], red[tid + off]);
        __syncthreads();
    }
    m = red[0];
    __syncthreads();

    float sum = 0.f;
    #pragma unroll
    for (int i = 0; i < 4; i++) { v[i] = __expf(v[i] - m); sum += v[i]; }

    red[tid] = sum; __syncthreads();
    #pragma unroll
    for (int off = 128; off > 0; off >>= 1) {
        if (tid < off) red[tid] += red[tid + off];
        __syncthreads();
    }
    const float inv = 1.0f / red[0];
    #pragma unroll
    for (int i = 0; i < 4; i++) p[tid + i * 256] = v[i] * inv;
}

// ---------------------------------------------------------------------------
// Row LayerNorm: one block (256 thr) per token row of H=768 (3 elems/thread).
// ---------------------------------------------------------------------------
__global__ void __launch_bounds__(256)
layernorm_rows(const float* __restrict__ in, const float* __restrict__ g,
               const float* __restrict__ b, float* __restrict__ out)
{
    const float* p = in  + (long)blockIdx.x * H;
    float*       o = out + (long)blockIdx.x * H;
    const int tid = threadIdx.x;
    __shared__ float rs[256], rq[256];

    const float x0 = p[tid], x1 = p[tid + 256], x2 = p[tid + 512];
    rs[tid] = x0 + x1 + x2;
    rq[tid] = x0 * x0 + x1 * x1 + x2 * x2;
    __syncthreads();
    #pragma unroll
    for (int off = 128; off > 0; off >>= 1) {
        if (tid < off) { rs[tid] += rs[tid + off]; rq[tid] += rq[tid + off]; }
        __syncthreads();
    }
    const float mean = rs[0] * (1.0f / H);
    const float var  = rq[0] * (1.0f / H) - mean * mean;
    const float inv  = rsqrtf(var + 1e-5f);

    o[tid]       = (x0 - mean) * inv * g[tid]       + b[tid];
    o[tid + 256] = (x1 - mean) * inv * g[tid + 256] + b[tid + 256];
    o[tid + 512] = (x2 - mean) * inv * g[tid + 512] + b[tid + 512];
}

// ---------------------------------------------------------------------------
extern "C" void kernel_launch(void* const* d_in, const int* in_sizes, int n_in,
                              void* d_out, int out_size)
{
    const float* hs    = (const float*)d_in[0];
    const float* mask  = (const float*)d_in[1];
    const float* q_w   = (const float*)d_in[2];
    const float* q_b   = (const float*)d_in[3];
    const float* k_w   = (const float*)d_in[4];
    const float* k_b   = (const float*)d_in[5];
    const float* v_w   = (const float*)d_in[6];
    const float* v_b   = (const float*)d_in[7];
    const float* ao_w  = (const float*)d_in[8];
    const float* ao_b  = (const float*)d_in[9];
    const float* ln1_g = (const float*)d_in[10];
    const float* ln1_b = (const float*)d_in[11];
    const float* ff1_w = (const float*)d_in[12];
    const float* ff1_b = (const float*)d_in[13];
    const float* ff2_w = (const float*)d_in[14];
    const float* ff2_b = (const float*)d_in[15];
    const float* ln2_g = (const float*)d_in[16];
    const float* ln2_b = (const float*)d_in[17];
    float* out = (float*)d_out;

    float *x, *q, *k, *v, *ctx, *t, *attn, *ffh, *sc;
    cudaGetSymbolAddress((void**)&x,    g_x);
    cudaGetSymbolAddress((void**)&q,    g_q);
    cudaGetSymbolAddress((void**)&k,    g_k);
    cudaGetSymbolAddress((void**)&v,    g_v);
    cudaGetSymbolAddress((void**)&ctx,  g_ctx);
    cudaGetSymbolAddress((void**)&t,    g_t);
    cudaGetSymbolAddress((void**)&attn, g_attn);
    cudaGetSymbolAddress((void**)&ffh,  g_ffh);
    cudaGetSymbolAddress((void**)&sc,   g_sc);

    // layer input <- hidden_states
    cudaMemcpyAsync(x, hs, (size_t)NTOK * H * sizeof(float),
                    cudaMemcpyDeviceToDevice);

    const dim3 gProj(H / 64,   NTOK / 64, 1);   // 12 x 64
    const dim3 gFF1 (FFD / 64, NTOK / 64, 1);   // 48 x 64
    const dim3 gScr (SS / 64,  SS / 64, BB * NHH); // 16 x 16 x 48
    const dim3 gCtx (HDD / 64, SS / 64, BB * NHH); // 1 x 16 x 48

    for (int layer = 0; layer < NLAYER; layer++) {
        // QKV projections
        gemm64<false, EPI_BIAS><<<gProj, 256>>>(x, q_w, q_b, nullptr, q,
            H, H, H, H, 0,0, 0,0, 0,0, 1.f);
        gemm64<false, EPI_BIAS><<<gProj, 256>>>(x, k_w, k_b, nullptr, k,
            H, H, H, H, 0,0, 0,0, 0,0, 1.f);
        gemm64<false, EPI_BIAS><<<gProj, 256>>>(x, v_w, v_b, nullptr, v,
            H, H, H, H, 0,0, 0,0, 0,0, 1.f);

        // scores[b,h] = (Q_bh * K_bh^T) / 8 + mask[b]
        gemm64<true, EPI_MASKSCALE><<<gScr, 256>>>(q, k, nullptr, mask, sc,
            HDD, H, H, SS,
            (long)SS * H, HDD,
            (long)SS * H, HDD,
            (long)NHH * SS * SS, (long)SS * SS,
            0.125f);

        softmax_rows<<<BB * NHH * SS, 256>>>(sc);

        // ctx[b,h] = P * V_bh   (written directly in merged [B,S,H] layout)
        gemm64<false, EPI_NONE><<<gCtx, 256>>>(sc, v, nullptr, nullptr, ctx,
            SS, SS, H, H,
            (long)NHH * SS * SS, (long)SS * SS,
            (long)SS * H, HDD,
            (long)SS * H, HDD,
            1.f);

        // attention output projection + residual, then LN1
        gemm64<false, EPI_BIASRES><<<gProj, 256>>>(ctx, ao_w, ao_b, x, t,
            H, H, H, H, 0,0, 0,0, 0,0, 1.f);
        layernorm_rows<<<NTOK, 256>>>(t, ln1_g, ln1_b, attn);

        // FFN
        gemm64<false, EPI_GELU><<<gFF1, 256>>>(attn, ff1_w, ff1_b, nullptr, ffh,
            H, H, FFD, FFD, 0,0, 0,0, 0,0, 1.f);
        gemm64<false, EPI_BIASRES><<<gProj, 256>>>(ffh, ff2_w, ff2_b, attn, t,
            FFD, FFD, H, H, 0,0, 0,0, 0,0, 1.f);

        float* dst = (layer == NLAYER - 1) ? out : x;
        layernorm_rows<<<NTOK, 256>>>(t, ln2_g, ln2_b, dst);
    }
}

// round 2
// speedup vs baseline: 1.5772x; 1.5772x over previous
#include <cuda_runtime.h>
#include <math.h>

#define H   768
#define FFD 3072
#define BB  4
#define SS  1024
#define NHH 12
#define HDD 64
#define NTOK (BB*SS)   // 4096
#define NLAYER 6

// ---------------- device scratch (no allocations allowed) ----------------
__device__ float g_x   [NTOK*H];
__device__ float g_q   [NTOK*H];
__device__ float g_k   [NTOK*H];
__device__ float g_v   [NTOK*H];
__device__ float g_ctx [NTOK*H];
__device__ float g_t   [NTOK*H];
__device__ float g_attn[NTOK*H];
__device__ float g_ffh [NTOK*FFD];
__device__ float g_sc  [BB*NHH*SS*SS]; // 201 MB scores/probs

// ---------------- epilogue modes ----------------
#define EPI_NONE      0
#define EPI_BIAS      1
#define EPI_GELU      2
#define EPI_BIASRES   3
#define EPI_MASKSCALE 4

// ---------------- small PTX helpers ----------------
__device__ __forceinline__ unsigned su32(const void* p) {
    return (unsigned)__cvta_generic_to_shared(p);
}
__device__ __forceinline__ void cpa16(const void* smem_dst, const float* g) {
    asm volatile("cp.async.ca.shared.global [%0], [%1], 16;"
                 :: "r"(su32(smem_dst)), "l"(g));
}
__device__ __forceinline__ void cp_commit() {
    asm volatile("cp.async.commit_group;");
}
template<int N> __device__ __forceinline__ void cp_wait() {
    asm volatile("cp.async.wait_group %0;" :: "n"(N));
}
// tf32 split: x = hi + lo (hi = rna-rounded tf32, lo covers the remainder)
__device__ __forceinline__ void split_tf32(float x, unsigned& hi, unsigned& lo) {
    asm("cvt.rna.tf32.f32 %0, %1;" : "=r"(hi) : "f"(x));
    float r = x - __uint_as_float(hi);
    asm("cvt.rna.tf32.f32 %0, %1;" : "=r"(lo) : "f"(r));
}
__device__ __forceinline__ void mma8(float c[4], const unsigned a[4], const unsigned b[2]) {
    asm volatile(
        "mma.sync.aligned.m16n8k8.row.col.f32.tf32.tf32.f32 "
        "{%0,%1,%2,%3}, {%4,%5,%6,%7}, {%8,%9}, {%0,%1,%2,%3};\n"
        : "+f"(c[0]), "+f"(c[1]), "+f"(c[2]), "+f"(c[3])
        : "r"(a[0]), "r"(a[1]), "r"(a[2]), "r"(a[3]), "r"(b[0]), "r"(b[1]));
}

// ---------------------------------------------------------------------------
// Tensor-core GEMM (3xTF32 == fp32 accuracy):
//   C[M,N] = A[M,K] * B[K,N]   (TRANSB: B is [N,K], computes A * B^T)
// CTA tile 128x64, BK=16, 256 threads = 8 warps (4m x 2n), warp tile 32x32.
// cp.async double-buffered. All shapes here: M%128==0, N%64==0, K%16==0.
// ---------------------------------------------------------------------------
template<bool TRANSB, int EPI>
__global__ void __launch_bounds__(256, 2)
gemm_tc(const float* __restrict__ A, const float* __restrict__ Bm,
        const float* __restrict__ bias, const float* __restrict__ res,
        float* __restrict__ C,
        int K, int lda, int ldb, int ldc,
        long sAb, long sAh, long sBb, long sBh, long sCb, long sCh,
        float scale)
{
    const int z  = blockIdx.z;
    const int bb = z / NHH;
    const int hh = z % NHH;
    A  += bb * sAb + hh * sAh;
    Bm += bb * sBb + hh * sBh;
    C  += bb * sCb + hh * sCh;

    const int row0 = blockIdx.y * 128;
    const int col0 = blockIdx.x * 64;
    const int tid  = threadIdx.x;
    const int lane = tid & 31;
    const int warp = tid >> 5;
    const int wm   = warp & 3;        // 4 warps along M
    const int wn   = warp >> 2;       // 2 warps along N
    const int mo   = wm * 32;         // warp m-offset in tile
    const int no   = wn * 32;         // warp n-offset in tile
    const int q    = lane >> 2;       // groupID   (0..7)
    const int tig  = lane & 3;        // thread-in-group (0..3)

    // A tile m-major, pitch 20 -> fragment LDS is bank-conflict-free.
    __shared__ __align__(16) float As[2][128][20];
    constexpr int BROWS  = TRANSB ? 64 : 16;
    constexpr int BPITCH = TRANSB ? 20 : 72;   // both pitches conflict-free
    __shared__ __align__(16) float Bs[2][BROWS][BPITCH];

    // per-thread load slots
    const int ar = tid >> 2, ac = (tid & 3) * 4;     // A: 128x16, 2 float4/thr
    const int br = tid >> 4, bc = (tid & 15) * 4;    // B nt: 16x64, 1 float4/thr
    // B trans: 64x16, 1 float4/thr, same slot pattern as A

    float acc[2][4][4] = {};

    auto load_stage = [&](int s, int k0) {
        cpa16(&As[s][ar][ac],      A + (long)(row0 + ar)      * lda + k0 + ac);
        cpa16(&As[s][ar + 64][ac], A + (long)(row0 + ar + 64) * lda + k0 + ac);
        if (TRANSB) {
            cpa16(&Bs[s][ar][ac], Bm + (long)(col0 + ar) * ldb + k0 + ac);
        } else {
            cpa16(&Bs[s][br][bc], Bm + (long)(k0 + br) * ldb + col0 + bc);
        }
    };

    auto compute = [&](int s) {
        #pragma unroll
        for (int kk = 0; kk < 16; kk += 8) {
            unsigned ahi[2][4], alo[2][4], bhi[4][2], blo[4][2];
            #pragma unroll
            for (int mt = 0; mt < 2; mt++) {
                const int m = mo + mt * 16 + q;
                split_tf32(As[s][m    ][kk + tig    ], ahi[mt][0], alo[mt][0]);
                split_tf32(As[s][m + 8][kk + tig    ], ahi[mt][1], alo[mt][1]);
                split_tf32(As[s][m    ][kk + tig + 4], ahi[mt][2], alo[mt][2]);
                split_tf32(As[s][m + 8][kk + tig + 4], ahi[mt][3], alo[mt][3]);
            }
            #pragma unroll
            for (int nt = 0; nt < 4; nt++) {
                const int n = no + nt * 8 + q;
                float b0, b1;
                if (TRANSB) { b0 = Bs[s][n][kk + tig];     b1 = Bs[s][n][kk + tig + 4]; }
                else        { b0 = Bs[s][kk + tig][n];     b1 = Bs[s][kk + tig + 4][n]; }
                split_tf32(b0, bhi[nt][0], blo[nt][0]);
                split_tf32(b1, bhi[nt][1], blo[nt][1]);
            }
            // 3xTF32: hi*hi, hi*lo, lo*hi (lo*lo ~2^-22, dropped)
            #pragma unroll
            for (int mt = 0; mt < 2; mt++)
                #pragma unroll
                for (int nt = 0; nt < 4; nt++) mma8(acc[mt][nt], ahi[mt], bhi[nt]);
            #pragma unroll
            for (int mt = 0; mt < 2; mt++)
                #pragma unroll
                for (int nt = 0; nt < 4; nt++) mma8(acc[mt][nt], ahi[mt], blo[nt]);
            #pragma unroll
            for (int mt = 0; mt < 2; mt++)
                #pragma unroll
                for (int nt = 0; nt < 4; nt++) mma8(acc[mt][nt], alo[mt], bhi[nt]);
        }
    };

    load_stage(0, 0);
    cp_commit();
    int cur = 0;
    for (int k0 = 16; k0 < K; k0 += 16) {
        load_stage(cur ^ 1, k0);
        cp_commit();
        cp_wait<1>();
        __syncthreads();
        compute(cur);
        __syncthreads();
        cur ^= 1;
    }
    cp_wait<0>();
    __syncthreads();
    compute(cur);

    // ---- epilogue ----
    #pragma unroll
    for (int mt = 0; mt < 2; mt++) {
        #pragma unroll
        for (int nt = 0; nt < 4; nt++) {
            const int cg = col0 + no + nt * 8 + 2 * tig;
            #pragma unroll
            for (int h = 0; h < 2; h++) {          // h=0 -> c0,c1 ; h=1 -> c2,c3
                const int rg = row0 + mo + mt * 16 + q + h * 8;
                float v0 = acc[mt][nt][h * 2 + 0];
                float v1 = acc[mt][nt][h * 2 + 1];
                if (EPI == EPI_MASKSCALE) {
                    v0 = v0 * scale + res[(long)bb * SS + cg];
                    v1 = v1 * scale + res[(long)bb * SS + cg + 1];
                } else if (EPI != EPI_NONE) {
                    v0 += bias[cg];
                    v1 += bias[cg + 1];
                    if (EPI == EPI_GELU) {
                        v0 = 0.5f * v0 * (1.0f + erff(v0 * 0.70710678118654752440f));
                        v1 = 0.5f * v1 * (1.0f + erff(v1 * 0.70710678118654752440f));
                    } else if (EPI == EPI_BIASRES) {
                        v0 += res[(long)rg * ldc + cg];
                        v1 += res[(long)rg * ldc + cg + 1];
                    }
                }
                *reinterpret_cast<float2*>(&C[(long)rg * ldc + cg]) =
                    make_float2(v0, v1);
            }
        }
    }
}

// ---------------------------------------------------------------------------
// Row softmax over scores: one block per row of length S=1024.
// ---------------------------------------------------------------------------
__global__ void __launch_bounds__(256) softmax_rows(float* __restrict__ sc)
{
    float* p = sc + (long)blockIdx.x * SS;
    const int tid = threadIdx.x;
    __shared__ float red[256];

    float v[4];
    float m = -1e30f;
    #pragma unroll
    for (int i = 0; i < 4; i++) { v[i] = p[tid + i * 256]; m = fmaxf(m, v[i]); }

    red[tid] = m; __syncthreads();
    #pragma unroll
    for (int off = 128; off > 0; off >>= 1) {
        if (tid < off) red[tid] = fmaxf(red[tid], red[tid + off]);
        __syncthreads();
    }
    m = red[0];
    __syncthreads();

    float sum = 0.f;
    #pragma unroll
    for (int i = 0; i < 4; i++) { v[i] = __expf(v[i] - m); sum += v[i]; }

    red[tid] = sum; __syncthreads();
    #pragma unroll
    for (int off = 128; off > 0; off >>= 1) {
        if (tid < off) red[tid] += red[tid + off];
        __syncthreads();
    }
    const float inv = 1.0f / red[0];
    #pragma unroll
    for (int i = 0; i < 4; i++) p[tid + i * 256] = v[i] * inv;
}

// ---------------------------------------------------------------------------
// Row LayerNorm: one block (256 thr) per token row of H=768.
// ---------------------------------------------------------------------------
__global__ void __launch_bounds__(256)
layernorm_rows(const float* __restrict__ in, const float* __restrict__ g,
               const float* __restrict__ b, float* __restrict__ out)
{
    const float* p = in  + (long)blockIdx.x * H;
    float*       o = out + (long)blockIdx.x * H;
    const int tid = threadIdx.x;
    __shared__ float rs[256], rq[256];

    const float x0 = p[tid], x1 = p[tid + 256], x2 = p[tid + 512];
    rs[tid] = x0 + x1 + x2;
    rq[tid] = x0 * x0 + x1 * x1 + x2 * x2;
    __syncthreads();
    #pragma unroll
    for (int off = 128; off > 0; off >>= 1) {
        if (tid < off) { rs[tid] += rs[tid + off]; rq[tid] += rq[tid + off]; }
        __syncthreads();
    }
    const float mean = rs[0] * (1.0f / H);
    const float var  = rq[0] * (1.0f / H) - mean * mean;
    const float inv  = rsqrtf(var + 1e-5f);

    o[tid]       = (x0 - mean) * inv * g[tid]       + b[tid];
    o[tid + 256] = (x1 - mean) * inv * g[tid + 256] + b[tid + 256];
    o[tid + 512] = (x2 - mean) * inv * g[tid + 512] + b[tid + 512];
}

// ---------------------------------------------------------------------------
extern "C" void kernel_launch(void* const* d_in, const int* in_sizes, int n_in,
                              void* d_out, int out_size)
{
    const float* hs    = (const float*)d_in[0];
    const float* mask  = (const float*)d_in[1];
    const float* q_w   = (const float*)d_in[2];
    const float* q_b   = (const float*)d_in[3];
    const float* k_w   = (const float*)d_in[4];
    const float* k_b   = (const float*)d_in[5];
    const float* v_w   = (const float*)d_in[6];
    const float* v_b   = (const float*)d_in[7];
    const float* ao_w  = (const float*)d_in[8];
    const float* ao_b  = (const float*)d_in[9];
    const float* ln1_g = (const float*)d_in[10];
    const float* ln1_b = (const float*)d_in[11];
    const float* ff1_w = (const float*)d_in[12];
    const float* ff1_b = (const float*)d_in[13];
    const float* ff2_w = (const float*)d_in[14];
    const float* ff2_b = (const float*)d_in[15];
    const float* ln2_g = (const float*)d_in[16];
    const float* ln2_b = (const float*)d_in[17];
    float* out = (float*)d_out;

    float *x, *q, *k, *v, *ctx, *t, *attn, *ffh, *sc;
    cudaGetSymbolAddress((void**)&x,    g_x);
    cudaGetSymbolAddress((void**)&q,    g_q);
    cudaGetSymbolAddress((void**)&k,    g_k);
    cudaGetSymbolAddress((void**)&v,    g_v);
    cudaGetSymbolAddress((void**)&ctx,  g_ctx);
    cudaGetSymbolAddress((void**)&t,    g_t);
    cudaGetSymbolAddress((void**)&attn, g_attn);
    cudaGetSymbolAddress((void**)&ffh,  g_ffh);
    cudaGetSymbolAddress((void**)&sc,   g_sc);

    cudaMemcpyAsync(x, hs, (size_t)NTOK * H * sizeof(float),
                    cudaMemcpyDeviceToDevice);

    const dim3 gProj(H / 64,   NTOK / 128, 1);       // 12 x 32
    const dim3 gFF1 (FFD / 64, NTOK / 128, 1);       // 48 x 32
    const dim3 gScr (SS / 64,  SS / 128, BB * NHH);  // 16 x 8 x 48
    const dim3 gCtx (HDD / 64, SS / 128, BB * NHH);  // 1 x 8 x 48

    for (int layer = 0; layer < NLAYER; layer++) {
        // QKV projections
        gemm_tc<false, EPI_BIAS><<<gProj, 256>>>(x, q_w, q_b, nullptr, q,
            H, H, H, H, 0,0, 0,0, 0,0, 1.f);
        gemm_tc<false, EPI_BIAS><<<gProj, 256>>>(x, k_w, k_b, nullptr, k,
            H, H, H, H, 0,0, 0,0, 0,0, 1.f);
        gemm_tc<false, EPI_BIAS><<<gProj, 256>>>(x, v_w, v_b, nullptr, v,
            H, H, H, H, 0,0, 0,0, 0,0, 1.f);

        // scores[b,h] = (Q_bh * K_bh^T) / 8 + mask[b]
        gemm_tc<true, EPI_MASKSCALE><<<gScr, 256>>>(q, k, nullptr, mask, sc,
            HDD, H, H, SS,
            (long)SS * H, HDD,
            (long)SS * H, HDD,
            (long)NHH * SS * SS, (long)SS * SS,
            0.125f);

        softmax_rows<<<BB * NHH * SS, 256>>>(sc);

        // ctx[b,h] = P * V_bh
        gemm_tc<false, EPI_NONE><<<gCtx, 256>>>(sc, v, nullptr, nullptr, ctx,
            SS, SS, H, H,
            (long)NHH * SS * SS, (long)SS * SS,
            (long)SS * H, HDD,
            (long)SS * H, HDD,
            1.f);

        // attention output projection + residual, then LN1
        gemm_tc<false, EPI_BIASRES><<<gProj, 256>>>(ctx, ao_w, ao_b, x, t,
            H, H, H, H, 0,0, 0,0, 0,0, 1.f);
        layernorm_rows<<<NTOK, 256>>>(t, ln1_g, ln1_b, attn);

        // FFN
        gemm_tc<false, EPI_GELU><<<gFF1, 256>>>(attn, ff1_w, ff1_b, nullptr, ffh,
            H, H, FFD, FFD, 0,0, 0,0, 0,0, 1.f);
        gemm_tc<false, EPI_BIASRES><<<gProj, 256>>>(ffh, ff2_w, ff2_b, attn, t,
            FFD, FFD, H, H, 0,0, 0,0, 0,0, 1.f);

        float* dst = (layer == NLAYER - 1) ? out : x;
        layernorm_rows<<<NTOK, 256>>>(t, ln2_g, ln2_b, dst);
    }
}

// round 3
// speedup vs baseline: 1.5778x; 1.0004x over previous
#include <cuda_runtime.h>
#include <math.h>

#define H   768
#define FFD 3072
#define BB  4
#define SS  1024
#define NHH 12
#define HDD 64
#define NTOK (BB*SS)   // 4096
#define NLAYER 6

// ---------------- device scratch (no allocations allowed) ----------------
__device__ float g_x   [NTOK*H];
__device__ float g_q   [NTOK*H];
__device__ float g_k   [NTOK*H];
__device__ float g_v   [NTOK*H];
__device__ float g_ctx [NTOK*H];
__device__ float g_t   [NTOK*H];
__device__ float g_attn[NTOK*H];
__device__ float g_ffh [NTOK*FFD];
__device__ float g_sc  [BB*NHH*SS*SS]; // 201 MB scores/probs

// ---------------- epilogue modes ----------------
#define EPI_NONE      0
#define EPI_BIAS      1
#define EPI_GELU      2
#define EPI_BIASRES   3
#define EPI_MASKSCALE 4

// ---------------- small PTX helpers ----------------
__device__ __forceinline__ unsigned su32(const void* p) {
    return (unsigned)__cvta_generic_to_shared(p);
}
__device__ __forceinline__ void cpa16(const void* smem_dst, const float* g) {
    asm volatile("cp.async.ca.shared.global [%0], [%1], 16;"
                 :: "r"(su32(smem_dst)), "l"(g));
}
__device__ __forceinline__ void cp_commit() {
    asm volatile("cp.async.commit_group;");
}
template<int N> __device__ __forceinline__ void cp_wait() {
    asm volatile("cp.async.wait_group %0;" :: "n"(N));
}
// tf32 split: x = hi + lo (hi = rna-rounded tf32, lo covers the remainder)
__device__ __forceinline__ void split_tf32(float x, unsigned& hi, unsigned& lo) {
    asm("cvt.rna.tf32.f32 %0, %1;" : "=r"(hi) : "f"(x));
    float r = x - __uint_as_float(hi);
    asm("cvt.rna.tf32.f32 %0, %1;" : "=r"(lo) : "f"(r));
}
__device__ __forceinline__ void mma8(float c[4], const unsigned a[4], const unsigned b[2]) {
    asm volatile(
        "mma.sync.aligned.m16n8k8.row.col.f32.tf32.tf32.f32 "
        "{%0,%1,%2,%3}, {%4,%5,%6,%7}, {%8,%9}, {%0,%1,%2,%3};\n"
        : "+f"(c[0]), "+f"(c[1]), "+f"(c[2]), "+f"(c[3])
        : "r"(a[0]), "r"(a[1]), "r"(a[2]), "r"(a[3]), "r"(b[0]), "r"(b[1]));
}

// ---------------------------------------------------------------------------
// Tensor-core GEMM (3xTF32 == fp32 accuracy):
//   C[M,N] = A[M,K] * B[K,N]   (TRANSB: B is [N,K], computes A * B^T)
// CTA tile 128x64, BK=16, 256 threads = 8 warps (4m x 2n), warp tile 32x32.
// cp.async double-buffered. All shapes here: M%128==0, N%64==0, K%16==0.
// ---------------------------------------------------------------------------
template<bool TRANSB, int EPI>
__global__ void __launch_bounds__(256, 2)
gemm_tc(const float* __restrict__ A, const float* __restrict__ Bm,
        const float* __restrict__ bias, const float* __restrict__ res,
        float* __restrict__ C,
        int K, int lda, int ldb, int ldc,
        long sAb, long sAh, long sBb, long sBh, long sCb, long sCh,
        float scale)
{
    const int z  = blockIdx.z;
    const int bb = z / NHH;
    const int hh = z % NHH;
    A  += bb * sAb + hh * sAh;
    Bm += bb * sBb + hh * sBh;
    C  += bb * sCb + hh * sCh;

    const int row0 = blockIdx.y * 128;
    const int col0 = blockIdx.x * 64;
    const int tid  = threadIdx.x;
    const int lane = tid & 31;
    const int warp = tid >> 5;
    const int wm   = warp & 3;        // 4 warps along M
    const int wn   = warp >> 2;       // 2 warps along N
    const int mo   = wm * 32;         // warp m-offset in tile
    const int no   = wn * 32;         // warp n-offset in tile
    const int q    = lane >> 2;       // groupID   (0..7)
    const int tig  = lane & 3;        // thread-in-group (0..3)

    // A tile m-major, pitch 20 -> fragment LDS is bank-conflict-free.
    __shared__ __align__(16) float As[2][128][20];
    constexpr int BROWS  = TRANSB ? 64 : 16;
    constexpr int BPITCH = TRANSB ? 20 : 72;   // both pitches conflict-free
    __shared__ __align__(16) float Bs[2][BROWS][BPITCH];

    // per-thread load slots
    const int ar = tid >> 2, ac = (tid & 3) * 4;     // A: 128x16, 2 float4/thr
    const int br = tid >> 4, bc = (tid & 15) * 4;    // B nt: 16x64, 1 float4/thr
    // B trans: 64x16, 1 float4/thr, same slot pattern as A

    float acc[2][4][4] = {};

    auto load_stage = [&](int s, int k0) {
        cpa16(&As[s][ar][ac],      A + (long)(row0 + ar)      * lda + k0 + ac);
        cpa16(&As[s][ar + 64][ac], A + (long)(row0 + ar + 64) * lda + k0 + ac);
        if (TRANSB) {
            cpa16(&Bs[s][ar][ac], Bm + (long)(col0 + ar) * ldb + k0 + ac);
        } else {
            cpa16(&Bs[s][br][bc], Bm + (long)(k0 + br) * ldb + col0 + bc);
        }
    };

    auto compute = [&](int s) {
        #pragma unroll
        for (int kk = 0; kk < 16; kk += 8) {
            unsigned ahi[2][4], alo[2][4], bhi[4][2], blo[4][2];
            #pragma unroll
            for (int mt = 0; mt < 2; mt++) {
                const int m = mo + mt * 16 + q;
                split_tf32(As[s][m    ][kk + tig    ], ahi[mt][0], alo[mt][0]);
                split_tf32(As[s][m + 8][kk + tig    ], ahi[mt][1], alo[mt][1]);
                split_tf32(As[s][m    ][kk + tig + 4], ahi[mt][2], alo[mt][2]);
                split_tf32(As[s][m + 8][kk + tig + 4], ahi[mt][3], alo[mt][3]);
            }
            #pragma unroll
            for (int nt = 0; nt < 4; nt++) {
                const int n = no + nt * 8 + q;
                float b0, b1;
                if (TRANSB) { b0 = Bs[s][n][kk + tig];     b1 = Bs[s][n][kk + tig + 4]; }
                else        { b0 = Bs[s][kk + tig][n];     b1 = Bs[s][kk + tig + 4][n]; }
                split_tf32(b0, bhi[nt][0], blo[nt][0]);
                split_tf32(b1, bhi[nt][1], blo[nt][1]);
            }
            // 3xTF32: hi*hi, hi*lo, lo*hi (lo*lo ~2^-22, dropped)
            #pragma unroll
            for (int mt = 0; mt < 2; mt++)
                #pragma unroll
                for (int nt = 0; nt < 4; nt++) mma8(acc[mt][nt], ahi[mt], bhi[nt]);
            #pragma unroll
            for (int mt = 0; mt < 2; mt++)
                #pragma unroll
                for (int nt = 0; nt < 4; nt++) mma8(acc[mt][nt], ahi[mt], blo[nt]);
            #pragma unroll
            for (int mt = 0; mt < 2; mt++)
                #pragma unroll
                for (int nt = 0; nt < 4; nt++) mma8(acc[mt][nt], alo[mt], bhi[nt]);
        }
    };

    load_stage(0, 0);
    cp_commit();
    int cur = 0;
    for (int k0 = 16; k0 < K; k0 += 16) {
        load_stage(cur ^ 1, k0);
        cp_commit();
        cp_wait<1>();
        __syncthreads();
        compute(cur);
        __syncthreads();
        cur ^= 1;
    }
    cp_wait<0>();
    __syncthreads();
    compute(cur);

    // ---- epilogue ----
    #pragma unroll
    for (int mt = 0; mt < 2; mt++) {
        #pragma unroll
        for (int nt = 0; nt < 4; nt++) {
            const int cg = col0 + no + nt * 8 + 2 * tig;
            #pragma unroll
            for (int h = 0; h < 2; h++) {          // h=0 -> c0,c1 ; h=1 -> c2,c3
                const int rg = row0 + mo + mt * 16 + q + h * 8;
                float v0 = acc[mt][nt][h * 2 + 0];
                float v1 = acc[mt][nt][h * 2 + 1];
                if (EPI == EPI_MASKSCALE) {
                    v0 = v0 * scale + res[(long)bb * SS + cg];
                    v1 = v1 * scale + res[(long)bb * SS + cg + 1];
                } else if (EPI != EPI_NONE) {
                    v0 += bias[cg];
                    v1 += bias[cg + 1];
                    if (EPI == EPI_GELU) {
                        v0 = 0.5f * v0 * (1.0f + erff(v0 * 0.70710678118654752440f));
                        v1 = 0.5f * v1 * (1.0f + erff(v1 * 0.70710678118654752440f));
                    } else if (EPI == EPI_BIASRES) {
                        v0 += res[(long)rg * ldc + cg];
                        v1 += res[(long)rg * ldc + cg + 1];
                    }
                }
                *reinterpret_cast<float2*>(&C[(long)rg * ldc + cg]) =
                    make_float2(v0, v1);
            }
        }
    }
}

// ---------------------------------------------------------------------------
// Row softmax over scores: one block per row of length S=1024.
// ---------------------------------------------------------------------------
__global__ void __launch_bounds__(256) softmax_rows(float* __restrict__ sc)
{
    float* p = sc + (long)blockIdx.x * SS;
    const int tid = threadIdx.x;
    __shared__ float red[256];

    float v[4];
    float m = -1e30f;
    #pragma unroll
    for (int i = 0; i < 4; i++) { v[i] = p[tid + i * 256]; m = fmaxf(m, v[i]); }

    red[tid] = m; __syncthreads();
    #pragma unroll
    for (int off = 128; off > 0; off >>= 1) {
        if (tid < off) red[tid] = fmaxf(red[tid], red[tid + off]);
        __syncthreads();
    }
    m = red[0];
    __syncthreads();

    float sum = 0.f;
    #pragma unroll
    for (int i = 0; i < 4; i++) { v[i] = __expf(v[i] - m); sum += v[i]; }

    red[tid] = sum; __syncthreads();
    #pragma unroll
    for (int off = 128; off > 0; off >>= 1) {
        if (tid < off) red[tid] += red[tid + off];
        __syncthreads();
    }
    const float inv = 1.0f / red[0];
    #pragma unroll
    for (int i = 0; i < 4; i++) p[tid + i * 256] = v[i] * inv;
}

// ---------------------------------------------------------------------------
// Row LayerNorm: one block (256 thr) per token row of H=768.
// ---------------------------------------------------------------------------
__global__ void __launch_bounds__(256)
layernorm_rows(const float* __restrict__ in, const float* __restrict__ g,
               const float* __restrict__ b, float* __restrict__ out)
{
    const float* p = in  + (long)blockIdx.x * H;
    float*       o = out + (long)blockIdx.x * H;
    const int tid = threadIdx.x;
    __shared__ float rs[256], rq[256];

    const float x0 = p[tid], x1 = p[tid + 256], x2 = p[tid + 512];
    rs[tid] = x0 + x1 + x2;
    rq[tid] = x0 * x0 + x1 * x1 + x2 * x2;
    __syncthreads();
    #pragma unroll
    for (int off = 128; off > 0; off >>= 1) {
        if (tid < off) { rs[tid] += rs[tid + off]; rq[tid] += rq[tid + off]; }
        __syncthreads();
    }
    const float mean = rs[0] * (1.0f / H);
    const float var  = rq[0] * (1.0f / H) - mean * mean;
    const float inv  = rsqrtf(var + 1e-5f);

    o[tid]       = (x0 - mean) * inv * g[tid]       + b[tid];
    o[tid + 256] = (x1 - mean) * inv * g[tid + 256] + b[tid + 256];
    o[tid + 512] = (x2 - mean) * inv * g[tid + 512] + b[tid + 512];
}

// ---------------------------------------------------------------------------
extern "C" void kernel_launch(void* const* d_in, const int* in_sizes, int n_in,
                              void* d_out, int out_size)
{
    const float* hs    = (const float*)d_in[0];
    const float* mask  = (const float*)d_in[1];
    const float* q_w   = (const float*)d_in[2];
    const float* q_b   = (const float*)d_in[3];
    const float* k_w   = (const float*)d_in[4];
    const float* k_b   = (const float*)d_in[5];
    const float* v_w   = (const float*)d_in[6];
    const float* v_b   = (const float*)d_in[7];
    const float* ao_w  = (const float*)d_in[8];
    const float* ao_b  = (const float*)d_in[9];
    const float* ln1_g = (const float*)d_in[10];
    const float* ln1_b = (const float*)d_in[11];
    const float* ff1_w = (const float*)d_in[12];
    const float* ff1_b = (const float*)d_in[13];
    const float* ff2_w = (const float*)d_in[14];
    const float* ff2_b = (const float*)d_in[15];
    const float* ln2_g = (const float*)d_in[16];
    const float* ln2_b = (const float*)d_in[17];
    float* out = (float*)d_out;

    float *x, *q, *k, *v, *ctx, *t, *attn, *ffh, *sc;
    cudaGetSymbolAddress((void**)&x,    g_x);
    cudaGetSymbolAddress((void**)&q,    g_q);
    cudaGetSymbolAddress((void**)&k,    g_k);
    cudaGetSymbolAddress((void**)&v,    g_v);
    cudaGetSymbolAddress((void**)&ctx,  g_ctx);
    cudaGetSymbolAddress((void**)&t,    g_t);
    cudaGetSymbolAddress((void**)&attn, g_attn);
    cudaGetSymbolAddress((void**)&ffh,  g_ffh);
    cudaGetSymbolAddress((void**)&sc,   g_sc);

    cudaMemcpyAsync(x, hs, (size_t)NTOK * H * sizeof(float),
                    cudaMemcpyDeviceToDevice);

    const dim3 gProj(H / 64,   NTOK / 128, 1);       // 12 x 32
    const dim3 gFF1 (FFD / 64, NTOK / 128, 1);       // 48 x 32
    const dim3 gScr (SS / 64,  SS / 128, BB * NHH);  // 16 x 8 x 48
    const dim3 gCtx (HDD / 64, SS / 128, BB * NHH);  // 1 x 8 x 48

    for (int layer = 0; layer < NLAYER; layer++) {
        // QKV projections
        gemm_tc<false, EPI_BIAS><<<gProj, 256>>>(x, q_w, q_b, nullptr, q,
            H, H, H, H, 0,0, 0,0, 0,0, 1.f);
        gemm_tc<false, EPI_BIAS><<<gProj, 256>>>(x, k_w, k_b, nullptr, k,
            H, H, H, H, 0,0, 0,0, 0,0, 1.f);
        gemm_tc<false, EPI_BIAS><<<gProj, 256>>>(x, v_w, v_b, nullptr, v,
            H, H, H, H, 0,0, 0,0, 0,0, 1.f);

        // scores[b,h] = (Q_bh * K_bh^T) / 8 + mask[b]
        gemm_tc<true, EPI_MASKSCALE><<<gScr, 256>>>(q, k, nullptr, mask, sc,
            HDD, H, H, SS,
            (long)SS * H, HDD,
            (long)SS * H, HDD,
            (long)NHH * SS * SS, (long)SS * SS,
            0.125f);

        softmax_rows<<<BB * NHH * SS, 256>>>(sc);

        // ctx[b,h] = P * V_bh
        gemm_tc<false, EPI_NONE><<<gCtx, 256>>>(sc, v, nullptr, nullptr, ctx,
            SS, SS, H, H,
            (long)NHH * SS * SS, (long)SS * SS,
            (long)SS * H, HDD,
            (long)SS * H, HDD,
            1.f);

        // attention output projection + residual, then LN1
        gemm_tc<false, EPI_BIASRES><<<gProj, 256>>>(ctx, ao_w, ao_b, x, t,
            H, H, H, H, 0,0, 0,0, 0,0, 1.f);
        layernorm_rows<<<NTOK, 256>>>(t, ln1_g, ln1_b, attn);

        // FFN
        gemm_tc<false, EPI_GELU><<<gFF1, 256>>>(attn, ff1_w, ff1_b, nullptr, ffh,
            H, H, FFD, FFD, 0,0, 0,0, 0,0, 1.f);
        gemm_tc<false, EPI_BIASRES><<<gProj, 256>>>(ffh, ff2_w, ff2_b, attn, t,
            FFD, FFD, H, H, 0,0, 0,0, 0,0, 1.f);

        float* dst = (layer == NLAYER - 1) ? out : x;
        layernorm_rows<<<NTOK, 256>>>(t, ln2_g, ln2_b, dst);
    }
}

// round 5
// speedup vs baseline: 2.4179x; 1.5324x over previous
#include <cuda_runtime.h>
#include <cuda_bf16.h>
#include <math.h>
#include <stdint.h>

#define H    768
#define FFD  3072
#define BB   4
#define SS   1024
#define NHH  12
#define HDD  64
#define NTOK 4096
#define NLAYER 6

typedef __nv_bfloat16 bf16;

// ---------------- device scratch ----------------
__device__ float g_x [NTOK*H];
__device__ float g_v [NTOK*H];
__device__ float g_t [NTOK*H];
__device__ float g_at[NTOK*H];
__device__ float g_sc[(long)BB*NHH*SS*SS];
__device__ bf16 g_xh[NTOK*H],  g_xl[NTOK*H];
__device__ bf16 g_qh[NTOK*H],  g_ql[NTOK*H];
__device__ bf16 g_kh[NTOK*H],  g_kl[NTOK*H];
__device__ bf16 g_vth[NTOK*H], g_vtl[NTOK*H];
__device__ bf16 g_ch[NTOK*H],  g_cl[NTOK*H];
__device__ bf16 g_ah[NTOK*H],  g_al[NTOK*H];
__device__ bf16 g_fh[NTOK*FFD], g_fl[NTOK*FFD];
__device__ bf16 g_ph[(long)BB*NHH*SS*SS], g_pl[(long)BB*NHH*SS*SS];
__device__ bf16 g_wqh[H*H], g_wql[H*H], g_wkh[H*H], g_wkl[H*H];
__device__ bf16 g_wvh[H*H], g_wvl[H*H], g_wah[H*H], g_wal[H*H];
__device__ bf16 g_w1h[H*FFD], g_w1l[H*FFD], g_w2h[H*FFD], g_w2l[H*FFD];

#define EPI_NONE      0
#define EPI_BIAS      1
#define EPI_GELU      2
#define EPI_BIASRES   3
#define EPI_MASKSCALE 4
#define OUT_F32   0
#define OUT_SPLIT 1

__device__ __forceinline__ uint32_t su32(const void* p) {
    return (uint32_t)__cvta_generic_to_shared(p);
}
__device__ __forceinline__ void cpa16(void* s, const void* g) {
    asm volatile("cp.async.ca.shared.global [%0], [%1], 16;" :: "r"(su32(s)), "l"(g));
}
__device__ __forceinline__ void cp_commit() { asm volatile("cp.async.commit_group;"); }
template<int N> __device__ __forceinline__ void cp_wait() {
    asm volatile("cp.async.wait_group %0;" :: "n"(N));
}
__device__ __forceinline__ void mma16(float c[4], const uint32_t a[4], const uint32_t b[2]) {
    asm volatile(
        "mma.sync.aligned.m16n8k16.row.col.f32.bf16.bf16.f32 "
        "{%0,%1,%2,%3}, {%4,%5,%6,%7}, {%8,%9}, {%0,%1,%2,%3};\n"
        : "+f"(c[0]), "+f"(c[1]), "+f"(c[2]), "+f"(c[3])
        : "r"(a[0]), "r"(a[1]), "r"(a[2]), "r"(a[3]), "r"(b[0]), "r"(b[1]));
}
__device__ __forceinline__ void spbf(float x, bf16& hi, bf16& lo) {
    hi = __float2bfloat16(x);
    lo = __float2bfloat16(x - __bfloat162float(hi));
}

// ---------------------------------------------------------------------------
// bf16 split GEMM on tensor cores: C[M,N] = (Ah+Al)[M,K] * (Bh+Bl)[N,K]^T
// 3 products hi*hi + hi*lo + lo*hi, fp32 accumulate. CTA tile 128x64, BK=32,
// 256 thr = 8 warps (4m x 2n), warp tile 32x32. cp.async double-buffered,
// 16B-chunk XOR swizzle -> conflict-free LDS fragments.
// ---------------------------------------------------------------------------
template<int EPI, int OUTM>
__global__ void __launch_bounds__(256, 2)
gemm_bf(const bf16* __restrict__ Ah, const bf16* __restrict__ Al,
        const bf16* __restrict__ Bh, const bf16* __restrict__ Bl,
        const float* __restrict__ bias, const float* __restrict__ res,
        float* __restrict__ Cf, bf16* __restrict__ Ch, bf16* __restrict__ Cl,
        int K, int lda, int ldb, int ldc,
        long sAb, long sAhh, long sBb, long sBhh, long sCb, long sChh,
        float scale)
{
    extern __shared__ __align__(16) char smem[];   // 2 stages x 24576 B
    const int tid = threadIdx.x, lane = tid & 31, warp = tid >> 5;
    const int bb = blockIdx.z / NHH, hh = blockIdx.z % NHH;
    const long aoff = bb * sAb + hh * sAhh;
    const long boff = bb * sBb + hh * sBhh;
    const long coff = bb * sCb + hh * sChh;
    Ah += aoff; Al += aoff; Bh += boff; Bl += boff;
    const int row0 = blockIdx.y * 128, col0 = blockIdx.x * 64;
    const int wm = warp & 3, wn = warp >> 2;
    const int q = lane >> 2, t = lane & 3;

    auto load_stage = [&](int s, int k0) {
        char* base = smem + s * 24576;
        #pragma unroll
        for (int i = 0; i < 4; i++) {              // A hi+lo: 1024 chunks
            int c = tid + i * 256, tile = c >> 9, rem = c & 511;
            int r = rem >> 2, cj = rem & 3;
            const bf16* src = (tile ? Al : Ah) + (long)(row0 + r) * lda + k0 + cj * 8;
            cpa16(base + tile * 8192 + r * 64 + ((cj ^ ((r >> 1) & 3)) * 16), src);
        }
        #pragma unroll
        for (int i = 0; i < 2; i++) {              // B hi+lo: 512 chunks
            int c = tid + i * 256, tile = c >> 8, rem = c & 255;
            int r = rem >> 2, cj = rem & 3;
            const bf16* src = (tile ? Bl : Bh) + (long)(col0 + r) * ldb + k0 + cj * 8;
            cpa16(base + 16384 + tile * 4096 + r * 64 + ((cj ^ ((r >> 1) & 3)) * 16), src);
        }
        cp_commit();
    };

    float acc[2][4][4] = {};

    auto frag_a = [&](const char* ab, int mt, int ks, uint32_t a[4]) {
        const int r1 = wm * 32 + mt * 16 + q, r2 = r1 + 8;
        const int c0 = ks * 2, c1 = ks * 2 + 1;
        a[0] = *(const uint32_t*)(ab + r1 * 64 + ((c0 ^ ((r1 >> 1) & 3)) * 16) + t * 4);
        a[1] = *(const uint32_t*)(ab + r2 * 64 + ((c0 ^ ((r2 >> 1) & 3)) * 16) + t * 4);
        a[2] = *(const uint32_t*)(ab + r1 * 64 + ((c1 ^ ((r1 >> 1) & 3)) * 16) + t * 4);
        a[3] = *(const uint32_t*)(ab + r2 * 64 + ((c1 ^ ((r2 >> 1) & 3)) * 16) + t * 4);
    };
    auto frag_b = [&](const char* bbp, int nt, int ks, uint32_t b[2]) {
        const int r = wn * 32 + nt * 8 + q;
        const int c0 = ks * 2, c1 = ks * 2 + 1;
        b[0] = *(const uint32_t*)(bbp + r * 64 + ((c0 ^ ((r >> 1) & 3)) * 16) + t * 4);
        b[1] = *(const uint32_t*)(bbp + r * 64 + ((c1 ^ ((r >> 1) & 3)) * 16) + t * 4);
    };
    auto compute = [&](int s) {
        char* base = smem + s * 24576;
        #pragma unroll
        for (int ks = 0; ks < 2; ks++) {
            uint32_t ahi[2][4], alo[2][4], bhi[4][2], blo[4][2];
            #pragma unroll
            for (int mt = 0; mt < 2; mt++) {
                frag_a(base,        mt, ks, ahi[mt]);
                frag_a(base + 8192, mt, ks, alo[mt]);
            }
            #pragma unroll
            for (int nt = 0; nt < 4; nt++) {
                frag_b(base + 16384, nt, ks, bhi[nt]);
                frag_b(base + 20480, nt, ks, blo[nt]);
            }
            #pragma unroll
            for (int mt = 0; mt < 2; mt++)
                #pragma unroll
                for (int nt = 0; nt < 4; nt++) {
                    mma16(acc[mt][nt], ahi[mt], bhi[nt]);
                    mma16(acc[mt][nt], ahi[mt], blo[nt]);
                    mma16(acc[mt][nt], alo[mt], bhi[nt]);
                }
        }
    };

    load_stage(0, 0);
    int cur = 0;
    for (int k0 = 32; k0 < K; k0 += 32) {
        load_stage(cur ^ 1, k0);
        cp_wait<1>();
        __syncthreads();
        compute(cur);
        __syncthreads();
        cur ^= 1;
    }
    cp_wait<0>();
    __syncthreads();
    compute(cur);

    // ---- epilogue ----
    #pragma unroll
    for (int mt = 0; mt < 2; mt++)
        #pragma unroll
        for (int nt = 0; nt < 4; nt++) {
            const int cg = col0 + wn * 32 + nt * 8 + 2 * t;
            #pragma unroll
            for (int h2 = 0; h2 < 2; h2++) {
                const int rg = row0 + wm * 32 + mt * 16 + q + h2 * 8;
                float v0 = acc[mt][nt][h2 * 2 + 0];
                float v1 = acc[mt][nt][h2 * 2 + 1];
                if (EPI == EPI_MASKSCALE) {
                    v0 = v0 * scale + res[(long)bb * SS + cg];
                    v1 = v1 * scale + res[(long)bb * SS + cg + 1];
                } else if (EPI != EPI_NONE) {
                    v0 += bias[cg];
                    v1 += bias[cg + 1];
                    if (EPI == EPI_GELU) {
                        v0 = 0.5f * v0 * (1.0f + erff(v0 * 0.70710678118654752440f));
                        v1 = 0.5f * v1 * (1.0f + erff(v1 * 0.70710678118654752440f));
                    } else if (EPI == EPI_BIASRES) {
                        v0 += res[(long)rg * ldc + cg];
                        v1 += res[(long)rg * ldc + cg + 1];
                    }
                }
                const long o = coff + (long)rg * ldc + cg;
                if (OUTM == OUT_F32) {
                    *(float2*)(Cf + o) = make_float2(v0, v1);
                } else {
                    bf16 h0, l0, h1, l1;
                    spbf(v0, h0, l0); spbf(v1, h1, l1);
                    *(__nv_bfloat162*)(Ch + o) = __halves2bfloat162(h0, h1);
                    *(__nv_bfloat162*)(Cl + o) = __halves2bfloat162(l0, l1);
                }
            }
        }
}

// ---------------------------------------------------------------------------
// 32x32 transpose + split: oh/ol[c][r] = split(in[r][c]) with batch/head strides.
// ---------------------------------------------------------------------------
__global__ void __launch_bounds__(256)
transpose_split(const float* __restrict__ in, bf16* __restrict__ oh,
                bf16* __restrict__ ol, int ldi, int ldo,
                long sib, long sih, long sob, long soh)
{
    __shared__ float tsm[32][33];
    const int bb = blockIdx.z / NHH, hh = blockIdx.z % NHH;
    in += bb * sib + hh * sih;
    const long ooff = bb * sob + hh * soh;
    const int r0 = blockIdx.y * 32, c0 = blockIdx.x * 32;
    const int tx = threadIdx.x & 31, ty = threadIdx.x >> 5;
    #pragma unroll
    for (int i = 0; i < 32; i += 8)
        tsm[ty + i][tx] = in[(long)(r0 + ty + i) * ldi + c0 + tx];
    __syncthreads();
    #pragma unroll
    for (int i = 0; i < 32; i += 8) {
        float v = tsm[tx][ty + i];
        bf16 hb, lb; spbf(v, hb, lb);
        long o = ooff + (long)(c0 + ty + i) * ldo + r0 + tx;
        oh[o] = hb; ol[o] = lb;
    }
}

// ---------------------------------------------------------------------------
// Softmax row (S=1024) fp32 in -> bf16 hi/lo out. 256 thr, 4 consecutive each.
// ---------------------------------------------------------------------------
__global__ void __launch_bounds__(256)
softmax_rows(const float* __restrict__ sc, bf16* __restrict__ ph,
             bf16* __restrict__ pl)
{
    const long off = (long)blockIdx.x * SS;
    const int tid = threadIdx.x, lane = tid & 31, warp = tid >> 5;
    __shared__ float red[8];
    float4 v = ((const float4*)(sc + off))[tid];

    float m = fmaxf(fmaxf(v.x, v.y), fmaxf(v.z, v.w));
    #pragma unroll
    for (int o = 16; o > 0; o >>= 1) m = fmaxf(m, __shfl_xor_sync(~0u, m, o));
    if (lane == 0) red[warp] = m;
    __syncthreads();
    m = red[0];
    #pragma unroll
    for (int i = 1; i < 8; i++) m = fmaxf(m, red[i]);
    __syncthreads();

    v.x = __expf(v.x - m); v.y = __expf(v.y - m);
    v.z = __expf(v.z - m); v.w = __expf(v.w - m);
    float s = v.x + v.y + v.z + v.w;
    #pragma unroll
    for (int o = 16; o > 0; o >>= 1) s += __shfl_xor_sync(~0u, s, o);
    if (lane == 0) red[warp] = s;
    __syncthreads();
    s = red[0];
    #pragma unroll
    for (int i = 1; i < 8; i++) s += red[i];
    const float inv = 1.0f / s;

    bf16 h0, l0, h1, l1;
    spbf(v.x * inv, h0, l0); spbf(v.y * inv, h1, l1);
    *(__nv_bfloat162*)(ph + off + tid * 4) = __halves2bfloat162(h0, h1);
    *(__nv_bfloat162*)(pl + off + tid * 4) = __halves2bfloat162(l0, l1);
    spbf(v.z * inv, h0, l0); spbf(v.w * inv, h1, l1);
    *(__nv_bfloat162*)(ph + off + tid * 4 + 2) = __halves2bfloat162(h0, h1);
    *(__nv_bfloat162*)(pl + off + tid * 4 + 2) = __halves2bfloat162(l0, l1);
}

// ---------------------------------------------------------------------------
// LayerNorm row H=768; fp32 out + optional bf16 hi/lo out.
// ---------------------------------------------------------------------------
template<bool SPLIT>
__global__ void __launch_bounds__(256)
ln_rows(const float* __restrict__ in, const float* __restrict__ g,
        const float* __restrict__ b, float* __restrict__ out,
        bf16* __restrict__ oh, bf16* __restrict__ ol)
{
    const long off = (long)blockIdx.x * H;
    const float* p = in + off;
    const int tid = threadIdx.x;
    __shared__ float rs[256], rq[256];
    const float x0 = p[tid], x1 = p[tid + 256], x2 = p[tid + 512];
    rs[tid] = x0 + x1 + x2;
    rq[tid] = x0 * x0 + x1 * x1 + x2 * x2;
    __syncthreads();
    #pragma unroll
    for (int o = 128; o > 0; o >>= 1) {
        if (tid < o) { rs[tid] += rs[tid + o]; rq[tid] += rq[tid + o]; }
        __syncthreads();
    }
    const float mean = rs[0] * (1.0f / H);
    const float var  = rq[0] * (1.0f / H) - mean * mean;
    const float inv  = rsqrtf(var + 1e-5f);
    #pragma unroll
    for (int i = 0; i < 3; i++) {
        const int c = tid + i * 256;
        const float xv = (i == 0 ? x0 : (i == 1 ? x1 : x2));
        const float o = (xv - mean) * inv * g[c] + b[c];
        out[off + c] = o;
        if (SPLIT) {
            bf16 hb, lb; spbf(o, hb, lb);
            oh[off + c] = hb; ol[off + c] = lb;
        }
    }
}

__global__ void __launch_bounds__(256)
split_arr(const float* __restrict__ in, bf16* __restrict__ oh, bf16* __restrict__ ol)
{
    const int i = blockIdx.x * 256 + threadIdx.x;
    float4 v = ((const float4*)in)[i];
    bf16 h0, l0, h1, l1;
    spbf(v.x, h0, l0); spbf(v.y, h1, l1);
    *(__nv_bfloat162*)(oh + i * 4) = __halves2bfloat162(h0, h1);
    *(__nv_bfloat162*)(ol + i * 4) = __halves2bfloat162(l0, l1);
    spbf(v.z, h0, l0); spbf(v.w, h1, l1);
    *(__nv_bfloat162*)(oh + i * 4 + 2) = __halves2bfloat162(h0, h1);
    *(__nv_bfloat162*)(ol + i * 4 + 2) = __halves2bfloat162(l0, l1);
}

// ---------------------------------------------------------------------------
extern "C" void kernel_launch(void* const* d_in, const int* in_sizes, int n_in,
                              void* d_out, int out_size)
{
    const float* hs    = (const float*)d_in[0];
    const float* mask  = (const float*)d_in[1];
    const float* q_w   = (const float*)d_in[2];
    const float* q_b   = (const float*)d_in[3];
    const float* k_w   = (const float*)d_in[4];
    const float* k_b   = (const float*)d_in[5];
    const float* v_w   = (const float*)d_in[6];
    const float* v_b   = (const float*)d_in[7];
    const float* ao_w  = (const float*)d_in[8];
    const float* ao_b  = (const float*)d_in[9];
    const float* ln1_g = (const float*)d_in[10];
    const float* ln1_b = (const float*)d_in[11];
    const float* ff1_w = (const float*)d_in[12];
    const float* ff1_b = (const float*)d_in[13];
    const float* ff2_w = (const float*)d_in[14];
    const float* ff2_b = (const float*)d_in[15];
    const float* ln2_g = (const float*)d_in[16];
    const float* ln2_b = (const float*)d_in[17];
    float* out = (float*)d_out;

    float *x, *v, *t, *at, *sc;
    bf16 *xh,*xl,*qh,*ql,*kh,*kl,*vth,*vtl,*ch,*cl,*ah,*al,*fh,*fl,*ph,*pl;
    bf16 *wqh,*wql,*wkh,*wkl,*wvh,*wvl,*wah,*wal,*w1h,*w1l,*w2h,*w2l;
    cudaGetSymbolAddress((void**)&x, g_x);    cudaGetSymbolAddress((void**)&v, g_v);
    cudaGetSymbolAddress((void**)&t, g_t);    cudaGetSymbolAddress((void**)&at, g_at);
    cudaGetSymbolAddress((void**)&sc, g_sc);
    cudaGetSymbolAddress((void**)&xh, g_xh);  cudaGetSymbolAddress((void**)&xl, g_xl);
    cudaGetSymbolAddress((void**)&qh, g_qh);  cudaGetSymbolAddress((void**)&ql, g_ql);
    cudaGetSymbolAddress((void**)&kh, g_kh);  cudaGetSymbolAddress((void**)&kl, g_kl);
    cudaGetSymbolAddress((void**)&vth, g_vth);cudaGetSymbolAddress((void**)&vtl, g_vtl);
    cudaGetSymbolAddress((void**)&ch, g_ch);  cudaGetSymbolAddress((void**)&cl, g_cl);
    cudaGetSymbolAddress((void**)&ah, g_ah);  cudaGetSymbolAddress((void**)&al, g_al);
    cudaGetSymbolAddress((void**)&fh, g_fh);  cudaGetSymbolAddress((void**)&fl, g_fl);
    cudaGetSymbolAddress((void**)&ph, g_ph);  cudaGetSymbolAddress((void**)&pl, g_pl);
    cudaGetSymbolAddress((void**)&wqh, g_wqh);cudaGetSymbolAddress((void**)&wql, g_wql);
    cudaGetSymbolAddress((void**)&wkh, g_wkh);cudaGetSymbolAddress((void**)&wkl, g_wkl);
    cudaGetSymbolAddress((void**)&wvh, g_wvh);cudaGetSymbolAddress((void**)&wvl, g_wvl);
    cudaGetSymbolAddress((void**)&wah, g_wah);cudaGetSymbolAddress((void**)&wal, g_wal);
    cudaGetSymbolAddress((void**)&w1h, g_w1h);cudaGetSymbolAddress((void**)&w1l, g_w1l);
    cudaGetSymbolAddress((void**)&w2h, g_w2h);cudaGetSymbolAddress((void**)&w2l, g_w2l);

    const int SMB = 49152;
    cudaFuncSetAttribute(gemm_bf<EPI_BIAS,     OUT_SPLIT>, cudaFuncAttributeMaxDynamicSharedMemorySize, SMB);
    cudaFuncSetAttribute(gemm_bf<EPI_BIAS,     OUT_F32>,   cudaFuncAttributeMaxDynamicSharedMemorySize, SMB);
    cudaFuncSetAttribute(gemm_bf<EPI_MASKSCALE,OUT_F32>,   cudaFuncAttributeMaxDynamicSharedMemorySize, SMB);
    cudaFuncSetAttribute(gemm_bf<EPI_NONE,     OUT_SPLIT>, cudaFuncAttributeMaxDynamicSharedMemorySize, SMB);
    cudaFuncSetAttribute(gemm_bf<EPI_BIASRES,  OUT_F32>,   cudaFuncAttributeMaxDynamicSharedMemorySize, SMB);
    cudaFuncSetAttribute(gemm_bf<EPI_GELU,     OUT_SPLIT>, cudaFuncAttributeMaxDynamicSharedMemorySize, SMB);

    cudaMemcpyAsync(x, hs, (size_t)NTOK * H * sizeof(float), cudaMemcpyDeviceToDevice);
    split_arr<<<NTOK * H / 1024, 256>>>(hs, xh, xl);

    // weight transpose + split (once per launch; shared across layers)
    transpose_split<<<dim3(24, 24, 1), 256>>>(q_w,  wqh, wql, H,   H,   0,0,0,0);
    transpose_split<<<dim3(24, 24, 1), 256>>>(k_w,  wkh, wkl, H,   H,   0,0,0,0);
    transpose_split<<<dim3(24, 24, 1), 256>>>(v_w,  wvh, wvl, H,   H,   0,0,0,0);
    transpose_split<<<dim3(24, 24, 1), 256>>>(ao_w, wah, wal, H,   H,   0,0,0,0);
    transpose_split<<<dim3(96, 24, 1), 256>>>(ff1_w, w1h, w1l, FFD, H,  0,0,0,0);
    transpose_split<<<dim3(24, 96, 1), 256>>>(ff2_w, w2h, w2l, H,  FFD, 0,0,0,0);

    const dim3 gProj(12, 32, 1), gFF1(48, 32, 1);
    const dim3 gScr(16, 8, 48), gCtx(1, 8, 48);
    const long SH = (long)SS * H, S2 = (long)SS * SS, DS = (long)HDD * SS;

    for (int layer = 0; layer < NLAYER; layer++) {
        gemm_bf<EPI_BIAS, OUT_SPLIT><<<gProj, 256, SMB>>>(
            xh, xl, wqh, wql, q_b, nullptr, nullptr, qh, ql,
            H, H, H, H, 0,0, 0,0, 0,0, 1.f);
        gemm_bf<EPI_BIAS, OUT_SPLIT><<<gProj, 256, SMB>>>(
            xh, xl, wkh, wkl, k_b, nullptr, nullptr, kh, kl,
            H, H, H, H, 0,0, 0,0, 0,0, 1.f);
        gemm_bf<EPI_BIAS, OUT_F32><<<gProj, 256, SMB>>>(
            xh, xl, wvh, wvl, v_b, nullptr, v, nullptr, nullptr,
            H, H, H, H, 0,0, 0,0, 0,0, 1.f);

        // vt[b][h][d][s] <- v[b][s][h*64+d], split
        transpose_split<<<dim3(2, 32, 48), 256>>>(v, vth, vtl, H, SS,
            SH, HDD, (long)NHH * DS, DS);

        // scores = Q K^T / 8 + mask
        gemm_bf<EPI_MASKSCALE, OUT_F32><<<gScr, 256, SMB>>>(
            qh, ql, kh, kl, nullptr, mask, sc, nullptr, nullptr,
            HDD, H, H, SS, SH, HDD, SH, HDD, (long)NHH * S2, S2, 0.125f);

        softmax_rows<<<BB * NHH * SS, 256>>>(sc, ph, pl);

        // ctx = P V
        gemm_bf<EPI_NONE, OUT_SPLIT><<<gCtx, 256, SMB>>>(
            ph, pl, vth, vtl, nullptr, nullptr, nullptr, ch, cl,
            SS, SS, SS, H, (long)NHH * S2, S2, (long)NHH * DS, DS, SH, HDD, 1.f);

        gemm_bf<EPI_BIASRES, OUT_F32><<<gProj, 256, SMB>>>(
            ch, cl, wah, wal, ao_b, x, t, nullptr, nullptr,
            H, H, H, H, 0,0, 0,0, 0,0, 1.f);
        ln_rows<true><<<NTOK, 256>>>(t, ln1_g, ln1_b, at, ah, al);

        gemm_bf<EPI_GELU, OUT_SPLIT><<<gFF1, 256, SMB>>>(
            ah, al, w1h, w1l, ff1_b, nullptr, nullptr, fh, fl,
            H, H, H, FFD, 0,0, 0,0, 0,0, 1.f);
        gemm_bf<EPI_BIASRES, OUT_F32><<<gProj, 256, SMB>>>(
            fh, fl, w2h, w2l, ff2_b, at, t, nullptr, nullptr,
            FFD, FFD, FFD, H, 0,0, 0,0, 0,0, 1.f);

        if (layer == NLAYER - 1) {
            ln_rows<false><<<NTOK, 256>>>(t, ln2_g, ln2_b, out, nullptr, nullptr);
        } else {
            ln_rows<true><<<NTOK, 256>>>(t, ln2_g, ln2_b, x, xh, xl);
        }
    }
}

// round 7
// speedup vs baseline: 2.7684x; 1.1450x over previous
#include <cuda_runtime.h>
#include <cuda_bf16.h>
#include <math.h>
#include <stdint.h>

#define H    768
#define FFD  3072
#define BB   4
#define SS   1024
#define NHH  12
#define HDD  64
#define NTOK 4096
#define NLAYER 6

typedef __nv_bfloat16 bf16;

// ---------------- device scratch ----------------
__device__ float g_x [NTOK*H];
__device__ float g_v [NTOK*H];
__device__ float g_t [NTOK*H];
__device__ float g_at[NTOK*H];
__device__ float g_sc[(long)BB*NHH*SS*SS];
__device__ bf16 g_xh[NTOK*H],  g_xl[NTOK*H];
__device__ bf16 g_qh[NTOK*H],  g_ql[NTOK*H];
__device__ bf16 g_kh[NTOK*H],  g_kl[NTOK*H];
__device__ bf16 g_vth[NTOK*H], g_vtl[NTOK*H];
__device__ bf16 g_ch[NTOK*H],  g_cl[NTOK*H];
__device__ bf16 g_ah[NTOK*H],  g_al[NTOK*H];
__device__ bf16 g_fh[NTOK*FFD], g_fl[NTOK*FFD];
__device__ bf16 g_ph[(long)BB*NHH*SS*SS], g_pl[(long)BB*NHH*SS*SS];
__device__ bf16 g_wqh[H*H], g_wql[H*H], g_wkh[H*H], g_wkl[H*H];
__device__ bf16 g_wvh[H*H], g_wvl[H*H], g_wah[H*H], g_wal[H*H];
__device__ bf16 g_w1h[H*FFD], g_w1l[H*FFD], g_w2h[H*FFD], g_w2l[H*FFD];

#define EPI_NONE      0
#define EPI_BIAS      1
#define EPI_GELU      2
#define EPI_BIASRES   3
#define EPI_MASKSCALE 4
#define OUT_F32   0
#define OUT_SPLIT 1

__device__ __forceinline__ uint32_t su32(const void* p) {
    return (uint32_t)__cvta_generic_to_shared(p);
}
__device__ __forceinline__ void cpa16(void* s, const void* g) {
    asm volatile("cp.async.ca.shared.global [%0], [%1], 16;" :: "r"(su32(s)), "l"(g));
}
__device__ __forceinline__ void cp_commit() { asm volatile("cp.async.commit_group;"); }
template<int N> __device__ __forceinline__ void cp_wait() {
    asm volatile("cp.async.wait_group %0;" :: "n"(N));
}
__device__ __forceinline__ void mma16(float c[4], const uint32_t a[4], const uint32_t b[2]) {
    asm volatile(
        "mma.sync.aligned.m16n8k16.row.col.f32.bf16.bf16.f32 "
        "{%0,%1,%2,%3}, {%4,%5,%6,%7}, {%8,%9}, {%0,%1,%2,%3};\n"
        : "+f"(c[0]), "+f"(c[1]), "+f"(c[2]), "+f"(c[3])
        : "r"(a[0]), "r"(a[1]), "r"(a[2]), "r"(a[3]), "r"(b[0]), "r"(b[1]));
}
__device__ __forceinline__ void ldsm4(uint32_t r[4], uint32_t addr) {
    asm volatile("ldmatrix.sync.aligned.m8n8.x4.shared.b16 {%0,%1,%2,%3}, [%4];"
                 : "=r"(r[0]), "=r"(r[1]), "=r"(r[2]), "=r"(r[3]) : "r"(addr));
}
__device__ __forceinline__ void spbf(float x, bf16& hi, bf16& lo) {
    hi = __float2bfloat16(x);
    lo = __float2bfloat16(x - __bfloat162float(hi));
}

// ---------------------------------------------------------------------------
// bf16 split GEMM on tensor cores: C[M,N] = (Ah+Al)[M,K] * (Bh+Bl)[N,K]^T
// 3 products hi*hi + hi*lo + lo*hi, fp32 accumulate. CTA tile 128x64, BK=32,
// 256 thr = 8 warps (4m x 2n), warp tile 32x32. cp.async double-buffered,
// 16B-chunk XOR swizzle; fragments loaded via ldmatrix.x4 (conflict-free).
// ---------------------------------------------------------------------------
template<int EPI, int OUTM>
__global__ void __launch_bounds__(256, 2)
gemm_bf(const bf16* __restrict__ Ah, const bf16* __restrict__ Al,
        const bf16* __restrict__ Bh, const bf16* __restrict__ Bl,
        const float* __restrict__ bias, const float* __restrict__ res,
        float* __restrict__ Cf, bf16* __restrict__ Ch, bf16* __restrict__ Cl,
        int K, int lda, int ldb, int ldc,
        long sAb, long sAhh, long sBb, long sBhh, long sCb, long sChh,
        float scale)
{
    extern __shared__ __align__(16) char smem[];   // 2 stages x 24576 B
    const int tid = threadIdx.x, lane = tid & 31, warp = tid >> 5;
    const int bb = blockIdx.z / NHH, hh = blockIdx.z % NHH;
    const long aoff = bb * sAb + hh * sAhh;
    const long boff = bb * sBb + hh * sBhh;
    const long coff = bb * sCb + hh * sChh;
    Ah += aoff; Al += aoff; Bh += boff; Bl += boff;
    const int row0 = blockIdx.y * 128, col0 = blockIdx.x * 64;
    const int wm = warp & 3, wn = warp >> 2;
    const int q = lane >> 2, t = lane & 3;

    // ldmatrix lane address components
    const int la = lane & 15, ca = lane >> 4;            // A: row-in-frag, k-half
    const int mb = lane >> 3;                            // B: matrix index
    const int rb = ((mb >> 1) << 3) + (lane & 7), cb = mb & 1;
    const uint32_t sbase = su32(smem);

    auto load_stage = [&](int s, int k0) {
        char* base = smem + s * 24576;
        #pragma unroll
        for (int i = 0; i < 4; i++) {              // A hi+lo: 1024 chunks
            int c = tid + i * 256, tile = c >> 9, rem = c & 511;
            int r = rem >> 2, cj = rem & 3;
            const bf16* src = (tile ? Al : Ah) + (long)(row0 + r) * lda + k0 + cj * 8;
            cpa16(base + tile * 8192 + r * 64 + ((cj ^ ((r >> 1) & 3)) * 16), src);
        }
        #pragma unroll
        for (int i = 0; i < 2; i++) {              // B hi+lo: 512 chunks
            int c = tid + i * 256, tile = c >> 8, rem = c & 255;
            int r = rem >> 2, cj = rem & 3;
            const bf16* src = (tile ? Bl : Bh) + (long)(col0 + r) * ldb + k0 + cj * 8;
            cpa16(base + 16384 + tile * 4096 + r * 64 + ((cj ^ ((r >> 1) & 3)) * 16), src);
        }
        cp_commit();
    };

    float acc[2][4][4] = {};

    auto compute = [&](int s) {
        const uint32_t ab = sbase + s * 24576;
        #pragma unroll
        for (int ks = 0; ks < 2; ks++) {
            uint32_t ahi[2][4], alo[2][4], bhi[4][2], blo[4][2];
            #pragma unroll
            for (int mt = 0; mt < 2; mt++) {
                const int r = wm * 32 + mt * 16 + la;
                const int c = 2 * ks + ca;
                const uint32_t ad = ab + r * 64 + ((c ^ ((r >> 1) & 3)) * 16);
                ldsm4(ahi[mt], ad);
                ldsm4(alo[mt], ad + 8192);
            }
            #pragma unroll
            for (int p = 0; p < 2; p++) {
                const int r = wn * 32 + p * 16 + rb;
                const int c = 2 * ks + cb;
                const uint32_t bd = ab + 16384 + r * 64 + ((c ^ ((r >> 1) & 3)) * 16);
                uint32_t th[4], tl[4];
                ldsm4(th, bd);
                ldsm4(tl, bd + 4096);
                bhi[2*p][0] = th[0]; bhi[2*p][1] = th[1];
                bhi[2*p+1][0] = th[2]; bhi[2*p+1][1] = th[3];
                blo[2*p][0] = tl[0]; blo[2*p][1] = tl[1];
                blo[2*p+1][0] = tl[2]; blo[2*p+1][1] = tl[3];
            }
            #pragma unroll
            for (int mt = 0; mt < 2; mt++)
                #pragma unroll
                for (int nt = 0; nt < 4; nt++) {
                    mma16(acc[mt][nt], ahi[mt], bhi[nt]);
                    mma16(acc[mt][nt], ahi[mt], blo[nt]);
                    mma16(acc[mt][nt], alo[mt], bhi[nt]);
                }
        }
    };

    load_stage(0, 0);
    int cur = 0;
    for (int k0 = 32; k0 < K; k0 += 32) {
        load_stage(cur ^ 1, k0);
        cp_wait<1>();
        __syncthreads();
        compute(cur);
        __syncthreads();
        cur ^= 1;
    }
    cp_wait<0>();
    __syncthreads();
    compute(cur);

    // ---- epilogue ----
    #pragma unroll
    for (int mt = 0; mt < 2; mt++)
        #pragma unroll
        for (int nt = 0; nt < 4; nt++) {
            const int cg = col0 + wn * 32 + nt * 8 + 2 * t;
            #pragma unroll
            for (int h2 = 0; h2 < 2; h2++) {
                const int rg = row0 + wm * 32 + mt * 16 + q + h2 * 8;
                float v0 = acc[mt][nt][h2 * 2 + 0];
                float v1 = acc[mt][nt][h2 * 2 + 1];
                if (EPI == EPI_MASKSCALE) {
                    v0 = v0 * scale + res[(long)bb * SS + cg];
                    v1 = v1 * scale + res[(long)bb * SS + cg + 1];
                } else if (EPI != EPI_NONE) {
                    v0 += bias[cg];
                    v1 += bias[cg + 1];
                    if (EPI == EPI_GELU) {
                        v0 = 0.5f * v0 * (1.0f + erff(v0 * 0.70710678118654752440f));
                        v1 = 0.5f * v1 * (1.0f + erff(v1 * 0.70710678118654752440f));
                    } else if (EPI == EPI_BIASRES) {
                        v0 += res[(long)rg * ldc + cg];
                        v1 += res[(long)rg * ldc + cg + 1];
                    }
                }
                const long o = coff + (long)rg * ldc + cg;
                if (OUTM == OUT_F32) {
                    *(float2*)(Cf + o) = make_float2(v0, v1);
                } else {
                    bf16 h0, l0, h1, l1;
                    spbf(v0, h0, l0); spbf(v1, h1, l1);
                    *(__nv_bfloat162*)(Ch + o) = __halves2bfloat162(h0, h1);
                    *(__nv_bfloat162*)(Cl + o) = __halves2bfloat162(l0, l1);
                }
            }
        }
}

// ---------------------------------------------------------------------------
// 32x32 transpose + split: oh/ol[c][r] = split(in[r][c]) with batch/head strides.
// ---------------------------------------------------------------------------
__global__ void __launch_bounds__(256)
transpose_split(const float* __restrict__ in, bf16* __restrict__ oh,
                bf16* __restrict__ ol, int ldi, int ldo,
                long sib, long sih, long sob, long soh)
{
    __shared__ float tsm[32][33];
    const int bb = blockIdx.z / NHH, hh = blockIdx.z % NHH;
    in += bb * sib + hh * sih;
    const long ooff = bb * sob + hh * soh;
    const int r0 = blockIdx.y * 32, c0 = blockIdx.x * 32;
    const int tx = threadIdx.x & 31, ty = threadIdx.x >> 5;
    #pragma unroll
    for (int i = 0; i < 32; i += 8)
        tsm[ty + i][tx] = in[(long)(r0 + ty + i) * ldi + c0 + tx];
    __syncthreads();
    #pragma unroll
    for (int i = 0; i < 32; i += 8) {
        float v = tsm[tx][ty + i];
        bf16 hb, lb; spbf(v, hb, lb);
        long o = ooff + (long)(c0 + ty + i) * ldo + r0 + tx;
        oh[o] = hb; ol[o] = lb;
    }
}

// ---------------------------------------------------------------------------
// Softmax row (S=1024) fp32 in -> bf16 hi/lo out.
// ---------------------------------------------------------------------------
__global__ void __launch_bounds__(256)
softmax_rows(const float* __restrict__ sc, bf16* __restrict__ ph,
             bf16* __restrict__ pl)
{
    const long off = (long)blockIdx.x * SS;
    const int tid = threadIdx.x, lane = tid & 31, warp = tid >> 5;
    __shared__ float red[8];
    float4 v = ((const float4*)(sc + off))[tid];

    float m = fmaxf(fmaxf(v.x, v.y), fmaxf(v.z, v.w));
    #pragma unroll
    for (int o = 16; o > 0; o >>= 1) m = fmaxf(m, __shfl_xor_sync(~0u, m, o));
    if (lane == 0) red[warp] = m;
    __syncthreads();
    m = red[0];
    #pragma unroll
    for (int i = 1; i < 8; i++) m = fmaxf(m, red[i]);
    __syncthreads();

    v.x = __expf(v.x - m); v.y = __expf(v.y - m);
    v.z = __expf(v.z - m); v.w = __expf(v.w - m);
    float s = v.x + v.y + v.z + v.w;
    #pragma unroll
    for (int o = 16; o > 0; o >>= 1) s += __shfl_xor_sync(~0u, s, o);
    if (lane == 0) red[warp] = s;
    __syncthreads();
    s = red[0];
    #pragma unroll
    for (int i = 1; i < 8; i++) s += red[i];
    const float inv = 1.0f / s;

    bf16 h0, l0, h1, l1;
    spbf(v.x * inv, h0, l0); spbf(v.y * inv, h1, l1);
    *(__nv_bfloat162*)(ph + off + tid * 4) = __halves2bfloat162(h0, h1);
    *(__nv_bfloat162*)(pl + off + tid * 4) = __halves2bfloat162(l0, l1);
    spbf(v.z * inv, h0, l0); spbf(v.w * inv, h1, l1);
    *(__nv_bfloat162*)(ph + off + tid * 4 + 2) = __halves2bfloat162(h0, h1);
    *(__nv_bfloat162*)(pl + off + tid * 4 + 2) = __halves2bfloat162(l0, l1);
}

// ---------------------------------------------------------------------------
// LayerNorm row H=768; fp32 out + optional bf16 hi/lo out.
// ---------------------------------------------------------------------------
template<bool SPLIT>
__global__ void __launch_bounds__(256)
ln_rows(const float* __restrict__ in, const float* __restrict__ g,
        const float* __restrict__ b, float* __restrict__ out,
        bf16* __restrict__ oh, bf16* __restrict__ ol)
{
    const long off = (long)blockIdx.x * H;
    const float* p = in + off;
    const int tid = threadIdx.x;
    __shared__ float rs[256], rq[256];
    const float x0 = p[tid], x1 = p[tid + 256], x2 = p[tid + 512];
    rs[tid] = x0 + x1 + x2;
    rq[tid] = x0 * x0 + x1 * x1 + x2 * x2;
    __syncthreads();
    #pragma unroll
    for (int o = 128; o > 0; o >>= 1) {
        if (tid < o) { rs[tid] += rs[tid + o]; rq[tid] += rq[tid + o]; }
        __syncthreads();
    }
    const float mean = rs[0] * (1.0f / H);
    const float var  = rq[0] * (1.0f / H) - mean * mean;
    const float inv  = rsqrtf(var + 1e-5f);
    #pragma unroll
    for (int i = 0; i < 3; i++) {
        const int c = tid + i * 256;
        const float xv = (i == 0 ? x0 : (i == 1 ? x1 : x2));
        const float o = (xv - mean) * inv * g[c] + b[c];
        out[off + c] = o;
        if (SPLIT) {
            bf16 hb, lb; spbf(o, hb, lb);
            oh[off + c] = hb; ol[off + c] = lb;
        }
    }
}

__global__ void __launch_bounds__(256)
split_arr(const float* __restrict__ in, bf16* __restrict__ oh, bf16* __restrict__ ol)
{
    const int i = blockIdx.x * 256 + threadIdx.x;
    float4 v = ((const float4*)in)[i];
    bf16 h0, l0, h1, l1;
    spbf(v.x, h0, l0); spbf(v.y, h1, l1);
    *(__nv_bfloat162*)(oh + i * 4) = __halves2bfloat162(h0, h1);
    *(__nv_bfloat162*)(ol + i * 4) = __halves2bfloat162(l0, l1);
    spbf(v.z, h0, l0); spbf(v.w, h1, l1);
    *(__nv_bfloat162*)(oh + i * 4 + 2) = __halves2bfloat162(h0, h1);
    *(__nv_bfloat162*)(ol + i * 4 + 2) = __halves2bfloat162(l0, l1);
}

// ---------------------------------------------------------------------------
extern "C" void kernel_launch(void* const* d_in, const int* in_sizes, int n_in,
                              void* d_out, int out_size)
{
    const float* hs    = (const float*)d_in[0];
    const float* mask  = (const float*)d_in[1];
    const float* q_w   = (const float*)d_in[2];
    const float* q_b   = (const float*)d_in[3];
    const float* k_w   = (const float*)d_in[4];
    const float* k_b   = (const float*)d_in[5];
    const float* v_w   = (const float*)d_in[6];
    const float* v_b   = (const float*)d_in[7];
    const float* ao_w  = (const float*)d_in[8];
    const float* ao_b  = (const float*)d_in[9];
    const float* ln1_g = (const float*)d_in[10];
    const float* ln1_b = (const float*)d_in[11];
    const float* ff1_w = (const float*)d_in[12];
    const float* ff1_b = (const float*)d_in[13];
    const float* ff2_w = (const float*)d_in[14];
    const float* ff2_b = (const float*)d_in[15];
    const float* ln2_g = (const float*)d_in[16];
    const float* ln2_b = (const float*)d_in[17];
    float* out = (float*)d_out;

    float *x, *v, *t, *at, *sc;
    bf16 *xh,*xl,*qh,*ql,*kh,*kl,*vth,*vtl,*ch,*cl,*ah,*al,*fh,*fl,*ph,*pl;
    bf16 *wqh,*wql,*wkh,*wkl,*wvh,*wvl,*wah,*wal,*w1h,*w1l,*w2h,*w2l;
    cudaGetSymbolAddress((void**)&x, g_x);    cudaGetSymbolAddress((void**)&v, g_v);
    cudaGetSymbolAddress((void**)&t, g_t);    cudaGetSymbolAddress((void**)&at, g_at);
    cudaGetSymbolAddress((void**)&sc, g_sc);
    cudaGetSymbolAddress((void**)&xh, g_xh);  cudaGetSymbolAddress((void**)&xl, g_xl);
    cudaGetSymbolAddress((void**)&qh, g_qh);  cudaGetSymbolAddress((void**)&ql, g_ql);
    cudaGetSymbolAddress((void**)&kh, g_kh);  cudaGetSymbolAddress((void**)&kl, g_kl);
    cudaGetSymbolAddress((void**)&vth, g_vth);cudaGetSymbolAddress((void**)&vtl, g_vtl);
    cudaGetSymbolAddress((void**)&ch, g_ch);  cudaGetSymbolAddress((void**)&cl, g_cl);
    cudaGetSymbolAddress((void**)&ah, g_ah);  cudaGetSymbolAddress((void**)&al, g_al);
    cudaGetSymbolAddress((void**)&fh, g_fh);  cudaGetSymbolAddress((void**)&fl, g_fl);
    cudaGetSymbolAddress((void**)&ph, g_ph);  cudaGetSymbolAddress((void**)&pl, g_pl);
    cudaGetSymbolAddress((void**)&wqh, g_wqh);cudaGetSymbolAddress((void**)&wql, g_wql);
    cudaGetSymbolAddress((void**)&wkh, g_wkh);cudaGetSymbolAddress((void**)&wkl, g_wkl);
    cudaGetSymbolAddress((void**)&wvh, g_wvh);cudaGetSymbolAddress((void**)&wvl, g_wvl);
    cudaGetSymbolAddress((void**)&wah, g_wah);cudaGetSymbolAddress((void**)&wal, g_wal);
    cudaGetSymbolAddress((void**)&w1h, g_w1h);cudaGetSymbolAddress((void**)&w1l, g_w1l);
    cudaGetSymbolAddress((void**)&w2h, g_w2h);cudaGetSymbolAddress((void**)&w2l, g_w2l);

    const int SMB = 49152;
    cudaFuncSetAttribute(gemm_bf<EPI_BIAS,     OUT_SPLIT>, cudaFuncAttributeMaxDynamicSharedMemorySize, SMB);
    cudaFuncSetAttribute(gemm_bf<EPI_BIAS,     OUT_F32>,   cudaFuncAttributeMaxDynamicSharedMemorySize, SMB);
    cudaFuncSetAttribute(gemm_bf<EPI_MASKSCALE,OUT_F32>,   cudaFuncAttributeMaxDynamicSharedMemorySize, SMB);
    cudaFuncSetAttribute(gemm_bf<EPI_NONE,     OUT_SPLIT>, cudaFuncAttributeMaxDynamicSharedMemorySize, SMB);
    cudaFuncSetAttribute(gemm_bf<EPI_BIASRES,  OUT_F32>,   cudaFuncAttributeMaxDynamicSharedMemorySize, SMB);
    cudaFuncSetAttribute(gemm_bf<EPI_GELU,     OUT_SPLIT>, cudaFuncAttributeMaxDynamicSharedMemorySize, SMB);

    cudaMemcpyAsync(x, hs, (size_t)NTOK * H * sizeof(float), cudaMemcpyDeviceToDevice);
    split_arr<<<NTOK * H / 1024, 256>>>(hs, xh, xl);

    // weight transpose + split (once per launch; shared across layers)
    transpose_split<<<dim3(24, 24, 1), 256>>>(q_w,  wqh, wql, H,   H,   0,0,0,0);
    transpose_split<<<dim3(24, 24, 1), 256>>>(k_w,  wkh, wkl, H,   H,   0,0,0,0);
    transpose_split<<<dim3(24, 24, 1), 256>>>(v_w,  wvh, wvl, H,   H,   0,0,0,0);
    transpose_split<<<dim3(24, 24, 1), 256>>>(ao_w, wah, wal, H,   H,   0,0,0,0);
    transpose_split<<<dim3(96, 24, 1), 256>>>(ff1_w, w1h, w1l, FFD, H,  0,0,0,0);
    transpose_split<<<dim3(24, 96, 1), 256>>>(ff2_w, w2h, w2l, H,  FFD, 0,0,0,0);

    const dim3 gProj(12, 32, 1), gFF1(48, 32, 1);
    const dim3 gScr(16, 8, 48), gCtx(1, 8, 48);
    const long SH = (long)SS * H, S2 = (long)SS * SS, DS = (long)HDD * SS;

    for (int layer = 0; layer < NLAYER; layer++) {
        gemm_bf<EPI_BIAS, OUT_SPLIT><<<gProj, 256, SMB>>>(
            xh, xl, wqh, wql, q_b, nullptr, nullptr, qh, ql,
            H, H, H, H, 0,0, 0,0, 0,0, 1.f);
        gemm_bf<EPI_BIAS, OUT_SPLIT><<<gProj, 256, SMB>>>(
            xh, xl, wkh, wkl, k_b, nullptr, nullptr, kh, kl,
            H, H, H, H, 0,0, 0,0, 0,0, 1.f);
        gemm_bf<EPI_BIAS, OUT_F32><<<gProj, 256, SMB>>>(
            xh, xl, wvh, wvl, v_b, nullptr, v, nullptr, nullptr,
            H, H, H, H, 0,0, 0,0, 0,0, 1.f);

        // vt[b][h][d][s] <- v[b][s][h*64+d], split
        transpose_split<<<dim3(2, 32, 48), 256>>>(v, vth, vtl, H, SS,
            SH, HDD, (long)NHH * DS, DS);

        // scores = Q K^T / 8 + mask
        gemm_bf<EPI_MASKSCALE, OUT_F32><<<gScr, 256, SMB>>>(
            qh, ql, kh, kl, nullptr, mask, sc, nullptr, nullptr,
            HDD, H, H, SS, SH, HDD, SH, HDD, (long)NHH * S2, S2, 0.125f);

        softmax_rows<<<BB * NHH * SS, 256>>>(sc, ph, pl);

        // ctx = P V
        gemm_bf<EPI_NONE, OUT_SPLIT><<<gCtx, 256, SMB>>>(
            ph, pl, vth, vtl, nullptr, nullptr, nullptr, ch, cl,
            SS, SS, SS, H, (long)NHH * S2, S2, (long)NHH * DS, DS, SH, HDD, 1.f);

        gemm_bf<EPI_BIASRES, OUT_F32><<<gProj, 256, SMB>>>(
            ch, cl, wah, wal, ao_b, x, t, nullptr, nullptr,
            H, H, H, H, 0,0, 0,0, 0,0, 1.f);
        ln_rows<true><<<NTOK, 256>>>(t, ln1_g, ln1_b, at, ah, al);

        gemm_bf<EPI_GELU, OUT_SPLIT><<<gFF1, 256, SMB>>>(
            ah, al, w1h, w1l, ff1_b, nullptr, nullptr, fh, fl,
            H, H, H, FFD, 0,0, 0,0, 0,0, 1.f);
        gemm_bf<EPI_BIASRES, OUT_F32><<<gProj, 256, SMB>>>(
            fh, fl, w2h, w2l, ff2_b, at, t, nullptr, nullptr,
            FFD, FFD, FFD, H, 0,0, 0,0, 0,0, 1.f);

        if (layer == NLAYER - 1) {
            ln_rows<false><<<NTOK, 256>>>(t, ln2_g, ln2_b, out, nullptr, nullptr);
        } else {
            ln_rows<true><<<NTOK, 256>>>(t, ln2_g, ln2_b, x, xh, xl);
        }
    }
}

// round 9
// speedup vs baseline: 3.1996x; 1.1557x over previous
#include <cuda_runtime.h>
#include <cuda_bf16.h>
#include <math.h>
#include <stdint.h>

#define H    768
#define FFD  3072
#define BB   4
#define SS   1024
#define NHH  12
#define HDD  64
#define NTOK 4096
#define NLAYER 6

typedef __nv_bfloat16 bf16;

// ---------------- device scratch ----------------
__device__ float g_t [NTOK*H];
__device__ float g_at[NTOK*H];
__device__ float g_x [NTOK*H];
__device__ bf16 g_xh[NTOK*H],  g_xl[NTOK*H];
__device__ bf16 g_qh[NTOK*H],  g_ql[NTOK*H];
__device__ bf16 g_kh[NTOK*H],  g_kl[NTOK*H];
__device__ bf16 g_vh[NTOK*H],  g_vl[NTOK*H];
__device__ bf16 g_ch[NTOK*H],  g_cl[NTOK*H];
__device__ bf16 g_ah[NTOK*H],  g_al[NTOK*H];
__device__ bf16 g_fh[NTOK*FFD], g_fl[NTOK*FFD];
__device__ bf16 g_wqh[H*H], g_wql[H*H], g_wkh[H*H], g_wkl[H*H];
__device__ bf16 g_wvh[H*H], g_wvl[H*H], g_wah[H*H], g_wal[H*H];
__device__ bf16 g_w1h[H*FFD], g_w1l[H*FFD], g_w2h[H*FFD], g_w2l[H*FFD];

#define EPI_NONE      0
#define EPI_BIAS      1
#define EPI_GELU      2
#define EPI_BIASRES   3
#define OUT_F32   0
#define OUT_SPLIT 1

__device__ __forceinline__ uint32_t su32(const void* p) {
    return (uint32_t)__cvta_generic_to_shared(p);
}
__device__ __forceinline__ void cpa16(void* s, const void* g) {
    asm volatile("cp.async.ca.shared.global [%0], [%1], 16;" :: "r"(su32(s)), "l"(g));
}
__device__ __forceinline__ void cp_commit() { asm volatile("cp.async.commit_group;"); }
template<int N> __device__ __forceinline__ void cp_wait() {
    asm volatile("cp.async.wait_group %0;" :: "n"(N));
}
__device__ __forceinline__ void mma16(float c[4], const uint32_t a[4], const uint32_t b[2]) {
    asm volatile(
        "mma.sync.aligned.m16n8k16.row.col.f32.bf16.bf16.f32 "
        "{%0,%1,%2,%3}, {%4,%5,%6,%7}, {%8,%9}, {%0,%1,%2,%3};\n"
        : "+f"(c[0]), "+f"(c[1]), "+f"(c[2]), "+f"(c[3])
        : "r"(a[0]), "r"(a[1]), "r"(a[2]), "r"(a[3]), "r"(b[0]), "r"(b[1]));
}
__device__ __forceinline__ void ldsm4(uint32_t r[4], uint32_t addr) {
    asm volatile("ldmatrix.sync.aligned.m8n8.x4.shared.b16 {%0,%1,%2,%3}, [%4];"
                 : "=r"(r[0]), "=r"(r[1]), "=r"(r[2]), "=r"(r[3]) : "r"(addr));
}
__device__ __forceinline__ void ldsm4t(uint32_t r[4], uint32_t addr) {
    asm volatile("ldmatrix.sync.aligned.m8n8.x4.trans.shared.b16 {%0,%1,%2,%3}, [%4];"
                 : "=r"(r[0]), "=r"(r[1]), "=r"(r[2]), "=r"(r[3]) : "r"(addr));
}
__device__ __forceinline__ void spbf(float x, bf16& hi, bf16& lo) {
    hi = __float2bfloat16(x);
    lo = __float2bfloat16(x - __bfloat162float(hi));
}
__device__ __forceinline__ void pack2(float x, float y, uint32_t& hi, uint32_t& lo) {
    bf16 hx = __float2bfloat16(x), hy = __float2bfloat16(y);
    bf16 lx = __float2bfloat16(x - __bfloat162float(hx));
    bf16 ly = __float2bfloat16(y - __bfloat162float(hy));
    hi = ((uint32_t)__bfloat16_as_ushort(hy) << 16) | __bfloat16_as_ushort(hx);
    lo = ((uint32_t)__bfloat16_as_ushort(ly) << 16) | __bfloat16_as_ushort(lx);
}

// ---------------------------------------------------------------------------
// bf16 split GEMM: C = (Ah+Al)(Bh+Bl)^T, 3 terms, fp32 accum.
// CTA tile 128x64, BK=32, 8 warps, ldmatrix fragments, cp.async double-buffer.
// ---------------------------------------------------------------------------
template<int EPI, int OUTM>
__global__ void __launch_bounds__(256, 2)
gemm_bf(const bf16* __restrict__ Ah, const bf16* __restrict__ Al,
        const bf16* __restrict__ Bh, const bf16* __restrict__ Bl,
        const float* __restrict__ bias, const float* __restrict__ res,
        float* __restrict__ Cf, bf16* __restrict__ Ch, bf16* __restrict__ Cl,
        int K, int lda, int ldb, int ldc)
{
    extern __shared__ __align__(16) char smem[];
    const int tid = threadIdx.x, lane = tid & 31, warp = tid >> 5;
    const int row0 = blockIdx.y * 128, col0 = blockIdx.x * 64;
    const int wm = warp & 3, wn = warp >> 2;
    const int q = lane >> 2, t = lane & 3;
    const int la = lane & 15, ca = lane >> 4;
    const int mb = lane >> 3;
    const int rb = ((mb >> 1) << 3) + (lane & 7), cb = mb & 1;
    const uint32_t sbase = su32(smem);

    auto load_stage = [&](int s, int k0) {
        char* base = smem + s * 24576;
        #pragma unroll
        for (int i = 0; i < 4; i++) {
            int c = tid + i * 256, tile = c >> 9, rem = c & 511;
            int r = rem >> 2, cj = rem & 3;
            const bf16* src = (tile ? Al : Ah) + (long)(row0 + r) * lda + k0 + cj * 8;
            cpa16(base + tile * 8192 + r * 64 + ((cj ^ ((r >> 1) & 3)) * 16), src);
        }
        #pragma unroll
        for (int i = 0; i < 2; i++) {
            int c = tid + i * 256, tile = c >> 8, rem = c & 255;
            int r = rem >> 2, cj = rem & 3;
            const bf16* src = (tile ? Bl : Bh) + (long)(col0 + r) * ldb + k0 + cj * 8;
            cpa16(base + 16384 + tile * 4096 + r * 64 + ((cj ^ ((r >> 1) & 3)) * 16), src);
        }
        cp_commit();
    };

    float acc[2][4][4] = {};

    auto compute = [&](int s) {
        const uint32_t ab = sbase + s * 24576;
        #pragma unroll
        for (int ks = 0; ks < 2; ks++) {
            uint32_t ahi[2][4], alo[2][4], bhi[4][2], blo[4][2];
            #pragma unroll
            for (int mt = 0; mt < 2; mt++) {
                const int r = wm * 32 + mt * 16 + la;
                const int c = 2 * ks + ca;
                const uint32_t ad = ab + r * 64 + ((c ^ ((r >> 1) & 3)) * 16);
                ldsm4(ahi[mt], ad);
                ldsm4(alo[mt], ad + 8192);
            }
            #pragma unroll
            for (int p = 0; p < 2; p++) {
                const int r = wn * 32 + p * 16 + rb;
                const int c = 2 * ks + cb;
                const uint32_t bd = ab + 16384 + r * 64 + ((c ^ ((r >> 1) & 3)) * 16);
                uint32_t th[4], tl[4];
                ldsm4(th, bd);
                ldsm4(tl, bd + 4096);
                bhi[2*p][0] = th[0]; bhi[2*p][1] = th[1];
                bhi[2*p+1][0] = th[2]; bhi[2*p+1][1] = th[3];
                blo[2*p][0] = tl[0]; blo[2*p][1] = tl[1];
                blo[2*p+1][0] = tl[2]; blo[2*p+1][1] = tl[3];
            }
            #pragma unroll
            for (int mt = 0; mt < 2; mt++)
                #pragma unroll
                for (int nt = 0; nt < 4; nt++) {
                    mma16(acc[mt][nt], ahi[mt], bhi[nt]);
                    mma16(acc[mt][nt], ahi[mt], blo[nt]);
                    mma16(acc[mt][nt], alo[mt], bhi[nt]);
                }
        }
    };

    load_stage(0, 0);
    int cur = 0;
    for (int k0 = 32; k0 < K; k0 += 32) {
        load_stage(cur ^ 1, k0);
        cp_wait<1>();
        __syncthreads();
        compute(cur);
        __syncthreads();
        cur ^= 1;
    }
    cp_wait<0>();
    __syncthreads();
    compute(cur);

    #pragma unroll
    for (int mt = 0; mt < 2; mt++)
        #pragma unroll
        for (int nt = 0; nt < 4; nt++) {
            const int cg = col0 + wn * 32 + nt * 8 + 2 * t;
            #pragma unroll
            for (int h2 = 0; h2 < 2; h2++) {
                const int rg = row0 + wm * 32 + mt * 16 + q + h2 * 8;
                float v0 = acc[mt][nt][h2 * 2 + 0];
                float v1 = acc[mt][nt][h2 * 2 + 1];
                if (EPI != EPI_NONE) {
                    v0 += bias[cg];
                    v1 += bias[cg + 1];
                    if (EPI == EPI_GELU) {
                        v0 = 0.5f * v0 * (1.0f + erff(v0 * 0.70710678118654752440f));
                        v1 = 0.5f * v1 * (1.0f + erff(v1 * 0.70710678118654752440f));
                    } else if (EPI == EPI_BIASRES) {
                        v0 += res[(long)rg * ldc + cg];
                        v1 += res[(long)rg * ldc + cg + 1];
                    }
                }
                const long o = (long)rg * ldc + cg;
                if (OUTM == OUT_F32) {
                    *(float2*)(Cf + o) = make_float2(v0, v1);
                } else {
                    bf16 h0, l0, h1, l1;
                    spbf(v0, h0, l0); spbf(v1, h1, l1);
                    *(__nv_bfloat162*)(Ch + o) = __halves2bfloat162(h0, h1);
                    *(__nv_bfloat162*)(Cl + o) = __halves2bfloat162(l0, l1);
                }
            }
        }
}

// ---------------------------------------------------------------------------
// Fused flash attention: per (row-block 128, b, h). Q in frags, K/V double-
// buffered, 3-term split mma everywhere, online softmax, ctx hi/lo out.
// smem: Qh 16K | Ql 16K | 2 stages x (Kh|Kl|Vh|Vl each 16K) | mask 4K = 164K
// ---------------------------------------------------------------------------
__global__ void __launch_bounds__(256, 1)
fattn(const bf16* __restrict__ Qh, const bf16* __restrict__ Ql,
      const bf16* __restrict__ Kh, const bf16* __restrict__ Kl,
      const bf16* __restrict__ Vh, const bf16* __restrict__ Vl,
      const float* __restrict__ mask,
      bf16* __restrict__ Ch, bf16* __restrict__ Cl)
{
    extern __shared__ __align__(16) char smem[];
    const int tid = threadIdx.x, lane = tid & 31, warp = tid >> 5;
    const int bh = blockIdx.y, bb = bh / NHH, hh = bh % NHH;
    const int row0 = blockIdx.x * 128;
    const long base = (long)bb * SS * H + hh * HDD;
    const int q = lane >> 2, t = lane & 3;
    const int la = lane & 15, ca = lane >> 4;
    const int mb = lane >> 3;
    const int rb = ((mb >> 1) << 3) + (lane & 7), cb = mb & 1;
    const uint32_t sbase = su32(smem);
    float* mask_s = (float*)(smem + 163840);

    for (int i = tid; i < SS; i += 256) mask_s[i] = mask[(long)bb * SS + i];

    auto load_q = [&]() {
        #pragma unroll
        for (int i = 0; i < 8; i++) {
            int c = tid + i * 256, buf = c >> 10, rem = c & 1023;
            int r = rem >> 3, cj = rem & 7;
            const bf16* src = (buf ? Ql : Qh) + base + (long)(row0 + r) * H + cj * 8;
            cpa16(smem + buf * 16384 + r * 128 + ((cj ^ (r & 7)) * 16), src);
        }
    };
    auto load_kv = [&](int s, int blk) {
        char* sb = smem + 32768 + s * 65536;
        #pragma unroll
        for (int i = 0; i < 16; i++) {
            int c = tid + i * 256, buf = c >> 10, rem = c & 1023;
            int r = rem >> 3, cj = rem & 7;
            const bf16* src =
                (buf == 0 ? Kh : buf == 1 ? Kl : buf == 2 ? Vh : Vl)
                + base + (long)(blk * 128 + r) * H + cj * 8;
            cpa16(sb + buf * 16384 + r * 128 + ((cj ^ (r & 7)) * 16), src);
        }
    };

    load_q();
    load_kv(0, 0);
    cp_commit();                 // group 0: Q + stage 0
    load_kv(1, 1);
    cp_commit();                 // group 1: stage 1
    cp_wait<1>();
    __syncthreads();             // Q + stage 0 ready

    // Q fragments (hi/lo), K-dim 64 -> 4 k16 steps
    uint32_t qfh[4][4], qfl[4][4];
    #pragma unroll
    for (int kk = 0; kk < 4; kk++) {
        const int r = warp * 16 + la;
        const int c = 2 * kk + ca;
        const uint32_t ad = sbase + r * 128 + ((c ^ (r & 7)) * 16);
        ldsm4(qfh[kk], ad);
        ldsm4(qfl[kk], ad + 16384);
    }

    float m0 = -INFINITY, m1 = -INFINITY, l0 = 0.f, l1 = 0.f;
    float o[8][4] = {};

    for (int j = 0; j < 8; j++) {
        const uint32_t stb = sbase + 32768 + (j & 1) * 65536;

        // S = Q K^T (3-term)
        float s[16][4];
        #pragma unroll
        for (int i = 0; i < 16; i++)
            #pragma unroll
            for (int c = 0; c < 4; c++) s[i][c] = 0.f;
        #pragma unroll
        for (int p = 0; p < 8; p++) {
            #pragma unroll
            for (int kk = 0; kk < 4; kk++) {
                const int r = p * 16 + rb;
                const int c = 2 * kk + cb;
                const uint32_t bd = stb + r * 128 + ((c ^ (r & 7)) * 16);
                uint32_t th[4], tl[4];
                ldsm4(th, bd);
                ldsm4(tl, bd + 16384);
                uint32_t b0h[2] = {th[0], th[1]}, b1h[2] = {th[2], th[3]};
                uint32_t b0l[2] = {tl[0], tl[1]}, b1l[2] = {tl[2], tl[3]};
                mma16(s[2*p],   qfh[kk], b0h);
                mma16(s[2*p],   qfh[kk], b0l);
                mma16(s[2*p],   qfl[kk], b0h);
                mma16(s[2*p+1], qfh[kk], b1h);
                mma16(s[2*p+1], qfh[kk], b1l);
                mma16(s[2*p+1], qfl[kk], b1h);
            }
        }

        // scale + mask
        #pragma unroll
        for (int nt = 0; nt < 16; nt++) {
            const int cc = j * 128 + nt * 8 + 2 * t;
            const float mk0 = mask_s[cc], mk1 = mask_s[cc + 1];
            s[nt][0] = s[nt][0] * 0.125f + mk0;
            s[nt][1] = s[nt][1] * 0.125f + mk1;
            s[nt][2] = s[nt][2] * 0.125f + mk0;
            s[nt][3] = s[nt][3] * 0.125f + mk1;
        }

        // online softmax
        float p0 = -INFINITY, p1 = -INFINITY;
        #pragma unroll
        for (int nt = 0; nt < 16; nt++) {
            p0 = fmaxf(p0, fmaxf(s[nt][0], s[nt][1]));
            p1 = fmaxf(p1, fmaxf(s[nt][2], s[nt][3]));
        }
        p0 = fmaxf(p0, __shfl_xor_sync(~0u, p0, 1));
        p0 = fmaxf(p0, __shfl_xor_sync(~0u, p0, 2));
        p1 = fmaxf(p1, __shfl_xor_sync(~0u, p1, 1));
        p1 = fmaxf(p1, __shfl_xor_sync(~0u, p1, 2));
        const float mn0 = fmaxf(m0, p0), mn1 = fmaxf(m1, p1);
        const float a0 = __expf(m0 - mn0), a1 = __expf(m1 - mn1);
        m0 = mn0; m1 = mn1;

        float sum0 = 0.f, sum1 = 0.f;
        #pragma unroll
        for (int nt = 0; nt < 16; nt++) {
            s[nt][0] = __expf(s[nt][0] - m0); sum0 += s[nt][0];
            s[nt][1] = __expf(s[nt][1] - m0); sum0 += s[nt][1];
            s[nt][2] = __expf(s[nt][2] - m1); sum1 += s[nt][2];
            s[nt][3] = __expf(s[nt][3] - m1); sum1 += s[nt][3];
        }
        sum0 += __shfl_xor_sync(~0u, sum0, 1);
        sum0 += __shfl_xor_sync(~0u, sum0, 2);
        sum1 += __shfl_xor_sync(~0u, sum1, 1);
        sum1 += __shfl_xor_sync(~0u, sum1, 2);
        l0 = l0 * a0 + sum0;
        l1 = l1 * a1 + sum1;
        #pragma unroll
        for (int dt = 0; dt < 8; dt++) {
            o[dt][0] *= a0; o[dt][1] *= a0;
            o[dt][2] *= a1; o[dt][3] *= a1;
        }

        // O += P V (3-term), V via ldmatrix.trans
        #pragma unroll
        for (int jk = 0; jk < 8; jk++) {
            uint32_t ah[4], al[4];
            pack2(s[2*jk][0],   s[2*jk][1],   ah[0], al[0]);
            pack2(s[2*jk][2],   s[2*jk][3],   ah[1], al[1]);
            pack2(s[2*jk+1][0], s[2*jk+1][1], ah[2], al[2]);
            pack2(s[2*jk+1][2], s[2*jk+1][3], ah[3], al[3]);
            #pragma unroll
            for (int dtp = 0; dtp < 4; dtp++) {
                const int r = jk * 16 + la;
                const int c = 2 * dtp + ca;
                const uint32_t vd = stb + 32768 + r * 128 + ((c ^ (r & 7)) * 16);
                uint32_t vh4[4], vl4[4];
                ldsm4t(vh4, vd);
                ldsm4t(vl4, vd + 16384);
                uint32_t vb0h[2] = {vh4[0], vh4[1]}, vb1h[2] = {vh4[2], vh4[3]};
                uint32_t vb0l[2] = {vl4[0], vl4[1]}, vb1l[2] = {vl4[2], vl4[3]};
                mma16(o[2*dtp],   ah, vb0h);
                mma16(o[2*dtp],   ah, vb0l);
                mma16(o[2*dtp],   al, vb0h);
                mma16(o[2*dtp+1], ah, vb1h);
                mma16(o[2*dtp+1], ah, vb1l);
                mma16(o[2*dtp+1], al, vb1h);
            }
        }

        __syncthreads();
        if (j < 7) {
            if (j + 2 < 8) { load_kv(j & 1, j + 2); cp_commit(); cp_wait<1>(); }
            else           { cp_wait<0>(); }
            __syncthreads();
        }
    }

    // epilogue: normalize, split, store ctx [tok][H]
    const float i0 = 1.0f / l0, i1 = 1.0f / l1;
    #pragma unroll
    for (int dt = 0; dt < 8; dt++) {
        const int cg = dt * 8 + 2 * t;
        #pragma unroll
        for (int h2 = 0; h2 < 2; h2++) {
            const int rg = row0 + warp * 16 + q + h2 * 8;
            const float inv = h2 ? i1 : i0;
            float v0 = o[dt][h2 * 2 + 0] * inv;
            float v1 = o[dt][h2 * 2 + 1] * inv;
            bf16 h0, lo0, h1, lo1;
            spbf(v0, h0, lo0); spbf(v1, h1, lo1);
            const long off = base + (long)rg * H + cg;
            *(__nv_bfloat162*)(Ch + off) = __halves2bfloat162(h0, h1);
            *(__nv_bfloat162*)(Cl + off) = __halves2bfloat162(lo0, lo1);
        }
    }
}

// ---------------------------------------------------------------------------
// 32x32 transpose + split (weights only).
// ---------------------------------------------------------------------------
__global__ void __launch_bounds__(256)
transpose_split(const float* __restrict__ in, bf16* __restrict__ oh,
                bf16* __restrict__ ol, int ldi, int ldo)
{
    __shared__ float tsm[32][33];
    const int r0 = blockIdx.y * 32, c0 = blockIdx.x * 32;
    const int tx = threadIdx.x & 31, ty = threadIdx.x >> 5;
    #pragma unroll
    for (int i = 0; i < 32; i += 8)
        tsm[ty + i][tx] = in[(long)(r0 + ty + i) * ldi + c0 + tx];
    __syncthreads();
    #pragma unroll
    for (int i = 0; i < 32; i += 8) {
        float v = tsm[tx][ty + i];
        bf16 hb, lb; spbf(v, hb, lb);
        long o = (long)(c0 + ty + i) * ldo + r0 + tx;
        oh[o] = hb; ol[o] = lb;
    }
}

// ---------------------------------------------------------------------------
// LayerNorm row H=768; fp32 out + optional bf16 hi/lo out.
// ---------------------------------------------------------------------------
template<bool SPLIT>
__global__ void __launch_bounds__(256)
ln_rows(const float* __restrict__ in, const float* __restrict__ g,
        const float* __restrict__ b, float* __restrict__ out,
        bf16* __restrict__ oh, bf16* __restrict__ ol)
{
    const long off = (long)blockIdx.x * H;
    const float* p = in + off;
    const int tid = threadIdx.x;
    __shared__ float rs[256], rq[256];
    const float x0 = p[tid], x1 = p[tid + 256], x2 = p[tid + 512];
    rs[tid] = x0 + x1 + x2;
    rq[tid] = x0 * x0 + x1 * x1 + x2 * x2;
    __syncthreads();
    #pragma unroll
    for (int o = 128; o > 0; o >>= 1) {
        if (tid < o) { rs[tid] += rs[tid + o]; rq[tid] += rq[tid + o]; }
        __syncthreads();
    }
    const float mean = rs[0] * (1.0f / H);
    const float var  = rq[0] * (1.0f / H) - mean * mean;
    const float inv  = rsqrtf(var + 1e-5f);
    #pragma unroll
    for (int i = 0; i < 3; i++) {
        const int c = tid + i * 256;
        const float xv = (i == 0 ? x0 : (i == 1 ? x1 : x2));
        const float o = (xv - mean) * inv * g[c] + b[c];
        out[off + c] = o;
        if (SPLIT) {
            bf16 hb, lb; spbf(o, hb, lb);
            oh[off + c] = hb; ol[off + c] = lb;
        }
    }
}

__global__ void __launch_bounds__(256)
split_arr(const float* __restrict__ in, bf16* __restrict__ oh, bf16* __restrict__ ol)
{
    const int i = blockIdx.x * 256 + threadIdx.x;
    float4 v = ((const float4*)in)[i];
    bf16 h0, l0, h1, l1;
    spbf(v.x, h0, l0); spbf(v.y, h1, l1);
    *(__nv_bfloat162*)(oh + i * 4) = __halves2bfloat162(h0, h1);
    *(__nv_bfloat162*)(ol + i * 4) = __halves2bfloat162(l0, l1);
    spbf(v.z, h0, l0); spbf(v.w, h1, l1);
    *(__nv_bfloat162*)(oh + i * 4 + 2) = __halves2bfloat162(h0, h1);
    *(__nv_bfloat162*)(ol + i * 4 + 2) = __halves2bfloat162(l0, l1);
}

// ---------------------------------------------------------------------------
extern "C" void kernel_launch(void* const* d_in, const int* in_sizes, int n_in,
                              void* d_out, int out_size)
{
    const float* hs    = (const float*)d_in[0];
    const float* mask  = (const float*)d_in[1];
    const float* q_w   = (const float*)d_in[2];
    const float* q_b   = (const float*)d_in[3];
    const float* k_w   = (const float*)d_in[4];
    const float* k_b   = (const float*)d_in[5];
    const float* v_w   = (const float*)d_in[6];
    const float* v_b   = (const float*)d_in[7];
    const float* ao_w  = (const float*)d_in[8];
    const float* ao_b  = (const float*)d_in[9];
    const float* ln1_g = (const float*)d_in[10];
    const float* ln1_b = (const float*)d_in[11];
    const float* ff1_w = (const float*)d_in[12];
    const float* ff1_b = (const float*)d_in[13];
    const float* ff2_w = (const float*)d_in[14];
    const float* ff2_b = (const float*)d_in[15];
    const float* ln2_g = (const float*)d_in[16];
    const float* ln2_b = (const float*)d_in[17];
    float* out = (float*)d_out;

    float *x, *t, *at;
    bf16 *xh,*xl,*qh,*ql,*kh,*kl,*vh,*vl,*ch,*cl,*ah,*al,*fh,*fl;
    bf16 *wqh,*wql,*wkh,*wkl,*wvh,*wvl,*wah,*wal,*w1h,*w1l,*w2h,*w2l;
    cudaGetSymbolAddress((void**)&x, g_x);
    cudaGetSymbolAddress((void**)&t, g_t);    cudaGetSymbolAddress((void**)&at, g_at);
    cudaGetSymbolAddress((void**)&xh, g_xh);  cudaGetSymbolAddress((void**)&xl, g_xl);
    cudaGetSymbolAddress((void**)&qh, g_qh);  cudaGetSymbolAddress((void**)&ql, g_ql);
    cudaGetSymbolAddress((void**)&kh, g_kh);  cudaGetSymbolAddress((void**)&kl, g_kl);
    cudaGetSymbolAddress((void**)&vh, g_vh);  cudaGetSymbolAddress((void**)&vl, g_vl);
    cudaGetSymbolAddress((void**)&ch, g_ch);  cudaGetSymbolAddress((void**)&cl, g_cl);
    cudaGetSymbolAddress((void**)&ah, g_ah);  cudaGetSymbolAddress((void**)&al, g_al);
    cudaGetSymbolAddress((void**)&fh, g_fh);  cudaGetSymbolAddress((void**)&fl, g_fl);
    cudaGetSymbolAddress((void**)&wqh, g_wqh);cudaGetSymbolAddress((void**)&wql, g_wql);
    cudaGetSymbolAddress((void**)&wkh, g_wkh);cudaGetSymbolAddress((void**)&wkl, g_wkl);
    cudaGetSymbolAddress((void**)&wvh, g_wvh);cudaGetSymbolAddress((void**)&wvl, g_wvl);
    cudaGetSymbolAddress((void**)&wah, g_wah);cudaGetSymbolAddress((void**)&wal, g_wal);
    cudaGetSymbolAddress((void**)&w1h, g_w1h);cudaGetSymbolAddress((void**)&w1l, g_w1l);
    cudaGetSymbolAddress((void**)&w2h, g_w2h);cudaGetSymbolAddress((void**)&w2l, g_w2l);

    const int SMB = 49152;
    cudaFuncSetAttribute(gemm_bf<EPI_BIAS,   OUT_SPLIT>, cudaFuncAttributeMaxDynamicSharedMemorySize, SMB);
    cudaFuncSetAttribute(gemm_bf<EPI_BIASRES,OUT_F32>,   cudaFuncAttributeMaxDynamicSharedMemorySize, SMB);
    cudaFuncSetAttribute(gemm_bf<EPI_GELU,   OUT_SPLIT>, cudaFuncAttributeMaxDynamicSharedMemorySize, SMB);
    const int SMF = 167936;   // 164 KB
    cudaFuncSetAttribute(fattn, cudaFuncAttributeMaxDynamicSharedMemorySize, SMF);

    cudaMemcpyAsync(x, hs, (size_t)NTOK * H * sizeof(float), cudaMemcpyDeviceToDevice);
    split_arr<<<NTOK * H / 1024, 256>>>(hs, xh, xl);

    transpose_split<<<dim3(24, 24), 256>>>(q_w,  wqh, wql, H,   H);
    transpose_split<<<dim3(24, 24), 256>>>(k_w,  wkh, wkl, H,   H);
    transpose_split<<<dim3(24, 24), 256>>>(v_w,  wvh, wvl, H,   H);
    transpose_split<<<dim3(24, 24), 256>>>(ao_w, wah, wal, H,   H);
    transpose_split<<<dim3(96, 24), 256>>>(ff1_w, w1h, w1l, FFD, H);
    transpose_split<<<dim3(24, 96), 256>>>(ff2_w, w2h, w2l, H,  FFD);

    const dim3 gProj(12, 32), gFF1(48, 32), gAtt(8, 48);

    for (int layer = 0; layer < NLAYER; layer++) {
        gemm_bf<EPI_BIAS, OUT_SPLIT><<<gProj, 256, SMB>>>(
            xh, xl, wqh, wql, q_b, nullptr, nullptr, qh, ql, H, H, H, H);
        gemm_bf<EPI_BIAS, OUT_SPLIT><<<gProj, 256, SMB>>>(
            xh, xl, wkh, wkl, k_b, nullptr, nullptr, kh, kl, H, H, H, H);
        gemm_bf<EPI_BIAS, OUT_SPLIT><<<gProj, 256, SMB>>>(
            xh, xl, wvh, wvl, v_b, nullptr, nullptr, vh, vl, H, H, H, H);

        fattn<<<gAtt, 256, SMF>>>(qh, ql, kh, kl, vh, vl, mask, ch, cl);

        gemm_bf<EPI_BIASRES, OUT_F32><<<gProj, 256, SMB>>>(
            ch, cl, wah, wal, ao_b, x, t, nullptr, nullptr, H, H, H, H);
        ln_rows<true><<<NTOK, 256>>>(t, ln1_g, ln1_b, at, ah, al);

        gemm_bf<EPI_GELU, OUT_SPLIT><<<gFF1, 256, SMB>>>(
            ah, al, w1h, w1l, ff1_b, nullptr, nullptr, fh, fl, H, H, H, FFD);
        gemm_bf<EPI_BIASRES, OUT_F32><<<gProj, 256, SMB>>>(
            fh, fl, w2h, w2l, ff2_b, at, t, nullptr, nullptr, FFD, FFD, FFD, H);

        if (layer == NLAYER - 1) {
            ln_rows<false><<<NTOK, 256>>>(t, ln2_g, ln2_b, out, nullptr, nullptr);
        } else {
            ln_rows<true><<<NTOK, 256>>>(t, ln2_g, ln2_b, x, xh, xl);
        }
    }
}

// round 10
// speedup vs baseline: 3.2439x; 1.0139x over previous
#include <cuda_runtime.h>
#include <cuda_bf16.h>
#include <math.h>
#include <stdint.h>

#define H    768
#define FFD  3072
#define BB   4
#define SS   1024
#define NHH  12
#define HDD  64
#define NTOK 4096
#define NLAYER 6
#define H3   2304   // 3*H packed QKV

typedef __nv_bfloat16 bf16;

// ---------------- device scratch ----------------
__device__ float g_t [NTOK*H];
__device__ float g_at[NTOK*H];
__device__ float g_x [NTOK*H];
__device__ float g_bqkv[H3];
__device__ bf16 g_xh[NTOK*H],   g_xl[NTOK*H];
__device__ bf16 g_qkvh[NTOK*H3], g_qkvl[NTOK*H3];
__device__ bf16 g_ch[NTOK*H],   g_cl[NTOK*H];
__device__ bf16 g_ah[NTOK*H],   g_al[NTOK*H];
__device__ bf16 g_fh[NTOK*FFD], g_fl[NTOK*FFD];
__device__ bf16 g_wqkvh[H3*H],  g_wqkvl[H3*H];
__device__ bf16 g_wah[H*H],     g_wal[H*H];
__device__ bf16 g_w1h[H*FFD],   g_w1l[H*FFD];
__device__ bf16 g_w2h[H*FFD],   g_w2l[H*FFD];

#define EPI_NONE      0
#define EPI_BIAS      1
#define EPI_GELU      2
#define EPI_BIASRES   3
#define OUT_F32   0
#define OUT_SPLIT 1

__device__ __forceinline__ uint32_t su32(const void* p) {
    return (uint32_t)__cvta_generic_to_shared(p);
}
__device__ __forceinline__ void cpa16(void* s, const void* g) {
    asm volatile("cp.async.ca.shared.global [%0], [%1], 16;" :: "r"(su32(s)), "l"(g));
}
__device__ __forceinline__ void cp_commit() { asm volatile("cp.async.commit_group;"); }
template<int N> __device__ __forceinline__ void cp_wait() {
    asm volatile("cp.async.wait_group %0;" :: "n"(N));
}
__device__ __forceinline__ void mma16(float c[4], const uint32_t a[4], const uint32_t b[2]) {
    asm volatile(
        "mma.sync.aligned.m16n8k16.row.col.f32.bf16.bf16.f32 "
        "{%0,%1,%2,%3}, {%4,%5,%6,%7}, {%8,%9}, {%0,%1,%2,%3};\n"
        : "+f"(c[0]), "+f"(c[1]), "+f"(c[2]), "+f"(c[3])
        : "r"(a[0]), "r"(a[1]), "r"(a[2]), "r"(a[3]), "r"(b[0]), "r"(b[1]));
}
__device__ __forceinline__ void ldsm4(uint32_t r[4], uint32_t addr) {
    asm volatile("ldmatrix.sync.aligned.m8n8.x4.shared.b16 {%0,%1,%2,%3}, [%4];"
                 : "=r"(r[0]), "=r"(r[1]), "=r"(r[2]), "=r"(r[3]) : "r"(addr));
}
__device__ __forceinline__ void ldsm4t(uint32_t r[4], uint32_t addr) {
    asm volatile("ldmatrix.sync.aligned.m8n8.x4.trans.shared.b16 {%0,%1,%2,%3}, [%4];"
                 : "=r"(r[0]), "=r"(r[1]), "=r"(r[2]), "=r"(r[3]) : "r"(addr));
}
__device__ __forceinline__ void spbf(float x, bf16& hi, bf16& lo) {
    hi = __float2bfloat16(x);
    lo = __float2bfloat16(x - __bfloat162float(hi));
}
__device__ __forceinline__ void pack2(float x, float y, uint32_t& hi, uint32_t& lo) {
    bf16 hx = __float2bfloat16(x), hy = __float2bfloat16(y);
    bf16 lx = __float2bfloat16(x - __bfloat162float(hx));
    bf16 ly = __float2bfloat16(y - __bfloat162float(hy));
    hi = ((uint32_t)__bfloat16_as_ushort(hy) << 16) | __bfloat16_as_ushort(hx);
    lo = ((uint32_t)__bfloat16_as_ushort(ly) << 16) | __bfloat16_as_ushort(lx);
}

// ---------------------------------------------------------------------------
// bf16 split GEMM: C = (Ah+Al)(Bh+Bl)^T, 3 terms, fp32 accum.
// CTA tile 128x64, BK=32, 8 warps, ldmatrix fragments, 3-stage cp.async.
// ---------------------------------------------------------------------------
template<int EPI, int OUTM>
__global__ void __launch_bounds__(256, 2)
gemm_bf(const bf16* __restrict__ Ah, const bf16* __restrict__ Al,
        const bf16* __restrict__ Bh, const bf16* __restrict__ Bl,
        const float* __restrict__ bias, const float* __restrict__ res,
        float* __restrict__ Cf, bf16* __restrict__ Ch, bf16* __restrict__ Cl,
        int K, int lda, int ldb, int ldc)
{
    extern __shared__ __align__(16) char smem[];   // 3 stages x 24576 B
    const int tid = threadIdx.x, lane = tid & 31, warp = tid >> 5;
    const int row0 = blockIdx.y * 128, col0 = blockIdx.x * 64;
    const int wm = warp & 3, wn = warp >> 2;
    const int q = lane >> 2, t = lane & 3;
    const int la = lane & 15, ca = lane >> 4;
    const int mb = lane >> 3;
    const int rb = ((mb >> 1) << 3) + (lane & 7), cb = mb & 1;
    const uint32_t sbase = su32(smem);

    auto load_stage = [&](int s, int k0) {
        char* base = smem + s * 24576;
        #pragma unroll
        for (int i = 0; i < 4; i++) {
            int c = tid + i * 256, tile = c >> 9, rem = c & 511;
            int r = rem >> 2, cj = rem & 3;
            const bf16* src = (tile ? Al : Ah) + (long)(row0 + r) * lda + k0 + cj * 8;
            cpa16(base + tile * 8192 + r * 64 + ((cj ^ ((r >> 1) & 3)) * 16), src);
        }
        #pragma unroll
        for (int i = 0; i < 2; i++) {
            int c = tid + i * 256, tile = c >> 8, rem = c & 255;
            int r = rem >> 2, cj = rem & 3;
            const bf16* src = (tile ? Bl : Bh) + (long)(col0 + r) * ldb + k0 + cj * 8;
            cpa16(base + 16384 + tile * 4096 + r * 64 + ((cj ^ ((r >> 1) & 3)) * 16), src);
        }
        cp_commit();
    };

    float acc[2][4][4] = {};

    auto compute = [&](int s) {
        const uint32_t ab = sbase + s * 24576;
        #pragma unroll
        for (int ks = 0; ks < 2; ks++) {
            uint32_t ahi[2][4], alo[2][4], bhi[4][2], blo[4][2];
            #pragma unroll
            for (int mt = 0; mt < 2; mt++) {
                const int r = wm * 32 + mt * 16 + la;
                const int c = 2 * ks + ca;
                const uint32_t ad = ab + r * 64 + ((c ^ ((r >> 1) & 3)) * 16);
                ldsm4(ahi[mt], ad);
                ldsm4(alo[mt], ad + 8192);
            }
            #pragma unroll
            for (int p = 0; p < 2; p++) {
                const int r = wn * 32 + p * 16 + rb;
                const int c = 2 * ks + cb;
                const uint32_t bd = ab + 16384 + r * 64 + ((c ^ ((r >> 1) & 3)) * 16);
                uint32_t th[4], tl[4];
                ldsm4(th, bd);
                ldsm4(tl, bd + 4096);
                bhi[2*p][0] = th[0]; bhi[2*p][1] = th[1];
                bhi[2*p+1][0] = th[2]; bhi[2*p+1][1] = th[3];
                blo[2*p][0] = tl[0]; blo[2*p][1] = tl[1];
                blo[2*p+1][0] = tl[2]; blo[2*p+1][1] = tl[3];
            }
            #pragma unroll
            for (int mt = 0; mt < 2; mt++)
                #pragma unroll
                for (int nt = 0; nt < 4; nt++) {
                    mma16(acc[mt][nt], ahi[mt], bhi[nt]);
                    mma16(acc[mt][nt], ahi[mt], blo[nt]);
                    mma16(acc[mt][nt], alo[mt], bhi[nt]);
                }
        }
    };

    const int nIt = K >> 5;
    load_stage(0, 0);
    load_stage(1, 32);
    for (int it = 0; it < nIt; it++) {
        if (it + 2 < nIt) { load_stage((it + 2) % 3, (it + 2) << 5); cp_wait<2>(); }
        else if (it + 1 < nIt) cp_wait<1>();
        else cp_wait<0>();
        __syncthreads();
        compute(it % 3);
        __syncthreads();
    }

    #pragma unroll
    for (int mt = 0; mt < 2; mt++)
        #pragma unroll
        for (int nt = 0; nt < 4; nt++) {
            const int cg = col0 + wn * 32 + nt * 8 + 2 * t;
            #pragma unroll
            for (int h2 = 0; h2 < 2; h2++) {
                const int rg = row0 + wm * 32 + mt * 16 + q + h2 * 8;
                float v0 = acc[mt][nt][h2 * 2 + 0];
                float v1 = acc[mt][nt][h2 * 2 + 1];
                if (EPI != EPI_NONE) {
                    v0 += bias[cg];
                    v1 += bias[cg + 1];
                    if (EPI == EPI_GELU) {
                        v0 = 0.5f * v0 * (1.0f + erff(v0 * 0.70710678118654752440f));
                        v1 = 0.5f * v1 * (1.0f + erff(v1 * 0.70710678118654752440f));
                    } else if (EPI == EPI_BIASRES) {
                        v0 += res[(long)rg * ldc + cg];
                        v1 += res[(long)rg * ldc + cg + 1];
                    }
                }
                const long o = (long)rg * ldc + cg;
                if (OUTM == OUT_F32) {
                    *(float2*)(Cf + o) = make_float2(v0, v1);
                } else {
                    bf16 h0, l0, h1, l1;
                    spbf(v0, h0, l0); spbf(v1, h1, l1);
                    *(__nv_bfloat162*)(Ch + o) = __halves2bfloat162(h0, h1);
                    *(__nv_bfloat162*)(Cl + o) = __halves2bfloat162(l0, l1);
                }
            }
        }
}

// ---------------------------------------------------------------------------
// Fused flash attention: Q/K/V read from packed [tok][2304] hi/lo buffers.
// smem: Qh 16K | Ql 16K | 2 stages x (Kh|Kl|Vh|Vl each 16K) | mask 4K = 164K
// ---------------------------------------------------------------------------
__global__ void __launch_bounds__(256, 1)
fattn(const bf16* __restrict__ QKVh, const bf16* __restrict__ QKVl,
      const float* __restrict__ mask,
      bf16* __restrict__ Ch, bf16* __restrict__ Cl)
{
    extern __shared__ __align__(16) char smem[];
    const int tid = threadIdx.x, lane = tid & 31, warp = tid >> 5;
    const int bh = blockIdx.y, bb = bh / NHH, hh = bh % NHH;
    const int row0 = blockIdx.x * 128;
    const long ibase = (long)bb * SS * H3 + hh * HDD;   // input (packed) base
    const long obase = (long)bb * SS * H  + hh * HDD;   // ctx output base
    const int q = lane >> 2, t = lane & 3;
    const int la = lane & 15, ca = lane >> 4;
    const int mb = lane >> 3;
    const int rb = ((mb >> 1) << 3) + (lane & 7), cb = mb & 1;
    const uint32_t sbase = su32(smem);
    float* mask_s = (float*)(smem + 163840);

    for (int i = tid; i < SS; i += 256) mask_s[i] = mask[(long)bb * SS + i];

    auto load_q = [&]() {
        #pragma unroll
        for (int i = 0; i < 8; i++) {
            int c = tid + i * 256, buf = c >> 10, rem = c & 1023;
            int r = rem >> 3, cj = rem & 7;
            const bf16* src = (buf ? QKVl : QKVh) + ibase + (long)(row0 + r) * H3 + cj * 8;
            cpa16(smem + buf * 16384 + r * 128 + ((cj ^ (r & 7)) * 16), src);
        }
    };
    auto load_kv = [&](int s, int blk) {
        char* sb = smem + 32768 + s * 65536;
        #pragma unroll
        for (int i = 0; i < 16; i++) {
            int c = tid + i * 256, buf = c >> 10, rem = c & 1023;
            int r = rem >> 3, cj = rem & 7;
            // buf 0: K hi (+H), 1: K lo, 2: V hi (+2H), 3: V lo
            const bf16* arr = (buf & 1) ? QKVl : QKVh;
            const int coff = (buf >> 1) ? 2 * H : H;
            const bf16* src = arr + ibase + coff + (long)(blk * 128 + r) * H3 + cj * 8;
            cpa16(sb + buf * 16384 + r * 128 + ((cj ^ (r & 7)) * 16), src);
        }
    };

    load_q();
    load_kv(0, 0);
    cp_commit();                 // group 0: Q + stage 0
    load_kv(1, 1);
    cp_commit();                 // group 1: stage 1
    cp_wait<1>();
    __syncthreads();             // Q + stage 0 ready

    uint32_t qfh[4][4], qfl[4][4];
    #pragma unroll
    for (int kk = 0; kk < 4; kk++) {
        const int r = warp * 16 + la;
        const int c = 2 * kk + ca;
        const uint32_t ad = sbase + r * 128 + ((c ^ (r & 7)) * 16);
        ldsm4(qfh[kk], ad);
        ldsm4(qfl[kk], ad + 16384);
    }

    float m0 = -INFINITY, m1 = -INFINITY, l0 = 0.f, l1 = 0.f;
    float o[8][4] = {};

    for (int j = 0; j < 8; j++) {
        const uint32_t stb = sbase + 32768 + (j & 1) * 65536;

        float s[16][4];
        #pragma unroll
        for (int i = 0; i < 16; i++)
            #pragma unroll
            for (int c = 0; c < 4; c++) s[i][c] = 0.f;
        #pragma unroll
        for (int p = 0; p < 8; p++) {
            #pragma unroll
            for (int kk = 0; kk < 4; kk++) {
                const int r = p * 16 + rb;
                const int c = 2 * kk + cb;
                const uint32_t bd = stb + r * 128 + ((c ^ (r & 7)) * 16);
                uint32_t th[4], tl[4];
                ldsm4(th, bd);
                ldsm4(tl, bd + 16384);
                uint32_t b0h[2] = {th[0], th[1]}, b1h[2] = {th[2], th[3]};
                uint32_t b0l[2] = {tl[0], tl[1]}, b1l[2] = {tl[2], tl[3]};
                mma16(s[2*p],   qfh[kk], b0h);
                mma16(s[2*p],   qfh[kk], b0l);
                mma16(s[2*p],   qfl[kk], b0h);
                mma16(s[2*p+1], qfh[kk], b1h);
                mma16(s[2*p+1], qfh[kk], b1l);
                mma16(s[2*p+1], qfl[kk], b1h);
            }
        }

        #pragma unroll
        for (int nt = 0; nt < 16; nt++) {
            const int cc = j * 128 + nt * 8 + 2 * t;
            const float mk0 = mask_s[cc], mk1 = mask_s[cc + 1];
            s[nt][0] = s[nt][0] * 0.125f + mk0;
            s[nt][1] = s[nt][1] * 0.125f + mk1;
            s[nt][2] = s[nt][2] * 0.125f + mk0;
            s[nt][3] = s[nt][3] * 0.125f + mk1;
        }

        float p0 = -INFINITY, p1 = -INFINITY;
        #pragma unroll
        for (int nt = 0; nt < 16; nt++) {
            p0 = fmaxf(p0, fmaxf(s[nt][0], s[nt][1]));
            p1 = fmaxf(p1, fmaxf(s[nt][2], s[nt][3]));
        }
        p0 = fmaxf(p0, __shfl_xor_sync(~0u, p0, 1));
        p0 = fmaxf(p0, __shfl_xor_sync(~0u, p0, 2));
        p1 = fmaxf(p1, __shfl_xor_sync(~0u, p1, 1));
        p1 = fmaxf(p1, __shfl_xor_sync(~0u, p1, 2));
        const float mn0 = fmaxf(m0, p0), mn1 = fmaxf(m1, p1);
        const float a0 = __expf(m0 - mn0), a1 = __expf(m1 - mn1);
        m0 = mn0; m1 = mn1;

        float sum0 = 0.f, sum1 = 0.f;
        #pragma unroll
        for (int nt = 0; nt < 16; nt++) {
            s[nt][0] = __expf(s[nt][0] - m0); sum0 += s[nt][0];
            s[nt][1] = __expf(s[nt][1] - m0); sum0 += s[nt][1];
            s[nt][2] = __expf(s[nt][2] - m1); sum1 += s[nt][2];
            s[nt][3] = __expf(s[nt][3] - m1); sum1 += s[nt][3];
        }
        sum0 += __shfl_xor_sync(~0u, sum0, 1);
        sum0 += __shfl_xor_sync(~0u, sum0, 2);
        sum1 += __shfl_xor_sync(~0u, sum1, 1);
        sum1 += __shfl_xor_sync(~0u, sum1, 2);
        l0 = l0 * a0 + sum0;
        l1 = l1 * a1 + sum1;
        #pragma unroll
        for (int dt = 0; dt < 8; dt++) {
            o[dt][0] *= a0; o[dt][1] *= a0;
            o[dt][2] *= a1; o[dt][3] *= a1;
        }

        #pragma unroll
        for (int jk = 0; jk < 8; jk++) {
            uint32_t ah[4], al[4];
            pack2(s[2*jk][0],   s[2*jk][1],   ah[0], al[0]);
            pack2(s[2*jk][2],   s[2*jk][3],   ah[1], al[1]);
            pack2(s[2*jk+1][0], s[2*jk+1][1], ah[2], al[2]);
            pack2(s[2*jk+1][2], s[2*jk+1][3], ah[3], al[3]);
            #pragma unroll
            for (int dtp = 0; dtp < 4; dtp++) {
                const int r = jk * 16 + la;
                const int c = 2 * dtp + ca;
                const uint32_t vd = stb + 32768 + r * 128 + ((c ^ (r & 7)) * 16);
                uint32_t vh4[4], vl4[4];
                ldsm4t(vh4, vd);
                ldsm4t(vl4, vd + 16384);
                uint32_t vb0h[2] = {vh4[0], vh4[1]}, vb1h[2] = {vh4[2], vh4[3]};
                uint32_t vb0l[2] = {vl4[0], vl4[1]}, vb1l[2] = {vl4[2], vl4[3]};
                mma16(o[2*dtp],   ah, vb0h);
                mma16(o[2*dtp],   ah, vb0l);
                mma16(o[2*dtp],   al, vb0h);
                mma16(o[2*dtp+1], ah, vb1h);
                mma16(o[2*dtp+1], ah, vb1l);
                mma16(o[2*dtp+1], al, vb1h);
            }
        }

        __syncthreads();
        if (j < 7) {
            if (j + 2 < 8) { load_kv(j & 1, j + 2); cp_commit(); cp_wait<1>(); }
            else           { cp_wait<0>(); }
            __syncthreads();
        }
    }

    const float i0 = 1.0f / l0, i1 = 1.0f / l1;
    #pragma unroll
    for (int dt = 0; dt < 8; dt++) {
        const int cg = dt * 8 + 2 * t;
        #pragma unroll
        for (int h2 = 0; h2 < 2; h2++) {
            const int rg = row0 + warp * 16 + q + h2 * 8;
            const float inv = h2 ? i1 : i0;
            float v0 = o[dt][h2 * 2 + 0] * inv;
            float v1 = o[dt][h2 * 2 + 1] * inv;
            bf16 h0, lo0, h1, lo1;
            spbf(v0, h0, lo0); spbf(v1, h1, lo1);
            const long off = obase + (long)rg * H + cg;
            *(__nv_bfloat162*)(Ch + off) = __halves2bfloat162(h0, h1);
            *(__nv_bfloat162*)(Cl + off) = __halves2bfloat162(lo0, lo1);
        }
    }
}

// ---------------------------------------------------------------------------
// Prep (single launch): split hs; transpose+split all weights (QKV packed);
// pack QKV bias. Dispatch by blockIdx.x range; uniform per block.
// ---------------------------------------------------------------------------
__device__ __forceinline__ void tr_tile(const float* in, bf16* oh, bf16* ol,
                                        int ldi, int ldo, int bx, int by,
                                        float (*tsm)[33])
{
    const int r0 = by * 32, c0 = bx * 32;
    const int tx = threadIdx.x & 31, ty = threadIdx.x >> 5;
    #pragma unroll
    for (int i = 0; i < 32; i += 8)
        tsm[ty + i][tx] = in[(long)(r0 + ty + i) * ldi + c0 + tx];
    __syncthreads();
    #pragma unroll
    for (int i = 0; i < 32; i += 8) {
        float v = tsm[tx][ty + i];
        bf16 hb, lb; spbf(v, hb, lb);
        long o = (long)(c0 + ty + i) * ldo + r0 + tx;
        oh[o] = hb; ol[o] = lb;
    }
}

__global__ void __launch_bounds__(256)
prep(const float* __restrict__ hs,
     const float* __restrict__ q_w, const float* __restrict__ k_w,
     const float* __restrict__ v_w, const float* __restrict__ ao_w,
     const float* __restrict__ ff1_w, const float* __restrict__ ff2_w,
     const float* __restrict__ q_b, const float* __restrict__ k_b,
     const float* __restrict__ v_b)
{
    __shared__ float tsm[32][33];
    const int b = blockIdx.x;
    if (b < 3072) {                           // split hs -> xh/xl
        const int i = b * 256 + threadIdx.x;
        float4 v = ((const float4*)hs)[i];
        bf16 h0, l0, h1, l1;
        spbf(v.x, h0, l0); spbf(v.y, h1, l1);
        *(__nv_bfloat162*)(g_xh + i * 4) = __halves2bfloat162(h0, h1);
        *(__nv_bfloat162*)(g_xl + i * 4) = __halves2bfloat162(l0, l1);
        spbf(v.z, h0, l0); spbf(v.w, h1, l1);
        *(__nv_bfloat162*)(g_xh + i * 4 + 2) = __halves2bfloat162(h0, h1);
        *(__nv_bfloat162*)(g_xl + i * 4 + 2) = __halves2bfloat162(l0, l1);
    } else if (b < 3648) {                    // q_w -> wqkv rows [0,768)
        int tt = b - 3072; tr_tile(q_w, g_wqkvh, g_wqkvl, H, H, tt % 24, tt / 24, tsm);
    } else if (b < 4224) {                    // k_w -> rows [768,1536)
        int tt = b - 3648; tr_tile(k_w, g_wqkvh + H*H, g_wqkvl + H*H, H, H, tt % 24, tt / 24, tsm);
    } else if (b < 4800) {                    // v_w -> rows [1536,2304)
        int tt = b - 4224; tr_tile(v_w, g_wqkvh + 2*H*H, g_wqkvl + 2*H*H, H, H, tt % 24, tt / 24, tsm);
    } else if (b < 5376) {                    // ao_w
        int tt = b - 4800; tr_tile(ao_w, g_wah, g_wal, H, H, tt % 24, tt / 24, tsm);
    } else if (b < 7680) {                    // ff1_w [768][3072] -> [3072][768]
        int tt = b - 5376; tr_tile(ff1_w, g_w1h, g_w1l, FFD, H, tt % 96, tt / 96, tsm);
    } else if (b < 9984) {                    // ff2_w [3072][768] -> [768][3072]
        int tt = b - 7680; tr_tile(ff2_w, g_w2h, g_w2l, H, FFD, tt % 24, tt / 24, tsm);
    } else {                                  // bias pack (9 blocks x 256 = 2304)
        const int i = (b - 9984) * 256 + threadIdx.x;
        float v = (i < H) ? q_b[i] : (i < 2*H) ? k_b[i - H] : v_b[i - 2*H];
        g_bqkv[i] = v;
    }
}

// ---------------------------------------------------------------------------
// LayerNorm row H=768; fp32 out + optional bf16 hi/lo out.
// ---------------------------------------------------------------------------
template<bool SPLIT>
__global__ void __launch_bounds__(256)
ln_rows(const float* __restrict__ in, const float* __restrict__ g,
        const float* __restrict__ b, float* __restrict__ out,
        bf16* __restrict__ oh, bf16* __restrict__ ol)
{
    const long off = (long)blockIdx.x * H;
    const float* p = in + off;
    const int tid = threadIdx.x;
    __shared__ float rs[256], rq[256];
    const float x0 = p[tid], x1 = p[tid + 256], x2 = p[tid + 512];
    rs[tid] = x0 + x1 + x2;
    rq[tid] = x0 * x0 + x1 * x1 + x2 * x2;
    __syncthreads();
    #pragma unroll
    for (int o = 128; o > 0; o >>= 1) {
        if (tid < o) { rs[tid] += rs[tid + o]; rq[tid] += rq[tid + o]; }
        __syncthreads();
    }
    const float mean = rs[0] * (1.0f / H);
    const float var  = rq[0] * (1.0f / H) - mean * mean;
    const float inv  = rsqrtf(var + 1e-5f);
    #pragma unroll
    for (int i = 0; i < 3; i++) {
        const int c = tid + i * 256;
        const float xv = (i == 0 ? x0 : (i == 1 ? x1 : x2));
        const float o = (xv - mean) * inv * g[c] + b[c];
        out[off + c] = o;
        if (SPLIT) {
            bf16 hb, lb; spbf(o, hb, lb);
            oh[off + c] = hb; ol[off + c] = lb;
        }
    }
}

// ---------------------------------------------------------------------------
extern "C" void kernel_launch(void* const* d_in, const int* in_sizes, int n_in,
                              void* d_out, int out_size)
{
    const float* hs    = (const float*)d_in[0];
    const float* mask  = (const float*)d_in[1];
    const float* q_w   = (const float*)d_in[2];
    const float* q_b   = (const float*)d_in[3];
    const float* k_w   = (const float*)d_in[4];
    const float* k_b   = (const float*)d_in[5];
    const float* v_w   = (const float*)d_in[6];
    const float* v_b   = (const float*)d_in[7];
    const float* ao_w  = (const float*)d_in[8];
    const float* ao_b  = (const float*)d_in[9];
    const float* ln1_g = (const float*)d_in[10];
    const float* ln1_b = (const float*)d_in[11];
    const float* ff1_w = (const float*)d_in[12];
    const float* ff1_b = (const float*)d_in[13];
    const float* ff2_w = (const float*)d_in[14];
    const float* ff2_b = (const float*)d_in[15];
    const float* ln2_g = (const float*)d_in[16];
    const float* ln2_b = (const float*)d_in[17];
    float* out = (float*)d_out;

    float *x, *t, *at, *bqkv;
    bf16 *xh,*xl,*qkvh,*qkvl,*ch,*cl,*ah,*al,*fh,*fl;
    bf16 *wqkvh,*wqkvl,*wah,*wal,*w1h,*w1l,*w2h,*w2l;
    cudaGetSymbolAddress((void**)&x, g_x);
    cudaGetSymbolAddress((void**)&t, g_t);      cudaGetSymbolAddress((void**)&at, g_at);
    cudaGetSymbolAddress((void**)&bqkv, g_bqkv);
    cudaGetSymbolAddress((void**)&xh, g_xh);    cudaGetSymbolAddress((void**)&xl, g_xl);
    cudaGetSymbolAddress((void**)&qkvh, g_qkvh);cudaGetSymbolAddress((void**)&qkvl, g_qkvl);
    cudaGetSymbolAddress((void**)&ch, g_ch);    cudaGetSymbolAddress((void**)&cl, g_cl);
    cudaGetSymbolAddress((void**)&ah, g_ah);    cudaGetSymbolAddress((void**)&al, g_al);
    cudaGetSymbolAddress((void**)&fh, g_fh);    cudaGetSymbolAddress((void**)&fl, g_fl);
    cudaGetSymbolAddress((void**)&wqkvh, g_wqkvh);
    cudaGetSymbolAddress((void**)&wqkvl, g_wqkvl);
    cudaGetSymbolAddress((void**)&wah, g_wah);  cudaGetSymbolAddress((void**)&wal, g_wal);
    cudaGetSymbolAddress((void**)&w1h, g_w1h);  cudaGetSymbolAddress((void**)&w1l, g_w1l);
    cudaGetSymbolAddress((void**)&w2h, g_w2h);  cudaGetSymbolAddress((void**)&w2l, g_w2l);

    const int SMB = 73728;    // 3 stages x 24576
    cudaFuncSetAttribute(gemm_bf<EPI_BIAS,   OUT_SPLIT>, cudaFuncAttributeMaxDynamicSharedMemorySize, SMB);
    cudaFuncSetAttribute(gemm_bf<EPI_BIASRES,OUT_F32>,   cudaFuncAttributeMaxDynamicSharedMemorySize, SMB);
    cudaFuncSetAttribute(gemm_bf<EPI_GELU,   OUT_SPLIT>, cudaFuncAttributeMaxDynamicSharedMemorySize, SMB);
    const int SMF = 167936;   // 164 KB
    cudaFuncSetAttribute(fattn, cudaFuncAttributeMaxDynamicSharedMemorySize, SMF);

    cudaMemcpyAsync(x, hs, (size_t)NTOK * H * sizeof(float), cudaMemcpyDeviceToDevice);
    prep<<<9993, 256>>>(hs, q_w, k_w, v_w, ao_w, ff1_w, ff2_w, q_b, k_b, v_b);

    const dim3 gQKV(36, 32), gProj(12, 32), gFF1(48, 32), gAtt(8, 48);

    for (int layer = 0; layer < NLAYER; layer++) {
        // fused QKV projection -> packed [tok][2304] hi/lo
        gemm_bf<EPI_BIAS, OUT_SPLIT><<<gQKV, 256, SMB>>>(
            xh, xl, wqkvh, wqkvl, bqkv, nullptr, nullptr, qkvh, qkvl,
            H, H, H, H3);

        fattn<<<gAtt, 256, SMF>>>(qkvh, qkvl, mask, ch, cl);

        gemm_bf<EPI_BIASRES, OUT_F32><<<gProj, 256, SMB>>>(
            ch, cl, wah, wal, ao_b, x, t, nullptr, nullptr, H, H, H, H);
        ln_rows<true><<<NTOK, 256>>>(t, ln1_g, ln1_b, at, ah, al);

        gemm_bf<EPI_GELU, OUT_SPLIT><<<gFF1, 256, SMB>>>(
            ah, al, w1h, w1l, ff1_b, nullptr, nullptr, fh, fl, H, H, H, FFD);
        gemm_bf<EPI_BIASRES, OUT_F32><<<gProj, 256, SMB>>>(
            fh, fl, w2h, w2l, ff2_b, at, t, nullptr, nullptr, FFD, FFD, FFD, H);

        if (layer == NLAYER - 1) {
            ln_rows<false><<<NTOK, 256>>>(t, ln2_g, ln2_b, out, nullptr, nullptr);
        } else {
            ln_rows<true><<<NTOK, 256>>>(t, ln2_g, ln2_b, x, xh, xl);
        }
    }
}

// round 11
// speedup vs baseline: 3.6565x; 1.1272x over previous
#include <cuda_runtime.h>
#include <cuda_bf16.h>
#include <math.h>
#include <stdint.h>

#define H    768
#define FFD  3072
#define BB   4
#define SS   1024
#define NHH  12
#define HDD  64
#define NTOK 4096
#define NLAYER 6
#define H3   2304   // 3*H packed QKV

typedef __nv_bfloat16 bf16;

// ---------------- device scratch ----------------
__device__ float g_t [NTOK*H];
__device__ float g_at[NTOK*H];
__device__ float g_x [NTOK*H];
__device__ float g_bqkv[H3];
__device__ bf16 g_xh[NTOK*H],   g_xl[NTOK*H];
__device__ bf16 g_qkvh[NTOK*H3], g_qkvl[NTOK*H3];
__device__ bf16 g_ch[NTOK*H],   g_cl[NTOK*H];
__device__ bf16 g_ah[NTOK*H],   g_al[NTOK*H];
__device__ bf16 g_fh[NTOK*FFD], g_fl[NTOK*FFD];
__device__ bf16 g_wqkvh[H3*H],  g_wqkvl[H3*H];
__device__ bf16 g_wah[H*H],     g_wal[H*H];
__device__ bf16 g_w1h[H*FFD],   g_w1l[H*FFD];
__device__ bf16 g_w2h[H*FFD],   g_w2l[H*FFD];

#define EPI_NONE      0
#define EPI_BIAS      1
#define EPI_GELU      2
#define EPI_BIASRES   3
#define OUT_F32   0
#define OUT_SPLIT 1

__device__ __forceinline__ uint32_t su32(const void* p) {
    return (uint32_t)__cvta_generic_to_shared(p);
}
__device__ __forceinline__ void cpa16(void* s, const void* g) {
    asm volatile("cp.async.cg.shared.global [%0], [%1], 16;" :: "r"(su32(s)), "l"(g));
}
__device__ __forceinline__ void cp_commit() { asm volatile("cp.async.commit_group;"); }
template<int N> __device__ __forceinline__ void cp_wait() {
    asm volatile("cp.async.wait_group %0;" :: "n"(N));
}
__device__ __forceinline__ void mma16(float c[4], const uint32_t a[4], const uint32_t b[2]) {
    asm volatile(
        "mma.sync.aligned.m16n8k16.row.col.f32.bf16.bf16.f32 "
        "{%0,%1,%2,%3}, {%4,%5,%6,%7}, {%8,%9}, {%0,%1,%2,%3};\n"
        : "+f"(c[0]), "+f"(c[1]), "+f"(c[2]), "+f"(c[3])
        : "r"(a[0]), "r"(a[1]), "r"(a[2]), "r"(a[3]), "r"(b[0]), "r"(b[1]));
}
__device__ __forceinline__ void ldsm4(uint32_t r[4], uint32_t addr) {
    asm volatile("ldmatrix.sync.aligned.m8n8.x4.shared.b16 {%0,%1,%2,%3}, [%4];"
                 : "=r"(r[0]), "=r"(r[1]), "=r"(r[2]), "=r"(r[3]) : "r"(addr));
}
__device__ __forceinline__ void ldsm4t(uint32_t r[4], uint32_t addr) {
    asm volatile("ldmatrix.sync.aligned.m8n8.x4.trans.shared.b16 {%0,%1,%2,%3}, [%4];"
                 : "=r"(r[0]), "=r"(r[1]), "=r"(r[2]), "=r"(r[3]) : "r"(addr));
}
__device__ __forceinline__ void spbf(float x, bf16& hi, bf16& lo) {
    hi = __float2bfloat16(x);
    lo = __float2bfloat16(x - __bfloat162float(hi));
}
__device__ __forceinline__ void pack2(float x, float y, uint32_t& hi, uint32_t& lo) {
    bf16 hx = __float2bfloat16(x), hy = __float2bfloat16(y);
    bf16 lx = __float2bfloat16(x - __bfloat162float(hx));
    bf16 ly = __float2bfloat16(y - __bfloat162float(hy));
    hi = ((uint32_t)__bfloat16_as_ushort(hy) << 16) | __bfloat16_as_ushort(hx);
    lo = ((uint32_t)__bfloat16_as_ushort(ly) << 16) | __bfloat16_as_ushort(lx);
}

// ---------------------------------------------------------------------------
// bf16 split GEMM: C = (Ah+Al)(Bh+Bl)^T, 3 terms, fp32 accum.
// CTA tile 128x64, BK=32, 8 warps, ldmatrix fragments.
// 4-stage cp.async ring -> ONE __syncthreads per k-iteration.
// ---------------------------------------------------------------------------
template<int EPI, int OUTM>
__global__ void __launch_bounds__(256, 2)
gemm_bf(const bf16* __restrict__ Ah, const bf16* __restrict__ Al,
        const bf16* __restrict__ Bh, const bf16* __restrict__ Bl,
        const float* __restrict__ bias, const float* __restrict__ res,
        float* __restrict__ Cf, bf16* __restrict__ Ch, bf16* __restrict__ Cl,
        int K, int lda, int ldb, int ldc)
{
    extern __shared__ __align__(16) char smem[];   // 4 stages x 24576 B
    const int tid = threadIdx.x, lane = tid & 31, warp = tid >> 5;
    const int row0 = blockIdx.y * 128, col0 = blockIdx.x * 64;
    const int wm = warp & 3, wn = warp >> 2;
    const int q = lane >> 2, t = lane & 3;
    const int la = lane & 15, ca = lane >> 4;
    const int mb = lane >> 3;
    const int rb = ((mb >> 1) << 3) + (lane & 7), cb = mb & 1;
    const uint32_t sbase = su32(smem);

    auto load_stage = [&](int s, int k0) {
        char* base = smem + s * 24576;
        #pragma unroll
        for (int i = 0; i < 4; i++) {
            int c = tid + i * 256, tile = c >> 9, rem = c & 511;
            int r = rem >> 2, cj = rem & 3;
            const bf16* src = (tile ? Al : Ah) + (long)(row0 + r) * lda + k0 + cj * 8;
            cpa16(base + tile * 8192 + r * 64 + ((cj ^ ((r >> 1) & 3)) * 16), src);
        }
        #pragma unroll
        for (int i = 0; i < 2; i++) {
            int c = tid + i * 256, tile = c >> 8, rem = c & 255;
            int r = rem >> 2, cj = rem & 3;
            const bf16* src = (tile ? Bl : Bh) + (long)(col0 + r) * ldb + k0 + cj * 8;
            cpa16(base + 16384 + tile * 4096 + r * 64 + ((cj ^ ((r >> 1) & 3)) * 16), src);
        }
        cp_commit();
    };

    float acc[2][4][4] = {};

    auto compute = [&](int s) {
        const uint32_t ab = sbase + s * 24576;
        #pragma unroll
        for (int ks = 0; ks < 2; ks++) {
            uint32_t ahi[2][4], alo[2][4], bhi[4][2], blo[4][2];
            #pragma unroll
            for (int mt = 0; mt < 2; mt++) {
                const int r = wm * 32 + mt * 16 + la;
                const int c = 2 * ks + ca;
                const uint32_t ad = ab + r * 64 + ((c ^ ((r >> 1) & 3)) * 16);
                ldsm4(ahi[mt], ad);
                ldsm4(alo[mt], ad + 8192);
            }
            #pragma unroll
            for (int p = 0; p < 2; p++) {
                const int r = wn * 32 + p * 16 + rb;
                const int c = 2 * ks + cb;
                const uint32_t bd = ab + 16384 + r * 64 + ((c ^ ((r >> 1) & 3)) * 16);
                uint32_t th[4], tl[4];
                ldsm4(th, bd);
                ldsm4(tl, bd + 4096);
                bhi[2*p][0] = th[0]; bhi[2*p][1] = th[1];
                bhi[2*p+1][0] = th[2]; bhi[2*p+1][1] = th[3];
                blo[2*p][0] = tl[0]; blo[2*p][1] = tl[1];
                blo[2*p+1][0] = tl[2]; blo[2*p+1][1] = tl[3];
            }
            #pragma unroll
            for (int mt = 0; mt < 2; mt++)
                #pragma unroll
                for (int nt = 0; nt < 4; nt++) {
                    mma16(acc[mt][nt], ahi[mt], bhi[nt]);
                    mma16(acc[mt][nt], ahi[mt], blo[nt]);
                    mma16(acc[mt][nt], alo[mt], bhi[nt]);
                }
        }
    };

    const int nIt = K >> 5;        // >= 24 for all shapes here
    load_stage(0, 0);
    load_stage(1, 32);
    load_stage(2, 64);
    for (int it = 0; it < nIt; it++) {
        // ensure the group for stage it%4 has landed
        if (it <= nIt - 3)      cp_wait<2>();
        else if (it == nIt - 2) cp_wait<1>();
        else                    cp_wait<0>();
        __syncthreads();   // also orders previous compute vs. the load below
        if (it < nIt - 3) load_stage((it + 3) & 3, (it + 3) << 5);
        compute(it & 3);
    }

    #pragma unroll
    for (int mt = 0; mt < 2; mt++)
        #pragma unroll
        for (int nt = 0; nt < 4; nt++) {
            const int cg = col0 + wn * 32 + nt * 8 + 2 * t;
            #pragma unroll
            for (int h2 = 0; h2 < 2; h2++) {
                const int rg = row0 + wm * 32 + mt * 16 + q + h2 * 8;
                float v0 = acc[mt][nt][h2 * 2 + 0];
                float v1 = acc[mt][nt][h2 * 2 + 1];
                if (EPI != EPI_NONE) {
                    v0 += bias[cg];
                    v1 += bias[cg + 1];
                    if (EPI == EPI_GELU) {
                        v0 = 0.5f * v0 * (1.0f + erff(v0 * 0.70710678118654752440f));
                        v1 = 0.5f * v1 * (1.0f + erff(v1 * 0.70710678118654752440f));
                    } else if (EPI == EPI_BIASRES) {
                        v0 += res[(long)rg * ldc + cg];
                        v1 += res[(long)rg * ldc + cg + 1];
                    }
                }
                const long o = (long)rg * ldc + cg;
                if (OUTM == OUT_F32) {
                    *(float2*)(Cf + o) = make_float2(v0, v1);
                } else {
                    bf16 h0, l0, h1, l1;
                    spbf(v0, h0, l0); spbf(v1, h1, l1);
                    *(__nv_bfloat162*)(Ch + o) = __halves2bfloat162(h0, h1);
                    *(__nv_bfloat162*)(Cl + o) = __halves2bfloat162(l0, l1);
                }
            }
        }
}

// ---------------------------------------------------------------------------
// Fused flash attention: Q/K/V read from packed [tok][2304] hi/lo buffers.
// smem: Qh 16K | Ql 16K | 2 stages x (Kh|Kl|Vh|Vl each 16K) | mask 4K = 164K
// ---------------------------------------------------------------------------
__global__ void __launch_bounds__(256, 1)
fattn(const bf16* __restrict__ QKVh, const bf16* __restrict__ QKVl,
      const float* __restrict__ mask,
      bf16* __restrict__ Ch, bf16* __restrict__ Cl)
{
    extern __shared__ __align__(16) char smem[];
    const int tid = threadIdx.x, lane = tid & 31, warp = tid >> 5;
    const int bh = blockIdx.y, bb = bh / NHH, hh = bh % NHH;
    const int row0 = blockIdx.x * 128;
    const long ibase = (long)bb * SS * H3 + hh * HDD;
    const long obase = (long)bb * SS * H  + hh * HDD;
    const int q = lane >> 2, t = lane & 3;
    const int la = lane & 15, ca = lane >> 4;
    const int mb = lane >> 3;
    const int rb = ((mb >> 1) << 3) + (lane & 7), cb = mb & 1;
    const uint32_t sbase = su32(smem);
    float* mask_s = (float*)(smem + 163840);

    for (int i = tid; i < SS; i += 256) mask_s[i] = mask[(long)bb * SS + i];

    auto load_q = [&]() {
        #pragma unroll
        for (int i = 0; i < 8; i++) {
            int c = tid + i * 256, buf = c >> 10, rem = c & 1023;
            int r = rem >> 3, cj = rem & 7;
            const bf16* src = (buf ? QKVl : QKVh) + ibase + (long)(row0 + r) * H3 + cj * 8;
            cpa16(smem + buf * 16384 + r * 128 + ((cj ^ (r & 7)) * 16), src);
        }
    };
    auto load_kv = [&](int s, int blk) {
        char* sb = smem + 32768 + s * 65536;
        #pragma unroll
        for (int i = 0; i < 16; i++) {
            int c = tid + i * 256, buf = c >> 10, rem = c & 1023;
            int r = rem >> 3, cj = rem & 7;
            const bf16* arr = (buf & 1) ? QKVl : QKVh;
            const int coff = (buf >> 1) ? 2 * H : H;
            const bf16* src = arr + ibase + coff + (long)(blk * 128 + r) * H3 + cj * 8;
            cpa16(sb + buf * 16384 + r * 128 + ((cj ^ (r & 7)) * 16), src);
        }
    };

    load_q();
    load_kv(0, 0);
    cp_commit();
    load_kv(1, 1);
    cp_commit();
    cp_wait<1>();
    __syncthreads();

    uint32_t qfh[4][4], qfl[4][4];
    #pragma unroll
    for (int kk = 0; kk < 4; kk++) {
        const int r = warp * 16 + la;
        const int c = 2 * kk + ca;
        const uint32_t ad = sbase + r * 128 + ((c ^ (r & 7)) * 16);
        ldsm4(qfh[kk], ad);
        ldsm4(qfl[kk], ad + 16384);
    }

    float m0 = -INFINITY, m1 = -INFINITY, l0 = 0.f, l1 = 0.f;
    float o[8][4] = {};

    for (int j = 0; j < 8; j++) {
        const uint32_t stb = sbase + 32768 + (j & 1) * 65536;

        float s[16][4];
        #pragma unroll
        for (int i = 0; i < 16; i++)
            #pragma unroll
            for (int c = 0; c < 4; c++) s[i][c] = 0.f;
        #pragma unroll
        for (int p = 0; p < 8; p++) {
            #pragma unroll
            for (int kk = 0; kk < 4; kk++) {
                const int r = p * 16 + rb;
                const int c = 2 * kk + cb;
                const uint32_t bd = stb + r * 128 + ((c ^ (r & 7)) * 16);
                uint32_t th[4], tl[4];
                ldsm4(th, bd);
                ldsm4(tl, bd + 16384);
                uint32_t b0h[2] = {th[0], th[1]}, b1h[2] = {th[2], th[3]};
                uint32_t b0l[2] = {tl[0], tl[1]}, b1l[2] = {tl[2], tl[3]};
                mma16(s[2*p],   qfh[kk], b0h);
                mma16(s[2*p],   qfh[kk], b0l);
                mma16(s[2*p],   qfl[kk], b0h);
                mma16(s[2*p+1], qfh[kk], b1h);
                mma16(s[2*p+1], qfh[kk], b1l);
                mma16(s[2*p+1], qfl[kk], b1h);
            }
        }

        #pragma unroll
        for (int nt = 0; nt < 16; nt++) {
            const int cc = j * 128 + nt * 8 + 2 * t;
            const float mk0 = mask_s[cc], mk1 = mask_s[cc + 1];
            s[nt][0] = s[nt][0] * 0.125f + mk0;
            s[nt][1] = s[nt][1] * 0.125f + mk1;
            s[nt][2] = s[nt][2] * 0.125f + mk0;
            s[nt][3] = s[nt][3] * 0.125f + mk1;
        }

        float p0 = -INFINITY, p1 = -INFINITY;
        #pragma unroll
        for (int nt = 0; nt < 16; nt++) {
            p0 = fmaxf(p0, fmaxf(s[nt][0], s[nt][1]));
            p1 = fmaxf(p1, fmaxf(s[nt][2], s[nt][3]));
        }
        p0 = fmaxf(p0, __shfl_xor_sync(~0u, p0, 1));
        p0 = fmaxf(p0, __shfl_xor_sync(~0u, p0, 2));
        p1 = fmaxf(p1, __shfl_xor_sync(~0u, p1, 1));
        p1 = fmaxf(p1, __shfl_xor_sync(~0u, p1, 2));
        const float mn0 = fmaxf(m0, p0), mn1 = fmaxf(m1, p1);
        const float a0 = __expf(m0 - mn0), a1 = __expf(m1 - mn1);
        m0 = mn0; m1 = mn1;

        float sum0 = 0.f, sum1 = 0.f;
        #pragma unroll
        for (int nt = 0; nt < 16; nt++) {
            s[nt][0] = __expf(s[nt][0] - m0); sum0 += s[nt][0];
            s[nt][1] = __expf(s[nt][1] - m0); sum0 += s[nt][1];
            s[nt][2] = __expf(s[nt][2] - m1); sum1 += s[nt][2];
            s[nt][3] = __expf(s[nt][3] - m1); sum1 += s[nt][3];
        }
        sum0 += __shfl_xor_sync(~0u, sum0, 1);
        sum0 += __shfl_xor_sync(~0u, sum0, 2);
        sum1 += __shfl_xor_sync(~0u, sum1, 1);
        sum1 += __shfl_xor_sync(~0u, sum1, 2);
        l0 = l0 * a0 + sum0;
        l1 = l1 * a1 + sum1;
        #pragma unroll
        for (int dt = 0; dt < 8; dt++) {
            o[dt][0] *= a0; o[dt][1] *= a0;
            o[dt][2] *= a1; o[dt][3] *= a1;
        }

        #pragma unroll
        for (int jk = 0; jk < 8; jk++) {
            uint32_t ah[4], al[4];
            pack2(s[2*jk][0],   s[2*jk][1],   ah[0], al[0]);
            pack2(s[2*jk][2],   s[2*jk][3],   ah[1], al[1]);
            pack2(s[2*jk+1][0], s[2*jk+1][1], ah[2], al[2]);
            pack2(s[2*jk+1][2], s[2*jk+1][3], ah[3], al[3]);
            #pragma unroll
            for (int dtp = 0; dtp < 4; dtp++) {
                const int r = jk * 16 + la;
                const int c = 2 * dtp + ca;
                const uint32_t vd = stb + 32768 + r * 128 + ((c ^ (r & 7)) * 16);
                uint32_t vh4[4], vl4[4];
                ldsm4t(vh4, vd);
                ldsm4t(vl4, vd + 16384);
                uint32_t vb0h[2] = {vh4[0], vh4[1]}, vb1h[2] = {vh4[2], vh4[3]};
                uint32_t vb0l[2] = {vl4[0], vl4[1]}, vb1l[2] = {vl4[2], vl4[3]};
                mma16(o[2*dtp],   ah, vb0h);
                mma16(o[2*dtp],   ah, vb0l);
                mma16(o[2*dtp],   al, vb0h);
                mma16(o[2*dtp+1], ah, vb1h);
                mma16(o[2*dtp+1], ah, vb1l);
                mma16(o[2*dtp+1], al, vb1h);
            }
        }

        __syncthreads();
        if (j < 7) {
            if (j + 2 < 8) { load_kv(j & 1, j + 2); cp_commit(); cp_wait<1>(); }
            else           { cp_wait<0>(); }
            __syncthreads();
        }
    }

    const float i0 = 1.0f / l0, i1 = 1.0f / l1;
    #pragma unroll
    for (int dt = 0; dt < 8; dt++) {
        const int cg = dt * 8 + 2 * t;
        #pragma unroll
        for (int h2 = 0; h2 < 2; h2++) {
            const int rg = row0 + warp * 16 + q + h2 * 8;
            const float inv = h2 ? i1 : i0;
            float v0 = o[dt][h2 * 2 + 0] * inv;
            float v1 = o[dt][h2 * 2 + 1] * inv;
            bf16 h0, lo0, h1, lo1;
            spbf(v0, h0, lo0); spbf(v1, h1, lo1);
            const long off = obase + (long)rg * H + cg;
            *(__nv_bfloat162*)(Ch + off) = __halves2bfloat162(h0, h1);
            *(__nv_bfloat162*)(Cl + off) = __halves2bfloat162(lo0, lo1);
        }
    }
}

// ---------------------------------------------------------------------------
// Prep (single launch): split hs; transpose+split all weights (QKV packed);
// pack QKV bias.
// ---------------------------------------------------------------------------
__device__ __forceinline__ void tr_tile(const float* in, bf16* oh, bf16* ol,
                                        int ldi, int ldo, int bx, int by,
                                        float (*tsm)[33])
{
    const int r0 = by * 32, c0 = bx * 32;
    const int tx = threadIdx.x & 31, ty = threadIdx.x >> 5;
    #pragma unroll
    for (int i = 0; i < 32; i += 8)
        tsm[ty + i][tx] = in[(long)(r0 + ty + i) * ldi + c0 + tx];
    __syncthreads();
    #pragma unroll
    for (int i = 0; i < 32; i += 8) {
        float v = tsm[tx][ty + i];
        bf16 hb, lb; spbf(v, hb, lb);
        long o = (long)(c0 + ty + i) * ldo + r0 + tx;
        oh[o] = hb; ol[o] = lb;
    }
}

__global__ void __launch_bounds__(256)
prep(const float* __restrict__ hs,
     const float* __restrict__ q_w, const float* __restrict__ k_w,
     const float* __restrict__ v_w, const float* __restrict__ ao_w,
     const float* __restrict__ ff1_w, const float* __restrict__ ff2_w,
     const float* __restrict__ q_b, const float* __restrict__ k_b,
     const float* __restrict__ v_b)
{
    __shared__ float tsm[32][33];
    const int b = blockIdx.x;
    if (b < 3072) {
        const int i = b * 256 + threadIdx.x;
        float4 v = ((const float4*)hs)[i];
        bf16 h0, l0, h1, l1;
        spbf(v.x, h0, l0); spbf(v.y, h1, l1);
        *(__nv_bfloat162*)(g_xh + i * 4) = __halves2bfloat162(h0, h1);
        *(__nv_bfloat162*)(g_xl + i * 4) = __halves2bfloat162(l0, l1);
        spbf(v.z, h0, l0); spbf(v.w, h1, l1);
        *(__nv_bfloat162*)(g_xh + i * 4 + 2) = __halves2bfloat162(h0, h1);
        *(__nv_bfloat162*)(g_xl + i * 4 + 2) = __halves2bfloat162(l0, l1);
    } else if (b < 3648) {
        int tt = b - 3072; tr_tile(q_w, g_wqkvh, g_wqkvl, H, H, tt % 24, tt / 24, tsm);
    } else if (b < 4224) {
        int tt = b - 3648; tr_tile(k_w, g_wqkvh + H*H, g_wqkvl + H*H, H, H, tt % 24, tt / 24, tsm);
    } else if (b < 4800) {
        int tt = b - 4224; tr_tile(v_w, g_wqkvh + 2*H*H, g_wqkvl + 2*H*H, H, H, tt % 24, tt / 24, tsm);
    } else if (b < 5376) {
        int tt = b - 4800; tr_tile(ao_w, g_wah, g_wal, H, H, tt % 24, tt / 24, tsm);
    } else if (b < 7680) {
        int tt = b - 5376; tr_tile(ff1_w, g_w1h, g_w1l, FFD, H, tt % 96, tt / 96, tsm);
    } else if (b < 9984) {
        int tt = b - 7680; tr_tile(ff2_w, g_w2h, g_w2l, H, FFD, tt % 24, tt / 24, tsm);
    } else {
        const int i = (b - 9984) * 256 + threadIdx.x;
        float v = (i < H) ? q_b[i] : (i < 2*H) ? k_b[i - H] : v_b[i - 2*H];
        g_bqkv[i] = v;
    }
}

// ---------------------------------------------------------------------------
// LayerNorm row H=768; fp32 out + optional bf16 hi/lo out.
// ---------------------------------------------------------------------------
template<bool SPLIT>
__global__ void __launch_bounds__(256)
ln_rows(const float* __restrict__ in, const float* __restrict__ g,
        const float* __restrict__ b, float* __restrict__ out,
        bf16* __restrict__ oh, bf16* __restrict__ ol)
{
    const long off = (long)blockIdx.x * H;
    const float* p = in + off;
    const int tid = threadIdx.x;
    __shared__ float rs[256], rq[256];
    const float x0 = p[tid], x1 = p[tid + 256], x2 = p[tid + 512];
    rs[tid] = x0 + x1 + x2;
    rq[tid] = x0 * x0 + x1 * x1 + x2 * x2;
    __syncthreads();
    #pragma unroll
    for (int o = 128; o > 0; o >>= 1) {
        if (tid < o) { rs[tid] += rs[tid + o]; rq[tid] += rq[tid + o]; }
        __syncthreads();
    }
    const float mean = rs[0] * (1.0f / H);
    const float var  = rq[0] * (1.0f / H) - mean * mean;
    const float inv  = rsqrtf(var + 1e-5f);
    #pragma unroll
    for (int i = 0; i < 3; i++) {
        const int c = tid + i * 256;
        const float xv = (i == 0 ? x0 : (i == 1 ? x1 : x2));
        const float o = (xv - mean) * inv * g[c] + b[c];
        out[off + c] = o;
        if (SPLIT) {
            bf16 hb, lb; spbf(o, hb, lb);
            oh[off + c] = hb; ol[off + c] = lb;
        }
    }
}

// ---------------------------------------------------------------------------
extern "C" void kernel_launch(void* const* d_in, const int* in_sizes, int n_in,
                              void* d_out, int out_size)
{
    const float* hs    = (const float*)d_in[0];
    const float* mask  = (const float*)d_in[1];
    const float* q_w   = (const float*)d_in[2];
    const float* q_b   = (const float*)d_in[3];
    const float* k_w   = (const float*)d_in[4];
    const float* k_b   = (const float*)d_in[5];
    const float* v_w   = (const float*)d_in[6];
    const float* v_b   = (const float*)d_in[7];
    const float* ao_w  = (const float*)d_in[8];
    const float* ao_b  = (const float*)d_in[9];
    const float* ln1_g = (const float*)d_in[10];
    const float* ln1_b = (const float*)d_in[11];
    const float* ff1_w = (const float*)d_in[12];
    const float* ff1_b = (const float*)d_in[13];
    const float* ff2_w = (const float*)d_in[14];
    const float* ff2_b = (const float*)d_in[15];
    const float* ln2_g = (const float*)d_in[16];
    const float* ln2_b = (const float*)d_in[17];
    float* out = (float*)d_out;

    float *x, *t, *at, *bqkv;
    bf16 *xh,*xl,*qkvh,*qkvl,*ch,*cl,*ah,*al,*fh,*fl;
    bf16 *wqkvh,*wqkvl,*wah,*wal,*w1h,*w1l,*w2h,*w2l;
    cudaGetSymbolAddress((void**)&x, g_x);
    cudaGetSymbolAddress((void**)&t, g_t);      cudaGetSymbolAddress((void**)&at, g_at);
    cudaGetSymbolAddress((void**)&bqkv, g_bqkv);
    cudaGetSymbolAddress((void**)&xh, g_xh);    cudaGetSymbolAddress((void**)&xl, g_xl);
    cudaGetSymbolAddress((void**)&qkvh, g_qkvh);cudaGetSymbolAddress((void**)&qkvl, g_qkvl);
    cudaGetSymbolAddress((void**)&ch, g_ch);    cudaGetSymbolAddress((void**)&cl, g_cl);
    cudaGetSymbolAddress((void**)&ah, g_ah);    cudaGetSymbolAddress((void**)&al, g_al);
    cudaGetSymbolAddress((void**)&fh, g_fh);    cudaGetSymbolAddress((void**)&fl, g_fl);
    cudaGetSymbolAddress((void**)&wqkvh, g_wqkvh);
    cudaGetSymbolAddress((void**)&wqkvl, g_wqkvl);
    cudaGetSymbolAddress((void**)&wah, g_wah);  cudaGetSymbolAddress((void**)&wal, g_wal);
    cudaGetSymbolAddress((void**)&w1h, g_w1h);  cudaGetSymbolAddress((void**)&w1l, g_w1l);
    cudaGetSymbolAddress((void**)&w2h, g_w2h);  cudaGetSymbolAddress((void**)&w2l, g_w2l);

    const int SMB = 98304;    // 4 stages x 24576
    cudaFuncSetAttribute(gemm_bf<EPI_BIAS,   OUT_SPLIT>, cudaFuncAttributeMaxDynamicSharedMemorySize, SMB);
    cudaFuncSetAttribute(gemm_bf<EPI_BIASRES,OUT_F32>,   cudaFuncAttributeMaxDynamicSharedMemorySize, SMB);
    cudaFuncSetAttribute(gemm_bf<EPI_GELU,   OUT_SPLIT>, cudaFuncAttributeMaxDynamicSharedMemorySize, SMB);
    const int SMF = 167936;   // 164 KB
    cudaFuncSetAttribute(fattn, cudaFuncAttributeMaxDynamicSharedMemorySize, SMF);

    cudaMemcpyAsync(x, hs, (size_t)NTOK * H * sizeof(float), cudaMemcpyDeviceToDevice);
    prep<<<9993, 256>>>(hs, q_w, k_w, v_w, ao_w, ff1_w, ff2_w, q_b, k_b, v_b);

    const dim3 gQKV(36, 32), gProj(12, 32), gFF1(48, 32), gAtt(8, 48);

    for (int layer = 0; layer < NLAYER; layer++) {
        gemm_bf<EPI_BIAS, OUT_SPLIT><<<gQKV, 256, SMB>>>(
            xh, xl, wqkvh, wqkvl, bqkv, nullptr, nullptr, qkvh, qkvl,
            H, H, H, H3);

        fattn<<<gAtt, 256, SMF>>>(qkvh, qkvl, mask, ch, cl);

        gemm_bf<EPI_BIASRES, OUT_F32><<<gProj, 256, SMB>>>(
            ch, cl, wah, wal, ao_b, x, t, nullptr, nullptr, H, H, H, H);
        ln_rows<true><<<NTOK, 256>>>(t, ln1_g, ln1_b, at, ah, al);

        gemm_bf<EPI_GELU, OUT_SPLIT><<<gFF1, 256, SMB>>>(
            ah, al, w1h, w1l, ff1_b, nullptr, nullptr, fh, fl, H, H, H, FFD);
        gemm_bf<EPI_BIASRES, OUT_F32><<<gProj, 256, SMB>>>(
            fh, fl, w2h, w2l, ff2_b, at, t, nullptr, nullptr, FFD, FFD, FFD, H);

        if (layer == NLAYER - 1) {
            ln_rows<false><<<NTOK, 256>>>(t, ln2_g, ln2_b, out, nullptr, nullptr);
        } else {
            ln_rows<true><<<NTOK, 256>>>(t, ln2_g, ln2_b, x, xh, xl);
        }
    }
}

// round 12
// speedup vs baseline: 3.6739x; 1.0048x over previous
#include <cuda_runtime.h>
#include <cuda_bf16.h>
#include <math.h>
#include <stdint.h>

#define H    768
#define FFD  3072
#define BB   4
#define SS   1024
#define NHH  12
#define HDD  64
#define NTOK 4096
#define NLAYER 6
#define H3   2304   // 3*H packed QKV

typedef __nv_bfloat16 bf16;

// ---------------- device scratch ----------------
__device__ float g_t [NTOK*H];
__device__ float g_at[NTOK*H];
__device__ float g_x [NTOK*H];
__device__ float g_bqkv[H3];
__device__ bf16 g_xh[NTOK*H],   g_xl[NTOK*H];
__device__ bf16 g_qkvh[NTOK*H3], g_qkvl[NTOK*H3];
__device__ bf16 g_ch[NTOK*H],   g_cl[NTOK*H];
__device__ bf16 g_ah[NTOK*H],   g_al[NTOK*H];
__device__ bf16 g_fh[NTOK*FFD], g_fl[NTOK*FFD];
__device__ bf16 g_wqkvh[H3*H],  g_wqkvl[H3*H];
__device__ bf16 g_wah[H*H],     g_wal[H*H];
__device__ bf16 g_w1h[H*FFD],   g_w1l[H*FFD];
__device__ bf16 g_w2h[H*FFD],   g_w2l[H*FFD];

#define EPI_NONE      0
#define EPI_BIAS      1
#define EPI_GELU      2
#define EPI_BIASRES   3
#define OUT_F32   0
#define OUT_SPLIT 1

__device__ __forceinline__ uint32_t su32(const void* p) {
    return (uint32_t)__cvta_generic_to_shared(p);
}
__device__ __forceinline__ void cpa16(void* s, const void* g) {
    asm volatile("cp.async.cg.shared.global [%0], [%1], 16;" :: "r"(su32(s)), "l"(g));
}
__device__ __forceinline__ void cp_commit() { asm volatile("cp.async.commit_group;"); }
template<int N> __device__ __forceinline__ void cp_wait() {
    asm volatile("cp.async.wait_group %0;" :: "n"(N));
}
__device__ __forceinline__ void mma16(float c[4], const uint32_t a[4], const uint32_t b[2]) {
    asm volatile(
        "mma.sync.aligned.m16n8k16.row.col.f32.bf16.bf16.f32 "
        "{%0,%1,%2,%3}, {%4,%5,%6,%7}, {%8,%9}, {%0,%1,%2,%3};\n"
        : "+f"(c[0]), "+f"(c[1]), "+f"(c[2]), "+f"(c[3])
        : "r"(a[0]), "r"(a[1]), "r"(a[2]), "r"(a[3]), "r"(b[0]), "r"(b[1]));
}
__device__ __forceinline__ void ldsm4(uint32_t r[4], uint32_t addr) {
    asm volatile("ldmatrix.sync.aligned.m8n8.x4.shared.b16 {%0,%1,%2,%3}, [%4];"
                 : "=r"(r[0]), "=r"(r[1]), "=r"(r[2]), "=r"(r[3]) : "r"(addr));
}
__device__ __forceinline__ void ldsm4t(uint32_t r[4], uint32_t addr) {
    asm volatile("ldmatrix.sync.aligned.m8n8.x4.trans.shared.b16 {%0,%1,%2,%3}, [%4];"
                 : "=r"(r[0]), "=r"(r[1]), "=r"(r[2]), "=r"(r[3]) : "r"(addr));
}
__device__ __forceinline__ void spbf(float x, bf16& hi, bf16& lo) {
    hi = __float2bfloat16(x);
    lo = __float2bfloat16(x - __bfloat162float(hi));
}
__device__ __forceinline__ void pack2(float x, float y, uint32_t& hi, uint32_t& lo) {
    bf16 hx = __float2bfloat16(x), hy = __float2bfloat16(y);
    bf16 lx = __float2bfloat16(x - __bfloat162float(hx));
    bf16 ly = __float2bfloat16(y - __bfloat162float(hy));
    hi = ((uint32_t)__bfloat16_as_ushort(hy) << 16) | __bfloat16_as_ushort(hx);
    lo = ((uint32_t)__bfloat16_as_ushort(ly) << 16) | __bfloat16_as_ushort(lx);
}

// ---------------------------------------------------------------------------
// bf16 split GEMM: C = (Ah+Al)(Bh+Bl)^T, 3 terms, fp32 accum.
// CTA tile 128x64, 8 warps, ldmatrix fragments.
// Pair-double-buffered 4-stage ring: BK=64 (2 chunks) per ONE __syncthreads.
// ---------------------------------------------------------------------------
template<int EPI, int OUTM>
__global__ void __launch_bounds__(256, 2)
gemm_bf(const bf16* __restrict__ Ah, const bf16* __restrict__ Al,
        const bf16* __restrict__ Bh, const bf16* __restrict__ Bl,
        const float* __restrict__ bias, const float* __restrict__ res,
        float* __restrict__ Cf, bf16* __restrict__ Ch, bf16* __restrict__ Cl,
        int K, int lda, int ldb, int ldc)
{
    extern __shared__ __align__(16) char smem[];   // 4 stages x 24576 B
    const int tid = threadIdx.x, lane = tid & 31, warp = tid >> 5;
    const int row0 = blockIdx.y * 128, col0 = blockIdx.x * 64;
    const int wm = warp & 3, wn = warp >> 2;
    const int q = lane >> 2, t = lane & 3;
    const int la = lane & 15, ca = lane >> 4;
    const int mb = lane >> 3;
    const int rb = ((mb >> 1) << 3) + (lane & 7), cb = mb & 1;
    const uint32_t sbase = su32(smem);

    auto load_stage = [&](int s, int k0) {     // no commit inside
        char* base = smem + s * 24576;
        #pragma unroll
        for (int i = 0; i < 4; i++) {
            int c = tid + i * 256, tile = c >> 9, rem = c & 511;
            int r = rem >> 2, cj = rem & 3;
            const bf16* src = (tile ? Al : Ah) + (long)(row0 + r) * lda + k0 + cj * 8;
            cpa16(base + tile * 8192 + r * 64 + ((cj ^ ((r >> 1) & 3)) * 16), src);
        }
        #pragma unroll
        for (int i = 0; i < 2; i++) {
            int c = tid + i * 256, tile = c >> 8, rem = c & 255;
            int r = rem >> 2, cj = rem & 3;
            const bf16* src = (tile ? Bl : Bh) + (long)(col0 + r) * ldb + k0 + cj * 8;
            cpa16(base + 16384 + tile * 4096 + r * 64 + ((cj ^ ((r >> 1) & 3)) * 16), src);
        }
    };

    float acc[2][4][4] = {};

    auto compute = [&](int s) {
        const uint32_t ab = sbase + s * 24576;
        #pragma unroll
        for (int ks = 0; ks < 2; ks++) {
            uint32_t ahi[2][4], alo[2][4], bhi[4][2], blo[4][2];
            #pragma unroll
            for (int mt = 0; mt < 2; mt++) {
                const int r = wm * 32 + mt * 16 + la;
                const int c = 2 * ks + ca;
                const uint32_t ad = ab + r * 64 + ((c ^ ((r >> 1) & 3)) * 16);
                ldsm4(ahi[mt], ad);
                ldsm4(alo[mt], ad + 8192);
            }
            #pragma unroll
            for (int p = 0; p < 2; p++) {
                const int r = wn * 32 + p * 16 + rb;
                const int c = 2 * ks + cb;
                const uint32_t bd = ab + 16384 + r * 64 + ((c ^ ((r >> 1) & 3)) * 16);
                uint32_t th[4], tl[4];
                ldsm4(th, bd);
                ldsm4(tl, bd + 4096);
                bhi[2*p][0] = th[0]; bhi[2*p][1] = th[1];
                bhi[2*p+1][0] = th[2]; bhi[2*p+1][1] = th[3];
                blo[2*p][0] = tl[0]; blo[2*p][1] = tl[1];
                blo[2*p+1][0] = tl[2]; blo[2*p+1][1] = tl[3];
            }
            #pragma unroll
            for (int mt = 0; mt < 2; mt++)
                #pragma unroll
                for (int nt = 0; nt < 4; nt++) {
                    mma16(acc[mt][nt], ahi[mt], bhi[nt]);
                    mma16(acc[mt][nt], ahi[mt], blo[nt]);
                    mma16(acc[mt][nt], alo[mt], bhi[nt]);
                }
        }
    };

    const int nP = K >> 6;         // pairs of 32-chunks; K % 64 == 0 here
    load_stage(0, 0);
    load_stage(1, 32);
    cp_commit();                   // group = pair 0
    for (int p = 0; p < nP; p++) {
        cp_wait<0>();              // only pair p in flight -> drained
        __syncthreads();           // pair p visible; pair p-1 fully consumed
        if (p + 1 < nP) {
            const int s0 = ((p + 1) & 1) * 2;
            load_stage(s0,     (2 * p + 2) << 5);
            load_stage(s0 + 1, (2 * p + 3) << 5);
            cp_commit();           // group = pair p+1
        }
        const int c0 = (p & 1) * 2;
        compute(c0);
        compute(c0 + 1);
    }

    #pragma unroll
    for (int mt = 0; mt < 2; mt++)
        #pragma unroll
        for (int nt = 0; nt < 4; nt++) {
            const int cg = col0 + wn * 32 + nt * 8 + 2 * t;
            #pragma unroll
            for (int h2 = 0; h2 < 2; h2++) {
                const int rg = row0 + wm * 32 + mt * 16 + q + h2 * 8;
                float v0 = acc[mt][nt][h2 * 2 + 0];
                float v1 = acc[mt][nt][h2 * 2 + 1];
                if (EPI != EPI_NONE) {
                    v0 += bias[cg];
                    v1 += bias[cg + 1];
                    if (EPI == EPI_GELU) {
                        v0 = 0.5f * v0 * (1.0f + erff(v0 * 0.70710678118654752440f));
                        v1 = 0.5f * v1 * (1.0f + erff(v1 * 0.70710678118654752440f));
                    } else if (EPI == EPI_BIASRES) {
                        v0 += res[(long)rg * ldc + cg];
                        v1 += res[(long)rg * ldc + cg + 1];
                    }
                }
                const long o = (long)rg * ldc + cg;
                if (OUTM == OUT_F32) {
                    *(float2*)(Cf + o) = make_float2(v0, v1);
                } else {
                    bf16 h0, l0, h1, l1;
                    spbf(v0, h0, l0); spbf(v1, h1, l1);
                    *(__nv_bfloat162*)(Ch + o) = __halves2bfloat162(h0, h1);
                    *(__nv_bfloat162*)(Cl + o) = __halves2bfloat162(l0, l1);
                }
            }
        }
}

// ---------------------------------------------------------------------------
// Fused flash attention (unchanged, known-good).
// ---------------------------------------------------------------------------
__global__ void __launch_bounds__(256, 1)
fattn(const bf16* __restrict__ QKVh, const bf16* __restrict__ QKVl,
      const float* __restrict__ mask,
      bf16* __restrict__ Ch, bf16* __restrict__ Cl)
{
    extern __shared__ __align__(16) char smem[];
    const int tid = threadIdx.x, lane = tid & 31, warp = tid >> 5;
    const int bh = blockIdx.y, bb = bh / NHH, hh = bh % NHH;
    const int row0 = blockIdx.x * 128;
    const long ibase = (long)bb * SS * H3 + hh * HDD;
    const long obase = (long)bb * SS * H  + hh * HDD;
    const int q = lane >> 2, t = lane & 3;
    const int la = lane & 15, ca = lane >> 4;
    const int mb = lane >> 3;
    const int rb = ((mb >> 1) << 3) + (lane & 7), cb = mb & 1;
    const uint32_t sbase = su32(smem);
    float* mask_s = (float*)(smem + 163840);

    for (int i = tid; i < SS; i += 256) mask_s[i] = mask[(long)bb * SS + i];

    auto load_q = [&]() {
        #pragma unroll
        for (int i = 0; i < 8; i++) {
            int c = tid + i * 256, buf = c >> 10, rem = c & 1023;
            int r = rem >> 3, cj = rem & 7;
            const bf16* src = (buf ? QKVl : QKVh) + ibase + (long)(row0 + r) * H3 + cj * 8;
            cpa16(smem + buf * 16384 + r * 128 + ((cj ^ (r & 7)) * 16), src);
        }
    };
    auto load_kv = [&](int s, int blk) {
        char* sb = smem + 32768 + s * 65536;
        #pragma unroll
        for (int i = 0; i < 16; i++) {
            int c = tid + i * 256, buf = c >> 10, rem = c & 1023;
            int r = rem >> 3, cj = rem & 7;
            const bf16* arr = (buf & 1) ? QKVl : QKVh;
            const int coff = (buf >> 1) ? 2 * H : H;
            const bf16* src = arr + ibase + coff + (long)(blk * 128 + r) * H3 + cj * 8;
            cpa16(sb + buf * 16384 + r * 128 + ((cj ^ (r & 7)) * 16), src);
        }
    };

    load_q();
    load_kv(0, 0);
    cp_commit();
    load_kv(1, 1);
    cp_commit();
    cp_wait<1>();
    __syncthreads();

    uint32_t qfh[4][4], qfl[4][4];
    #pragma unroll
    for (int kk = 0; kk < 4; kk++) {
        const int r = warp * 16 + la;
        const int c = 2 * kk + ca;
        const uint32_t ad = sbase + r * 128 + ((c ^ (r & 7)) * 16);
        ldsm4(qfh[kk], ad);
        ldsm4(qfl[kk], ad + 16384);
    }

    float m0 = -INFINITY, m1 = -INFINITY, l0 = 0.f, l1 = 0.f;
    float o[8][4] = {};

    for (int j = 0; j < 8; j++) {
        const uint32_t stb = sbase + 32768 + (j & 1) * 65536;

        float s[16][4];
        #pragma unroll
        for (int i = 0; i < 16; i++)
            #pragma unroll
            for (int c = 0; c < 4; c++) s[i][c] = 0.f;
        #pragma unroll
        for (int p = 0; p < 8; p++) {
            #pragma unroll
            for (int kk = 0; kk < 4; kk++) {
                const int r = p * 16 + rb;
                const int c = 2 * kk + cb;
                const uint32_t bd = stb + r * 128 + ((c ^ (r & 7)) * 16);
                uint32_t th[4], tl[4];
                ldsm4(th, bd);
                ldsm4(tl, bd + 16384);
                uint32_t b0h[2] = {th[0], th[1]}, b1h[2] = {th[2], th[3]};
                uint32_t b0l[2] = {tl[0], tl[1]}, b1l[2] = {tl[2], tl[3]};
                mma16(s[2*p],   qfh[kk], b0h);
                mma16(s[2*p],   qfh[kk], b0l);
                mma16(s[2*p],   qfl[kk], b0h);
                mma16(s[2*p+1], qfh[kk], b1h);
                mma16(s[2*p+1], qfh[kk], b1l);
                mma16(s[2*p+1], qfl[kk], b1h);
            }
        }

        #pragma unroll
        for (int nt = 0; nt < 16; nt++) {
            const int cc = j * 128 + nt * 8 + 2 * t;
            const float mk0 = mask_s[cc], mk1 = mask_s[cc + 1];
            s[nt][0] = s[nt][0] * 0.125f + mk0;
            s[nt][1] = s[nt][1] * 0.125f + mk1;
            s[nt][2] = s[nt][2] * 0.125f + mk0;
            s[nt][3] = s[nt][3] * 0.125f + mk1;
        }

        float p0 = -INFINITY, p1 = -INFINITY;
        #pragma unroll
        for (int nt = 0; nt < 16; nt++) {
            p0 = fmaxf(p0, fmaxf(s[nt][0], s[nt][1]));
            p1 = fmaxf(p1, fmaxf(s[nt][2], s[nt][3]));
        }
        p0 = fmaxf(p0, __shfl_xor_sync(~0u, p0, 1));
        p0 = fmaxf(p0, __shfl_xor_sync(~0u, p0, 2));
        p1 = fmaxf(p1, __shfl_xor_sync(~0u, p1, 1));
        p1 = fmaxf(p1, __shfl_xor_sync(~0u, p1, 2));
        const float mn0 = fmaxf(m0, p0), mn1 = fmaxf(m1, p1);
        const float a0 = __expf(m0 - mn0), a1 = __expf(m1 - mn1);
        m0 = mn0; m1 = mn1;

        float sum0 = 0.f, sum1 = 0.f;
        #pragma unroll
        for (int nt = 0; nt < 16; nt++) {
            s[nt][0] = __expf(s[nt][0] - m0); sum0 += s[nt][0];
            s[nt][1] = __expf(s[nt][1] - m0); sum0 += s[nt][1];
            s[nt][2] = __expf(s[nt][2] - m1); sum1 += s[nt][2];
            s[nt][3] = __expf(s[nt][3] - m1); sum1 += s[nt][3];
        }
        sum0 += __shfl_xor_sync(~0u, sum0, 1);
        sum0 += __shfl_xor_sync(~0u, sum0, 2);
        sum1 += __shfl_xor_sync(~0u, sum1, 1);
        sum1 += __shfl_xor_sync(~0u, sum1, 2);
        l0 = l0 * a0 + sum0;
        l1 = l1 * a1 + sum1;
        #pragma unroll
        for (int dt = 0; dt < 8; dt++) {
            o[dt][0] *= a0; o[dt][1] *= a0;
            o[dt][2] *= a1; o[dt][3] *= a1;
        }

        #pragma unroll
        for (int jk = 0; jk < 8; jk++) {
            uint32_t ah[4], al[4];
            pack2(s[2*jk][0],   s[2*jk][1],   ah[0], al[0]);
            pack2(s[2*jk][2],   s[2*jk][3],   ah[1], al[1]);
            pack2(s[2*jk+1][0], s[2*jk+1][1], ah[2], al[2]);
            pack2(s[2*jk+1][2], s[2*jk+1][3], ah[3], al[3]);
            #pragma unroll
            for (int dtp = 0; dtp < 4; dtp++) {
                const int r = jk * 16 + la;
                const int c = 2 * dtp + ca;
                const uint32_t vd = stb + 32768 + r * 128 + ((c ^ (r & 7)) * 16);
                uint32_t vh4[4], vl4[4];
                ldsm4t(vh4, vd);
                ldsm4t(vl4, vd + 16384);
                uint32_t vb0h[2] = {vh4[0], vh4[1]}, vb1h[2] = {vh4[2], vh4[3]};
                uint32_t vb0l[2] = {vl4[0], vl4[1]}, vb1l[2] = {vl4[2], vl4[3]};
                mma16(o[2*dtp],   ah, vb0h);
                mma16(o[2*dtp],   ah, vb0l);
                mma16(o[2*dtp],   al, vb0h);
                mma16(o[2*dtp+1], ah, vb1h);
                mma16(o[2*dtp+1], ah, vb1l);
                mma16(o[2*dtp+1], al, vb1h);
            }
        }

        __syncthreads();
        if (j < 7) {
            if (j + 2 < 8) { load_kv(j & 1, j + 2); cp_commit(); cp_wait<1>(); }
            else           { cp_wait<0>(); }
            __syncthreads();
        }
    }

    const float i0 = 1.0f / l0, i1 = 1.0f / l1;
    #pragma unroll
    for (int dt = 0; dt < 8; dt++) {
        const int cg = dt * 8 + 2 * t;
        #pragma unroll
        for (int h2 = 0; h2 < 2; h2++) {
            const int rg = row0 + warp * 16 + q + h2 * 8;
            const float inv = h2 ? i1 : i0;
            float v0 = o[dt][h2 * 2 + 0] * inv;
            float v1 = o[dt][h2 * 2 + 1] * inv;
            bf16 h0, lo0, h1, lo1;
            spbf(v0, h0, lo0); spbf(v1, h1, lo1);
            const long off = obase + (long)rg * H + cg;
            *(__nv_bfloat162*)(Ch + off) = __halves2bfloat162(h0, h1);
            *(__nv_bfloat162*)(Cl + off) = __halves2bfloat162(lo0, lo1);
        }
    }
}

// ---------------------------------------------------------------------------
// Prep (single launch): split hs; transpose+split all weights; pack QKV bias.
// ---------------------------------------------------------------------------
__device__ __forceinline__ void tr_tile(const float* in, bf16* oh, bf16* ol,
                                        int ldi, int ldo, int bx, int by,
                                        float (*tsm)[33])
{
    const int r0 = by * 32, c0 = bx * 32;
    const int tx = threadIdx.x & 31, ty = threadIdx.x >> 5;
    #pragma unroll
    for (int i = 0; i < 32; i += 8)
        tsm[ty + i][tx] = in[(long)(r0 + ty + i) * ldi + c0 + tx];
    __syncthreads();
    #pragma unroll
    for (int i = 0; i < 32; i += 8) {
        float v = tsm[tx][ty + i];
        bf16 hb, lb; spbf(v, hb, lb);
        long o = (long)(c0 + ty + i) * ldo + r0 + tx;
        oh[o] = hb; ol[o] = lb;
    }
}

__global__ void __launch_bounds__(256)
prep(const float* __restrict__ hs,
     const float* __restrict__ q_w, const float* __restrict__ k_w,
     const float* __restrict__ v_w, const float* __restrict__ ao_w,
     const float* __restrict__ ff1_w, const float* __restrict__ ff2_w,
     const float* __restrict__ q_b, const float* __restrict__ k_b,
     const float* __restrict__ v_b)
{
    __shared__ float tsm[32][33];
    const int b = blockIdx.x;
    if (b < 3072) {
        const int i = b * 256 + threadIdx.x;
        float4 v = ((const float4*)hs)[i];
        bf16 h0, l0, h1, l1;
        spbf(v.x, h0, l0); spbf(v.y, h1, l1);
        *(__nv_bfloat162*)(g_xh + i * 4) = __halves2bfloat162(h0, h1);
        *(__nv_bfloat162*)(g_xl + i * 4) = __halves2bfloat162(l0, l1);
        spbf(v.z, h0, l0); spbf(v.w, h1, l1);
        *(__nv_bfloat162*)(g_xh + i * 4 + 2) = __halves2bfloat162(h0, h1);
        *(__nv_bfloat162*)(g_xl + i * 4 + 2) = __halves2bfloat162(l0, l1);
    } else if (b < 3648) {
        int tt = b - 3072; tr_tile(q_w, g_wqkvh, g_wqkvl, H, H, tt % 24, tt / 24, tsm);
    } else if (b < 4224) {
        int tt = b - 3648; tr_tile(k_w, g_wqkvh + H*H, g_wqkvl + H*H, H, H, tt % 24, tt / 24, tsm);
    } else if (b < 4800) {
        int tt = b - 4224; tr_tile(v_w, g_wqkvh + 2*H*H, g_wqkvl + 2*H*H, H, H, tt % 24, tt / 24, tsm);
    } else if (b < 5376) {
        int tt = b - 4800; tr_tile(ao_w, g_wah, g_wal, H, H, tt % 24, tt / 24, tsm);
    } else if (b < 7680) {
        int tt = b - 5376; tr_tile(ff1_w, g_w1h, g_w1l, FFD, H, tt % 96, tt / 96, tsm);
    } else if (b < 9984) {
        int tt = b - 7680; tr_tile(ff2_w, g_w2h, g_w2l, H, FFD, tt % 24, tt / 24, tsm);
    } else {
        const int i = (b - 9984) * 256 + threadIdx.x;
        float v = (i < H) ? q_b[i] : (i < 2*H) ? k_b[i - H] : v_b[i - 2*H];
        g_bqkv[i] = v;
    }
}

// ---------------------------------------------------------------------------
// LayerNorm row H=768; warp-shuffle reductions (2 barriers total).
// ---------------------------------------------------------------------------
template<bool SPLIT>
__global__ void __launch_bounds__(256)
ln_rows(const float* __restrict__ in, const float* __restrict__ g,
        const float* __restrict__ b, float* __restrict__ out,
        bf16* __restrict__ oh, bf16* __restrict__ ol)
{
    const long off = (long)blockIdx.x * H;
    const float* p = in + off;
    const int tid = threadIdx.x, lane = tid & 31, warp = tid >> 5;
    __shared__ float rs[8], rq[8];
    const float x0 = p[tid], x1 = p[tid + 256], x2 = p[tid + 512];
    float s  = x0 + x1 + x2;
    float sq = x0 * x0 + x1 * x1 + x2 * x2;
    #pragma unroll
    for (int o = 16; o > 0; o >>= 1) {
        s  += __shfl_xor_sync(~0u, s,  o);
        sq += __shfl_xor_sync(~0u, sq, o);
    }
    if (lane == 0) { rs[warp] = s; rq[warp] = sq; }
    __syncthreads();
    float ts = 0.f, tq = 0.f;
    #pragma unroll
    for (int i = 0; i < 8; i++) { ts += rs[i]; tq += rq[i]; }
    const float mean = ts * (1.0f / H);
    const float var  = tq * (1.0f / H) - mean * mean;
    const float inv  = rsqrtf(var + 1e-5f);
    #pragma unroll
    for (int i = 0; i < 3; i++) {
        const int c = tid + i * 256;
        const float xv = (i == 0 ? x0 : (i == 1 ? x1 : x2));
        const float o = (xv - mean) * inv * g[c] + b[c];
        out[off + c] = o;
        if (SPLIT) {
            bf16 hb, lb; spbf(o, hb, lb);
            oh[off + c] = hb; ol[off + c] = lb;
        }
    }
}

// ---------------------------------------------------------------------------
extern "C" void kernel_launch(void* const* d_in, const int* in_sizes, int n_in,
                              void* d_out, int out_size)
{
    const float* hs    = (const float*)d_in[0];
    const float* mask  = (const float*)d_in[1];
    const float* q_w   = (const float*)d_in[2];
    const float* q_b   = (const float*)d_in[3];
    const float* k_w   = (const float*)d_in[4];
    const float* k_b   = (const float*)d_in[5];
    const float* v_w   = (const float*)d_in[6];
    const float* v_b   = (const float*)d_in[7];
    const float* ao_w  = (const float*)d_in[8];
    const float* ao_b  = (const float*)d_in[9];
    const float* ln1_g = (const float*)d_in[10];
    const float* ln1_b = (const float*)d_in[11];
    const float* ff1_w = (const float*)d_in[12];
    const float* ff1_b = (const float*)d_in[13];
    const float* ff2_w = (const float*)d_in[14];
    const float* ff2_b = (const float*)d_in[15];
    const float* ln2_g = (const float*)d_in[16];
    const float* ln2_b = (const float*)d_in[17];
    float* out = (float*)d_out;

    float *x, *t, *at, *bqkv;
    bf16 *xh,*xl,*qkvh,*qkvl,*ch,*cl,*ah,*al,*fh,*fl;
    bf16 *wqkvh,*wqkvl,*wah,*wal,*w1h,*w1l,*w2h,*w2l;
    cudaGetSymbolAddress((void**)&x, g_x);
    cudaGetSymbolAddress((void**)&t, g_t);      cudaGetSymbolAddress((void**)&at, g_at);
    cudaGetSymbolAddress((void**)&bqkv, g_bqkv);
    cudaGetSymbolAddress((void**)&xh, g_xh);    cudaGetSymbolAddress((void**)&xl, g_xl);
    cudaGetSymbolAddress((void**)&qkvh, g_qkvh);cudaGetSymbolAddress((void**)&qkvl, g_qkvl);
    cudaGetSymbolAddress((void**)&ch, g_ch);    cudaGetSymbolAddress((void**)&cl, g_cl);
    cudaGetSymbolAddress((void**)&ah, g_ah);    cudaGetSymbolAddress((void**)&al, g_al);
    cudaGetSymbolAddress((void**)&fh, g_fh);    cudaGetSymbolAddress((void**)&fl, g_fl);
    cudaGetSymbolAddress((void**)&wqkvh, g_wqkvh);
    cudaGetSymbolAddress((void**)&wqkvl, g_wqkvl);
    cudaGetSymbolAddress((void**)&wah, g_wah);  cudaGetSymbolAddress((void**)&wal, g_wal);
    cudaGetSymbolAddress((void**)&w1h, g_w1h);  cudaGetSymbolAddress((void**)&w1l, g_w1l);
    cudaGetSymbolAddress((void**)&w2h, g_w2h);  cudaGetSymbolAddress((void**)&w2l, g_w2l);

    const int SMB = 98304;    // 4 stages x 24576
    cudaFuncSetAttribute(gemm_bf<EPI_BIAS,   OUT_SPLIT>, cudaFuncAttributeMaxDynamicSharedMemorySize, SMB);
    cudaFuncSetAttribute(gemm_bf<EPI_BIASRES,OUT_F32>,   cudaFuncAttributeMaxDynamicSharedMemorySize, SMB);
    cudaFuncSetAttribute(gemm_bf<EPI_GELU,   OUT_SPLIT>, cudaFuncAttributeMaxDynamicSharedMemorySize, SMB);
    const int SMF = 167936;   // 164 KB
    cudaFuncSetAttribute(fattn, cudaFuncAttributeMaxDynamicSharedMemorySize, SMF);

    cudaMemcpyAsync(x, hs, (size_t)NTOK * H * sizeof(float), cudaMemcpyDeviceToDevice);
    prep<<<9993, 256>>>(hs, q_w, k_w, v_w, ao_w, ff1_w, ff2_w, q_b, k_b, v_b);

    const dim3 gQKV(36, 32), gProj(12, 32), gFF1(48, 32), gAtt(8, 48);

    for (int layer = 0; layer < NLAYER; layer++) {
        gemm_bf<EPI_BIAS, OUT_SPLIT><<<gQKV, 256, SMB>>>(
            xh, xl, wqkvh, wqkvl, bqkv, nullptr, nullptr, qkvh, qkvl,
            H, H, H, H3);

        fattn<<<gAtt, 256, SMF>>>(qkvh, qkvl, mask, ch, cl);

        gemm_bf<EPI_BIASRES, OUT_F32><<<gProj, 256, SMB>>>(
            ch, cl, wah, wal, ao_b, x, t, nullptr, nullptr, H, H, H, H);
        ln_rows<true><<<NTOK, 256>>>(t, ln1_g, ln1_b, at, ah, al);

        gemm_bf<EPI_GELU, OUT_SPLIT><<<gFF1, 256, SMB>>>(
            ah, al, w1h, w1l, ff1_b, nullptr, nullptr, fh, fl, H, H, H, FFD);
        gemm_bf<EPI_BIASRES, OUT_F32><<<gProj, 256, SMB>>>(
            fh, fl, w2h, w2l, ff2_b, at, t, nullptr, nullptr, FFD, FFD, FFD, H);

        if (layer == NLAYER - 1) {
            ln_rows<false><<<NTOK, 256>>>(t, ln2_g, ln2_b, out, nullptr, nullptr);
        } else {
            ln_rows<true><<<NTOK, 256>>>(t, ln2_g, ln2_b, x, xh, xl);
        }
    }
}

// round 15
// speedup vs baseline: 3.7523x; 1.0213x over previous
#include <cuda_runtime.h>
#include <cuda_bf16.h>
#include <math.h>
#include <stdint.h>

#define H    768
#define FFD  3072
#define BB   4
#define SS   1024
#define NHH  12
#define HDD  64
#define NTOK 4096
#define NLAYER 6
#define H3   2304   // 3*H packed QKV

typedef __nv_bfloat16 bf16;

// ---------------- device scratch ----------------
__device__ float g_t [NTOK*H];
__device__ float g_at[NTOK*H];
__device__ float g_x [NTOK*H];
__device__ float g_bqkv[H3];
__device__ bf16 g_xh[NTOK*H],   g_xl[NTOK*H];
__device__ bf16 g_qkvh[NTOK*H3], g_qkvl[NTOK*H3];
__device__ bf16 g_ch[NTOK*H],   g_cl[NTOK*H];
__device__ bf16 g_ah[NTOK*H],   g_al[NTOK*H];
__device__ bf16 g_fh[NTOK*FFD], g_fl[NTOK*FFD];
__device__ bf16 g_wqkvh[H3*H],  g_wqkvl[H3*H];
__device__ bf16 g_wah[H*H],     g_wal[H*H];
__device__ bf16 g_w1h[H*FFD],   g_w1l[H*FFD];
__device__ bf16 g_w2h[H*FFD],   g_w2l[H*FFD];

#define EPI_NONE      0
#define EPI_BIAS      1
#define EPI_GELU      2
#define EPI_BIASRES   3
#define OUT_F32   0
#define OUT_SPLIT 1

__device__ __forceinline__ uint32_t su32(const void* p) {
    return (uint32_t)__cvta_generic_to_shared(p);
}
__device__ __forceinline__ void cpa16(void* s, const void* g) {
    asm volatile("cp.async.cg.shared.global [%0], [%1], 16;" :: "r"(su32(s)), "l"(g));
}
__device__ __forceinline__ void cp_commit() { asm volatile("cp.async.commit_group;"); }
template<int N> __device__ __forceinline__ void cp_wait() {
    asm volatile("cp.async.wait_group %0;" :: "n"(N));
}
__device__ __forceinline__ void mma16(float c[4], const uint32_t a[4], const uint32_t b[2]) {
    asm volatile(
        "mma.sync.aligned.m16n8k16.row.col.f32.bf16.bf16.f32 "
        "{%0,%1,%2,%3}, {%4,%5,%6,%7}, {%8,%9}, {%0,%1,%2,%3};\n"
        : "+f"(c[0]), "+f"(c[1]), "+f"(c[2]), "+f"(c[3])
        : "r"(a[0]), "r"(a[1]), "r"(a[2]), "r"(a[3]), "r"(b[0]), "r"(b[1]));
}
__device__ __forceinline__ void ldsm4(uint32_t r[4], uint32_t addr) {
    asm volatile("ldmatrix.sync.aligned.m8n8.x4.shared.b16 {%0,%1,%2,%3}, [%4];"
                 : "=r"(r[0]), "=r"(r[1]), "=r"(r[2]), "=r"(r[3]) : "r"(addr));
}
__device__ __forceinline__ void ldsm4t(uint32_t r[4], uint32_t addr) {
    asm volatile("ldmatrix.sync.aligned.m8n8.x4.trans.shared.b16 {%0,%1,%2,%3}, [%4];"
                 : "=r"(r[0]), "=r"(r[1]), "=r"(r[2]), "=r"(r[3]) : "r"(addr));
}
__device__ __forceinline__ void spbf(float x, bf16& hi, bf16& lo) {
    hi = __float2bfloat16(x);
    lo = __float2bfloat16(x - __bfloat162float(hi));
}
__device__ __forceinline__ void pack2(float x, float y, uint32_t& hi, uint32_t& lo) {
    bf16 hx = __float2bfloat16(x), hy = __float2bfloat16(y);
    bf16 lx = __float2bfloat16(x - __bfloat162float(hx));
    bf16 ly = __float2bfloat16(y - __bfloat162float(hy));
    hi = ((uint32_t)__bfloat16_as_ushort(hy) << 16) | __bfloat16_as_ushort(hx);
    lo = ((uint32_t)__bfloat16_as_ushort(ly) << 16) | __bfloat16_as_ushort(lx);
}

// ---------------------------------------------------------------------------
// bf16 split GEMM: C = (Ah+Al)(Bh+Bl)^T, 3 terms, fp32 accum.
// CTA tile 128x64, BK=32, 8 warps, ldmatrix fragments.
// 3-stage cp.async ring, one __syncthreads per chunk, 3 CTAs/SM.
// ---------------------------------------------------------------------------
template<int EPI, int OUTM>
__global__ void __launch_bounds__(256, 3)
gemm_bf(const bf16* __restrict__ Ah, const bf16* __restrict__ Al,
        const bf16* __restrict__ Bh, const bf16* __restrict__ Bl,
        const float* __restrict__ bias, const float* __restrict__ res,
        float* __restrict__ Cf, bf16* __restrict__ Ch, bf16* __restrict__ Cl,
        int K, int lda, int ldb, int ldc)
{
    extern __shared__ __align__(16) char smem[];   // 3 stages x 24576 B
    const int tid = threadIdx.x, lane = tid & 31, warp = tid >> 5;
    const int row0 = blockIdx.y * 128, col0 = blockIdx.x * 64;
    const int wm = warp & 3, wn = warp >> 2;
    const int q = lane >> 2, t = lane & 3;
    const int la = lane & 15, ca = lane >> 4;
    const int mb = lane >> 3;
    const int rb = ((mb >> 1) << 3) + (lane & 7), cb = mb & 1;
    const uint32_t sbase = su32(smem);

    auto load_stage = [&](int s, int k0) {
        char* base = smem + s * 24576;
        #pragma unroll
        for (int i = 0; i < 4; i++) {
            int c = tid + i * 256, tile = c >> 9, rem = c & 511;
            int r = rem >> 2, cj = rem & 3;
            const bf16* src = (tile ? Al : Ah) + (long)(row0 + r) * lda + k0 + cj * 8;
            cpa16(base + tile * 8192 + r * 64 + ((cj ^ ((r >> 1) & 3)) * 16), src);
        }
        #pragma unroll
        for (int i = 0; i < 2; i++) {
            int c = tid + i * 256, tile = c >> 8, rem = c & 255;
            int r = rem >> 2, cj = rem & 3;
            const bf16* src = (tile ? Bl : Bh) + (long)(col0 + r) * ldb + k0 + cj * 8;
            cpa16(base + 16384 + tile * 4096 + r * 64 + ((cj ^ ((r >> 1) & 3)) * 16), src);
        }
        cp_commit();
    };

    float acc[2][4][4] = {};

    auto compute = [&](int s) {
        const uint32_t ab = sbase + s * 24576;
        #pragma unroll
        for (int ks = 0; ks < 2; ks++) {
            uint32_t ahi[2][4], alo[2][4], bhi[4][2], blo[4][2];
            #pragma unroll
            for (int mt = 0; mt < 2; mt++) {
                const int r = wm * 32 + mt * 16 + la;
                const int c = 2 * ks + ca;
                const uint32_t ad = ab + r * 64 + ((c ^ ((r >> 1) & 3)) * 16);
                ldsm4(ahi[mt], ad);
                ldsm4(alo[mt], ad + 8192);
            }
            #pragma unroll
            for (int p = 0; p < 2; p++) {
                const int r = wn * 32 + p * 16 + rb;
                const int c = 2 * ks + cb;
                const uint32_t bd = ab + 16384 + r * 64 + ((c ^ ((r >> 1) & 3)) * 16);
                uint32_t th[4], tl[4];
                ldsm4(th, bd);
                ldsm4(tl, bd + 4096);
                bhi[2*p][0] = th[0]; bhi[2*p][1] = th[1];
                bhi[2*p+1][0] = th[2]; bhi[2*p+1][1] = th[3];
                blo[2*p][0] = tl[0]; blo[2*p][1] = tl[1];
                blo[2*p+1][0] = tl[2]; blo[2*p+1][1] = tl[3];
            }
            #pragma unroll
            for (int mt = 0; mt < 2; mt++)
                #pragma unroll
                for (int nt = 0; nt < 4; nt++) {
                    mma16(acc[mt][nt], ahi[mt], bhi[nt]);
                    mma16(acc[mt][nt], ahi[mt], blo[nt]);
                    mma16(acc[mt][nt], alo[mt], bhi[nt]);
                }
        }
    };

    const int nIt = K >> 5;
    load_stage(0, 0);
    load_stage(1, 32);
    for (int it = 0; it < nIt; it++) {
        if (it + 1 < nIt) cp_wait<1>();
        else              cp_wait<0>();
        __syncthreads();   // stage it%3 ready; stage (it+2)%3 (=it-1) consumed
        if (it + 2 < nIt) load_stage((it + 2) % 3, (it + 2) << 5);
        compute(it % 3);
    }

    #pragma unroll
    for (int mt = 0; mt < 2; mt++)
        #pragma unroll
        for (int nt = 0; nt < 4; nt++) {
            const int cg = col0 + wn * 32 + nt * 8 + 2 * t;
            #pragma unroll
            for (int h2 = 0; h2 < 2; h2++) {
                const int rg = row0 + wm * 32 + mt * 16 + q + h2 * 8;
                float v0 = acc[mt][nt][h2 * 2 + 0];
                float v1 = acc[mt][nt][h2 * 2 + 1];
                if (EPI != EPI_NONE) {
                    v0 += bias[cg];
                    v1 += bias[cg + 1];
                    if (EPI == EPI_GELU) {
                        v0 = 0.5f * v0 * (1.0f + erff(v0 * 0.70710678118654752440f));
                        v1 = 0.5f * v1 * (1.0f + erff(v1 * 0.70710678118654752440f));
                    } else if (EPI == EPI_BIASRES) {
                        v0 += res[(long)rg * ldc + cg];
                        v1 += res[(long)rg * ldc + cg + 1];
                    }
                }
                const long o = (long)rg * ldc + cg;
                if (OUTM == OUT_F32) {
                    *(float2*)(Cf + o) = make_float2(v0, v1);
                } else {
                    bf16 h0, l0, h1, l1;
                    spbf(v0, h0, l0); spbf(v1, h1, l1);
                    *(__nv_bfloat162*)(Ch + o) = __halves2bfloat162(h0, h1);
                    *(__nv_bfloat162*)(Cl + o) = __halves2bfloat162(l0, l1);
                }
            }
        }
}

// ---------------------------------------------------------------------------
// Fused flash attention (unchanged, known-good).
// ---------------------------------------------------------------------------
__global__ void __launch_bounds__(256, 1)
fattn(const bf16* __restrict__ QKVh, const bf16* __restrict__ QKVl,
      const float* __restrict__ mask,
      bf16* __restrict__ Ch, bf16* __restrict__ Cl)
{
    extern __shared__ __align__(16) char smem[];
    const int tid = threadIdx.x, lane = tid & 31, warp = tid >> 5;
    const int bh = blockIdx.y, bb = bh / NHH, hh = bh % NHH;
    const int row0 = blockIdx.x * 128;
    const long ibase = (long)bb * SS * H3 + hh * HDD;
    const long obase = (long)bb * SS * H  + hh * HDD;
    const int q = lane >> 2, t = lane & 3;
    const int la = lane & 15, ca = lane >> 4;
    const int mb = lane >> 3;
    const int rb = ((mb >> 1) << 3) + (lane & 7), cb = mb & 1;
    const uint32_t sbase = su32(smem);
    float* mask_s = (float*)(smem + 163840);

    for (int i = tid; i < SS; i += 256) mask_s[i] = mask[(long)bb * SS + i];

    auto load_q = [&]() {
        #pragma unroll
        for (int i = 0; i < 8; i++) {
            int c = tid + i * 256, buf = c >> 10, rem = c & 1023;
            int r = rem >> 3, cj = rem & 7;
            const bf16* src = (buf ? QKVl : QKVh) + ibase + (long)(row0 + r) * H3 + cj * 8;
            cpa16(smem + buf * 16384 + r * 128 + ((cj ^ (r & 7)) * 16), src);
        }
    };
    auto load_kv = [&](int s, int blk) {
        char* sb = smem + 32768 + s * 65536;
        #pragma unroll
        for (int i = 0; i < 16; i++) {
            int c = tid + i * 256, buf = c >> 10, rem = c & 1023;
            int r = rem >> 3, cj = rem & 7;
            const bf16* arr = (buf & 1) ? QKVl : QKVh;
            const int coff = (buf >> 1) ? 2 * H : H;
            const bf16* src = arr + ibase + coff + (long)(blk * 128 + r) * H3 + cj * 8;
            cpa16(sb + buf * 16384 + r * 128 + ((cj ^ (r & 7)) * 16), src);
        }
    };

    load_q();
    load_kv(0, 0);
    cp_commit();
    load_kv(1, 1);
    cp_commit();
    cp_wait<1>();
    __syncthreads();

    uint32_t qfh[4][4], qfl[4][4];
    #pragma unroll
    for (int kk = 0; kk < 4; kk++) {
        const int r = warp * 16 + la;
        const int c = 2 * kk + ca;
        const uint32_t ad = sbase + r * 128 + ((c ^ (r & 7)) * 16);
        ldsm4(qfh[kk], ad);
        ldsm4(qfl[kk], ad + 16384);
    }

    float m0 = -INFINITY, m1 = -INFINITY, l0 = 0.f, l1 = 0.f;
    float o[8][4] = {};

    for (int j = 0; j < 8; j++) {
        const uint32_t stb = sbase + 32768 + (j & 1) * 65536;

        float s[16][4];
        #pragma unroll
        for (int i = 0; i < 16; i++)
            #pragma unroll
            for (int c = 0; c < 4; c++) s[i][c] = 0.f;
        #pragma unroll
        for (int p = 0; p < 8; p++) {
            #pragma unroll
            for (int kk = 0; kk < 4; kk++) {
                const int r = p * 16 + rb;
                const int c = 2 * kk + cb;
                const uint32_t bd = stb + r * 128 + ((c ^ (r & 7)) * 16);
                uint32_t th[4], tl[4];
                ldsm4(th, bd);
                ldsm4(tl, bd + 16384);
                uint32_t b0h[2] = {th[0], th[1]}, b1h[2] = {th[2], th[3]};
                uint32_t b0l[2] = {tl[0], tl[1]}, b1l[2] = {tl[2], tl[3]};
                mma16(s[2*p],   qfh[kk], b0h);
                mma16(s[2*p],   qfh[kk], b0l);
                mma16(s[2*p],   qfl[kk], b0h);
                mma16(s[2*p+1], qfh[kk], b1h);
                mma16(s[2*p+1], qfh[kk], b1l);
                mma16(s[2*p+1], qfl[kk], b1h);
            }
        }

        #pragma unroll
        for (int nt = 0; nt < 16; nt++) {
            const int cc = j * 128 + nt * 8 + 2 * t;
            const float mk0 = mask_s[cc], mk1 = mask_s[cc + 1];
            s[nt][0] = s[nt][0] * 0.125f + mk0;
            s[nt][1] = s[nt][1] * 0.125f + mk1;
            s[nt][2] = s[nt][2] * 0.125f + mk0;
            s[nt][3] = s[nt][3] * 0.125f + mk1;
        }

        float p0 = -INFINITY, p1 = -INFINITY;
        #pragma unroll
        for (int nt = 0; nt < 16; nt++) {
            p0 = fmaxf(p0, fmaxf(s[nt][0], s[nt][1]));
            p1 = fmaxf(p1, fmaxf(s[nt][2], s[nt][3]));
        }
        p0 = fmaxf(p0, __shfl_xor_sync(~0u, p0, 1));
        p0 = fmaxf(p0, __shfl_xor_sync(~0u, p0, 2));
        p1 = fmaxf(p1, __shfl_xor_sync(~0u, p1, 1));
        p1 = fmaxf(p1, __shfl_xor_sync(~0u, p1, 2));
        const float mn0 = fmaxf(m0, p0), mn1 = fmaxf(m1, p1);
        const float a0 = __expf(m0 - mn0), a1 = __expf(m1 - mn1);
        m0 = mn0; m1 = mn1;

        float sum0 = 0.f, sum1 = 0.f;
        #pragma unroll
        for (int nt = 0; nt < 16; nt++) {
            s[nt][0] = __expf(s[nt][0] - m0); sum0 += s[nt][0];
            s[nt][1] = __expf(s[nt][1] - m0); sum0 += s[nt][1];
            s[nt][2] = __expf(s[nt][2] - m1); sum1 += s[nt][2];
            s[nt][3] = __expf(s[nt][3] - m1); sum1 += s[nt][3];
        }
        sum0 += __shfl_xor_sync(~0u, sum0, 1);
        sum0 += __shfl_xor_sync(~0u, sum0, 2);
        sum1 += __shfl_xor_sync(~0u, sum1, 1);
        sum1 += __shfl_xor_sync(~0u, sum1, 2);
        l0 = l0 * a0 + sum0;
        l1 = l1 * a1 + sum1;
        #pragma unroll
        for (int dt = 0; dt < 8; dt++) {
            o[dt][0] *= a0; o[dt][1] *= a0;
            o[dt][2] *= a1; o[dt][3] *= a1;
        }

        #pragma unroll
        for (int jk = 0; jk < 8; jk++) {
            uint32_t ah[4], al[4];
            pack2(s[2*jk][0],   s[2*jk][1],   ah[0], al[0]);
            pack2(s[2*jk][2],   s[2*jk][3],   ah[1], al[1]);
            pack2(s[2*jk+1][0], s[2*jk+1][1], ah[2], al[2]);
            pack2(s[2*jk+1][2], s[2*jk+1][3], ah[3], al[3]);
            #pragma unroll
            for (int dtp = 0; dtp < 4; dtp++) {
                const int r = jk * 16 + la;
                const int c = 2 * dtp + ca;
                const uint32_t vd = stb + 32768 + r * 128 + ((c ^ (r & 7)) * 16);
                uint32_t vh4[4], vl4[4];
                ldsm4t(vh4, vd);
                ldsm4t(vl4, vd + 16384);
                uint32_t vb0h[2] = {vh4[0], vh4[1]}, vb1h[2] = {vh4[2], vh4[3]};
                uint32_t vb0l[2] = {vl4[0], vl4[1]}, vb1l[2] = {vl4[2], vl4[3]};
                mma16(o[2*dtp],   ah, vb0h);
                mma16(o[2*dtp],   ah, vb0l);
                mma16(o[2*dtp],   al, vb0h);
                mma16(o[2*dtp+1], ah, vb1h);
                mma16(o[2*dtp+1], ah, vb1l);
                mma16(o[2*dtp+1], al, vb1h);
            }
        }

        __syncthreads();
        if (j < 7) {
            if (j + 2 < 8) { load_kv(j & 1, j + 2); cp_commit(); cp_wait<1>(); }
            else           { cp_wait<0>(); }
            __syncthreads();
        }
    }

    const float i0 = 1.0f / l0, i1 = 1.0f / l1;
    #pragma unroll
    for (int dt = 0; dt < 8; dt++) {
        const int cg = dt * 8 + 2 * t;
        #pragma unroll
        for (int h2 = 0; h2 < 2; h2++) {
            const int rg = row0 + warp * 16 + q + h2 * 8;
            const float inv = h2 ? i1 : i0;
            float v0 = o[dt][h2 * 2 + 0] * inv;
            float v1 = o[dt][h2 * 2 + 1] * inv;
            bf16 h0, lo0, h1, lo1;
            spbf(v0, h0, lo0); spbf(v1, h1, lo1);
            const long off = obase + (long)rg * H + cg;
            *(__nv_bfloat162*)(Ch + off) = __halves2bfloat162(h0, h1);
            *(__nv_bfloat162*)(Cl + off) = __halves2bfloat162(lo0, lo1);
        }
    }
}

// ---------------------------------------------------------------------------
// Prep (single launch): split hs; transpose+split all weights; pack QKV bias.
// ---------------------------------------------------------------------------
__device__ __forceinline__ void tr_tile(const float* in, bf16* oh, bf16* ol,
                                        int ldi, int ldo, int bx, int by,
                                        float (*tsm)[33])
{
    const int r0 = by * 32, c0 = bx * 32;
    const int tx = threadIdx.x & 31, ty = threadIdx.x >> 5;
    #pragma unroll
    for (int i = 0; i < 32; i += 8)
        tsm[ty + i][tx] = in[(long)(r0 + ty + i) * ldi + c0 + tx];
    __syncthreads();
    #pragma unroll
    for (int i = 0; i < 32; i += 8) {
        float v = tsm[tx][ty + i];
        bf16 hb, lb; spbf(v, hb, lb);
        long o = (long)(c0 + ty + i) * ldo + r0 + tx;
        oh[o] = hb; ol[o] = lb;
    }
}

__global__ void __launch_bounds__(256)
prep(const float* __restrict__ hs,
     const float* __restrict__ q_w, const float* __restrict__ k_w,
     const float* __restrict__ v_w, const float* __restrict__ ao_w,
     const float* __restrict__ ff1_w, const float* __restrict__ ff2_w,
     const float* __restrict__ q_b, const float* __restrict__ k_b,
     const float* __restrict__ v_b)
{
    __shared__ float tsm[32][33];
    const int b = blockIdx.x;
    if (b < 3072) {
        const int i = b * 256 + threadIdx.x;
        float4 v = ((const float4*)hs)[i];
        bf16 h0, l0, h1, l1;
        spbf(v.x, h0, l0); spbf(v.y, h1, l1);
        *(__nv_bfloat162*)(g_xh + i * 4) = __halves2bfloat162(h0, h1);
        *(__nv_bfloat162*)(g_xl + i * 4) = __halves2bfloat162(l0, l1);
        spbf(v.z, h0, l0); spbf(v.w, h1, l1);
        *(__nv_bfloat162*)(g_xh + i * 4 + 2) = __halves2bfloat162(h0, h1);
        *(__nv_bfloat162*)(g_xl + i * 4 + 2) = __halves2bfloat162(l0, l1);
    } else if (b < 3648) {
        int tt = b - 3072; tr_tile(q_w, g_wqkvh, g_wqkvl, H, H, tt % 24, tt / 24, tsm);
    } else if (b < 4224) {
        int tt = b - 3648; tr_tile(k_w, g_wqkvh + H*H, g_wqkvl + H*H, H, H, tt % 24, tt / 24, tsm);
    } else if (b < 4800) {
        int tt = b - 4224; tr_tile(v_w, g_wqkvh + 2*H*H, g_wqkvl + 2*H*H, H, H, tt % 24, tt / 24, tsm);
    } else if (b < 5376) {
        int tt = b - 4800; tr_tile(ao_w, g_wah, g_wal, H, H, tt % 24, tt / 24, tsm);
    } else if (b < 7680) {
        int tt = b - 5376; tr_tile(ff1_w, g_w1h, g_w1l, FFD, H, tt % 96, tt / 96, tsm);
    } else if (b < 9984) {
        int tt = b - 7680; tr_tile(ff2_w, g_w2h, g_w2l, H, FFD, tt % 24, tt / 24, tsm);
    } else {
        const int i = (b - 9984) * 256 + threadIdx.x;
        float v = (i < H) ? q_b[i] : (i < 2*H) ? k_b[i - H] : v_b[i - 2*H];
        g_bqkv[i] = v;
    }
}

// ---------------------------------------------------------------------------
// LayerNorm row H=768; warp-shuffle reductions.
// ---------------------------------------------------------------------------
template<bool SPLIT>
__global__ void __launch_bounds__(256)
ln_rows(const float* __restrict__ in, const float* __restrict__ g,
        const float* __restrict__ b, float* __restrict__ out,
        bf16* __restrict__ oh, bf16* __restrict__ ol)
{
    const long off = (long)blockIdx.x * H;
    const float* p = in + off;
    const int tid = threadIdx.x, lane = tid & 31, warp = tid >> 5;
    __shared__ float rs[8], rq[8];
    const float x0 = p[tid], x1 = p[tid + 256], x2 = p[tid + 512];
    float s  = x0 + x1 + x2;
    float sq = x0 * x0 + x1 * x1 + x2 * x2;
    #pragma unroll
    for (int o = 16; o > 0; o >>= 1) {
        s  += __shfl_xor_sync(~0u, s,  o);
        sq += __shfl_xor_sync(~0u, sq, o);
    }
    if (lane == 0) { rs[warp] = s; rq[warp] = sq; }
    __syncthreads();
    float ts = 0.f, tq = 0.f;
    #pragma unroll
    for (int i = 0; i < 8; i++) { ts += rs[i]; tq += rq[i]; }
    const float mean = ts * (1.0f / H);
    const float var  = tq * (1.0f / H) - mean * mean;
    const float inv  = rsqrtf(var + 1e-5f);
    #pragma unroll
    for (int i = 0; i < 3; i++) {
        const int c = tid + i * 256;
        const float xv = (i == 0 ? x0 : (i == 1 ? x1 : x2));
        const float o = (xv - mean) * inv * g[c] + b[c];
        out[off + c] = o;
        if (SPLIT) {
            bf16 hb, lb; spbf(o, hb, lb);
            oh[off + c] = hb; ol[off + c] = lb;
        }
    }
}

// ---------------------------------------------------------------------------
extern "C" void kernel_launch(void* const* d_in, const int* in_sizes, int n_in,
                              void* d_out, int out_size)
{
    const float* hs    = (const float*)d_in[0];
    const float* mask  = (const float*)d_in[1];
    const float* q_w   = (const float*)d_in[2];
    const float* q_b   = (const float*)d_in[3];
    const float* k_w   = (const float*)d_in[4];
    const float* k_b   = (const float*)d_in[5];
    const float* v_w   = (const float*)d_in[6];
    const float* v_b   = (const float*)d_in[7];
    const float* ao_w  = (const float*)d_in[8];
    const float* ao_b  = (const float*)d_in[9];
    const float* ln1_g = (const float*)d_in[10];
    const float* ln1_b = (const float*)d_in[11];
    const float* ff1_w = (const float*)d_in[12];
    const float* ff1_b = (const float*)d_in[13];
    const float* ff2_w = (const float*)d_in[14];
    const float* ff2_b = (const float*)d_in[15];
    const float* ln2_g = (const float*)d_in[16];
    const float* ln2_b = (const float*)d_in[17];
    float* out = (float*)d_out;

    float *x, *t, *at, *bqkv;
    bf16 *xh,*xl,*qkvh,*qkvl,*ch,*cl,*ah,*al,*fh,*fl;
    bf16 *wqkvh,*wqkvl,*wah,*wal,*w1h,*w1l,*w2h,*w2l;
    cudaGetSymbolAddress((void**)&x, g_x);
    cudaGetSymbolAddress((void**)&t, g_t);      cudaGetSymbolAddress((void**)&at, g_at);
    cudaGetSymbolAddress((void**)&bqkv, g_bqkv);
    cudaGetSymbolAddress((void**)&xh, g_xh);    cudaGetSymbolAddress((void**)&xl, g_xl);
    cudaGetSymbolAddress((void**)&qkvh, g_qkvh);cudaGetSymbolAddress((void**)&qkvl, g_qkvl);
    cudaGetSymbolAddress((void**)&ch, g_ch);    cudaGetSymbolAddress((void**)&cl, g_cl);
    cudaGetSymbolAddress((void**)&ah, g_ah);    cudaGetSymbolAddress((void**)&al, g_al);
    cudaGetSymbolAddress((void**)&fh, g_fh);    cudaGetSymbolAddress((void**)&fl, g_fl);
    cudaGetSymbolAddress((void**)&wqkvh, g_wqkvh);
    cudaGetSymbolAddress((void**)&wqkvl, g_wqkvl);
    cudaGetSymbolAddress((void**)&wah, g_wah);  cudaGetSymbolAddress((void**)&wal, g_wal);
    cudaGetSymbolAddress((void**)&w1h, g_w1h);  cudaGetSymbolAddress((void**)&w1l, g_w1l);
    cudaGetSymbolAddress((void**)&w2h, g_w2h);  cudaGetSymbolAddress((void**)&w2l, g_w2l);

    const int SMB = 73728;    // 3 stages x 24576; x3 CTAs = 221184 B/SM
    cudaFuncSetAttribute(gemm_bf<EPI_BIAS,   OUT_SPLIT>, cudaFuncAttributeMaxDynamicSharedMemorySize, SMB);
    cudaFuncSetAttribute(gemm_bf<EPI_BIASRES,OUT_F32>,   cudaFuncAttributeMaxDynamicSharedMemorySize, SMB);
    cudaFuncSetAttribute(gemm_bf<EPI_GELU,   OUT_SPLIT>, cudaFuncAttributeMaxDynamicSharedMemorySize, SMB);
    const int SMF = 167936;   // 164 KB
    cudaFuncSetAttribute(fattn, cudaFuncAttributeMaxDynamicSharedMemorySize, SMF);

    cudaMemcpyAsync(x, hs, (size_t)NTOK * H * sizeof(float), cudaMemcpyDeviceToDevice);
    prep<<<9993, 256>>>(hs, q_w, k_w, v_w, ao_w, ff1_w, ff2_w, q_b, k_b, v_b);

    const dim3 gQKV(36, 32), gProj(12, 32), gFF1(48, 32), gAtt(8, 48);

    for (int layer = 0; layer < NLAYER; layer++) {
        gemm_bf<EPI_BIAS, OUT_SPLIT><<<gQKV, 256, SMB>>>(
            xh, xl, wqkvh, wqkvl, bqkv, nullptr, nullptr, qkvh, qkvl,
            H, H, H, H3);

        fattn<<<gAtt, 256, SMF>>>(qkvh, qkvl, mask, ch, cl);

        gemm_bf<EPI_BIASRES, OUT_F32><<<gProj, 256, SMB>>>(
            ch, cl, wah, wal, ao_b, x, t, nullptr, nullptr, H, H, H, H);
        ln_rows<true><<<NTOK, 256>>>(t, ln1_g, ln1_b, at, ah, al);

        gemm_bf<EPI_GELU, OUT_SPLIT><<<gFF1, 256, SMB>>>(
            ah, al, w1h, w1l, ff1_b, nullptr, nullptr, fh, fl, H, H, H, FFD);
        gemm_bf<EPI_BIASRES, OUT_F32><<<gProj, 256, SMB>>>(
            fh, fl, w2h, w2l, ff2_b, at, t, nullptr, nullptr, FFD, FFD, FFD, H);

        if (layer == NLAYER - 1) {
            ln_rows<false><<<NTOK, 256>>>(t, ln2_g, ln2_b, out, nullptr, nullptr);
        } else {
            ln_rows<true><<<NTOK, 256>>>(t, ln2_g, ln2_b, x, xh, xl);
        }
    }
}